// round 6
// baseline (speedup 1.0000x reference)
#include <cuda_runtime.h>
#include <math.h>
#include <stdint.h>

// Problem constants
#define BATCH 2
#define SEQ   2048
#define DMODEL 1024
#define NHEAD 16
#define DHEAD 64
#define MTOT  (BATCH*SEQ)      // 4096
#define LAMBDA_INIT 0.8f
#define LN_EPS 1e-5f

// ---------------------------------------------------------------------------
// Scratch
// ---------------------------------------------------------------------------
__device__ float g_q0[MTOT*DMODEL];
__device__ float g_q1[MTOT*DMODEL];
__device__ float g_k0[MTOT*DMODEL];
__device__ float g_k1[MTOT*DMODEL];
__device__ float g_v [MTOT*DMODEL];
__device__ float g_attn[MTOT*DMODEL];
__device__ float g_lambda;

__device__ __forceinline__ uint32_t cvt_tf32(float x) {
    uint32_t r;
    asm("cvt.rna.tf32.f32 %0, %1;" : "=r"(r) : "f"(x));
    return r;
}
__device__ __forceinline__ float tf32f(float x) {
    return __uint_as_float(cvt_tf32(x));
}

// ---------------------------------------------------------------------------
// Lambda scalar
// ---------------------------------------------------------------------------
__global__ void lambda_kernel(const float* __restrict__ l0, const float* __restrict__ l1,
                              const float* __restrict__ l2, const float* __restrict__ l3) {
    int t = threadIdx.x; // 32 threads
    float a = l0[t]*l1[t] + l0[t+32]*l1[t+32];
    float b = l2[t]*l3[t] + l2[t+32]*l3[t+32];
    #pragma unroll
    for (int o = 16; o >= 1; o >>= 1) {
        a += __shfl_xor_sync(0xffffffffu, a, o);
        b += __shfl_xor_sync(0xffffffffu, b, o);
    }
    if (t == 0) g_lambda = (-expf(a) + LAMBDA_INIT) + (-expf(b) + LAMBDA_INIT);
}

// ---------------------------------------------------------------------------
// TF32 tensor-core GEMM: C[M,N] = A[M,K] @ B[K,N], row-major.
// 128x128x32 block tile, 256 threads, mma.m16n8k8.tf32, cp.async dbl-buffered.
// __launch_bounds__(256, 2): cap regs at 128 -> 2 CTAs/SM (16 warps resident).
// ---------------------------------------------------------------------------
#define BM 128
#define BN 128
#define BK 32
#define A_LD 36
#define B_LD 136
#define AS_STAGE (BM*A_LD)
#define BS_STAGE (BK*B_LD)
#define GEMM_SMEM_BYTES ((2*(AS_STAGE+BS_STAGE))*4)

__global__ __launch_bounds__(256, 2) void gemm_tf32(const float* __restrict__ A,
                                                    const float* __restrict__ B,
                                                    float* __restrict__ C,
                                                    int M, int N, int K) {
    extern __shared__ float sm[];
    float* As = sm;
    float* Bs = sm + 2 * AS_STAGE;

    int tid  = threadIdx.x;
    int lane = tid & 31;
    int warp = tid >> 5;
    int g    = lane >> 2;
    int tig  = lane & 3;
    int wm   = (warp >> 2) * 64;
    int wn   = (warp & 3) * 32;

    int bx = blockIdx.x, by = blockIdx.y;

    const float* Ag = A + (size_t)(by * BM) * K;
    const float* Bg = B + bx * BN;

    int a_row = tid >> 3;
    int a_col = (tid & 7) * 4;
    int b_row = tid >> 5;
    int b_col = (tid & 31) * 4;

    uint32_t s_as = (uint32_t)__cvta_generic_to_shared(As);
    uint32_t s_bs = (uint32_t)__cvta_generic_to_shared(Bs);

    float acc[4][4][4];
    #pragma unroll
    for (int i = 0; i < 4; i++)
        #pragma unroll
        for (int j = 0; j < 4; j++)
            #pragma unroll
            for (int q = 0; q < 4; q++) acc[i][j][q] = 0.f;

    uint32_t a_lane_off = ((uint32_t)((wm + (lane & 15)) * A_LD + (lane >> 4) * 4)) * 4u;

    const int NT = K / BK;

    auto prefetch = [&](int kt, int stage) {
        uint32_t ad = s_as + (uint32_t)stage * AS_STAGE * 4;
        const float* ag = Ag + kt * BK;
        #pragma unroll
        for (int r = 0; r < 4; r++) {
            int row = a_row + r * 32;
            uint32_t dst = ad + (uint32_t)(row * A_LD + a_col) * 4;
            const float* src = ag + (size_t)row * K + a_col;
            asm volatile("cp.async.cg.shared.global [%0], [%1], 16;\n" :: "r"(dst), "l"(src));
        }
        uint32_t bd = s_bs + (uint32_t)stage * BS_STAGE * 4;
        const float* bg = Bg + (size_t)(kt * BK) * N;
        #pragma unroll
        for (int r = 0; r < 4; r++) {
            int row = b_row + r * 8;
            uint32_t dst = bd + (uint32_t)(row * B_LD + b_col) * 4;
            const float* src = bg + (size_t)row * N + b_col;
            asm volatile("cp.async.cg.shared.global [%0], [%1], 16;\n" :: "r"(dst), "l"(src));
        }
        asm volatile("cp.async.commit_group;\n");
    };

    prefetch(0, 0);

    for (int kt = 0; kt < NT; kt++) {
        int stage = kt & 1;
        if (kt + 1 < NT) {
            prefetch(kt + 1, stage ^ 1);
            asm volatile("cp.async.wait_group 1;\n");
        } else {
            asm volatile("cp.async.wait_group 0;\n");
        }
        __syncthreads();

        uint32_t a_base = s_as + (uint32_t)stage * AS_STAGE * 4 + a_lane_off;
        const float* bsp = Bs + stage * BS_STAGE;

        #pragma unroll
        for (int k8 = 0; k8 < BK / 8; k8++) {
            uint32_t arg[4][4];
            #pragma unroll
            for (int i = 0; i < 4; i++) {
                uint32_t addr = a_base + (uint32_t)(i * 16 * A_LD + k8 * 8) * 4;
                asm volatile("ldmatrix.sync.aligned.m8n8.x4.shared.b16 {%0,%1,%2,%3}, [%4];\n"
                             : "=r"(arg[i][0]), "=r"(arg[i][1]), "=r"(arg[i][2]), "=r"(arg[i][3])
                             : "r"(addr));
            }
            uint32_t brg[4][2];
            #pragma unroll
            for (int j = 0; j < 4; j++) {
                float b0 = bsp[(k8 * 8 + tig)     * B_LD + wn + j * 8 + g];
                float b1 = bsp[(k8 * 8 + tig + 4) * B_LD + wn + j * 8 + g];
                brg[j][0] = cvt_tf32(b0);
                brg[j][1] = cvt_tf32(b1);
            }
            #pragma unroll
            for (int i = 0; i < 4; i++)
                #pragma unroll
                for (int q = 0; q < 4; q++)
                    arg[i][q] = cvt_tf32(__uint_as_float(arg[i][q]));

            #pragma unroll
            for (int i = 0; i < 4; i++)
                #pragma unroll
                for (int j = 0; j < 4; j++)
                    asm volatile(
                        "mma.sync.aligned.m16n8k8.row.col.f32.tf32.tf32.f32 "
                        "{%0,%1,%2,%3}, {%4,%5,%6,%7}, {%8,%9}, {%0,%1,%2,%3};\n"
                        : "+f"(acc[i][j][0]), "+f"(acc[i][j][1]),
                          "+f"(acc[i][j][2]), "+f"(acc[i][j][3])
                        : "r"(arg[i][0]), "r"(arg[i][1]), "r"(arg[i][2]), "r"(arg[i][3]),
                          "r"(brg[j][0]), "r"(brg[j][1]));
        }
        __syncthreads();
    }

    #pragma unroll
    for (int i = 0; i < 4; i++) {
        int row = by * BM + wm + i * 16 + g;
        #pragma unroll
        for (int j = 0; j < 4; j++) {
            int col = bx * BN + wn + j * 8 + 2 * tig;
            *(float2*)(C + (size_t)row * N + col)       = make_float2(acc[i][j][0], acc[i][j][1]);
            *(float2*)(C + (size_t)(row + 8) * N + col) = make_float2(acc[i][j][2], acc[i][j][3]);
        }
    }
}

// ---------------------------------------------------------------------------
// Tensor-core differential flash attention + per-head LayerNorm.
// 128 threads = 4 warps; warp w owns q rows [w*16, w*16+16).
// K kept NATURAL [kv][dh]; one load phase + 2 block syncs per kt.
// ---------------------------------------------------------------------------
#define QLD 68   // %32=4 -> ldmatrix float-quadrant geometry, conflict-free
#define PLD 68
#define KLD 68   // %32=4 -> QK B-frag scalar LDS conflict-free (g*4+tig)
#define VLD 72   // %32=8 -> PV B-frag scalar LDS conflict-free
#define SQ_OFF  0
#define SK0_OFF (2*64*QLD)              // 8704
#define SK1_OFF (SK0_OFF + 64*KLD)      // 13056
#define SV_OFF  (SK1_OFF + 64*KLD)      // 17408
#define SP_OFF  (SV_OFF + 64*VLD)       // 22016
#define ATTN2_SMEM_FLOATS (SP_OFF + 64*PLD)   // 26368
#define ATTN2_SMEM_BYTES (ATTN2_SMEM_FLOATS*4) // 105472

__global__ __launch_bounds__(128) void attn_tc_kernel(
        const float* __restrict__ q0b, const float* __restrict__ q1b,
        const float* __restrict__ k0b, const float* __restrict__ k1b,
        const float* __restrict__ vb,
        const float* __restrict__ ln_w, const float* __restrict__ ln_b,
        float* __restrict__ attn) {
    extern __shared__ float sm[];
    float* sQ  = sm + SQ_OFF;    // [2][64][QLD] tf32 bits
    float* sK0 = sm + SK0_OFF;   // [64 kv][KLD] natural, tf32 bits
    float* sK1 = sm + SK1_OFF;
    float* sV  = sm + SV_OFF;    // [64 kv][VLD] natural, tf32 bits
    float* sP  = sm + SP_OFF;    // [64 q][PLD] tf32 bits, per-stream reuse

    int qt = gridDim.x - 1 - blockIdx.x;   // heavy tiles first
    int bh = blockIdx.y;
    int b = bh >> 4, h = bh & 15;

    int tid = threadIdx.x;
    int lane = tid & 31;
    int w = tid >> 5;
    int g = lane >> 2;
    int tig = lane & 3;

    const float scale = 0.125f;
    const float slope = exp2f(-0.5f * (float)(h + 1));
    const size_t base = (size_t)b * SEQ * DMODEL + (size_t)h * DHEAD;

    const int frow = tid & 63;
    const int fc0  = (tid >> 6) * 32;

    // --- load Q (both streams), row-major, pre-cvt tf32 ---
    {
        size_t gofs = base + (size_t)(qt * 64 + frow) * DMODEL + fc0;
        #pragma unroll
        for (int st = 0; st < 2; st++) {
            const float* src = (st == 0) ? q0b : q1b;
            float* dst = sQ + st * 64 * QLD + frow * QLD + fc0;
            #pragma unroll
            for (int c = 0; c < 32; c += 4) {
                float4 v4 = *(const float4*)(src + gofs + c);
                dst[c + 0] = tf32f(v4.x);
                dst[c + 1] = tf32f(v4.y);
                dst[c + 2] = tf32f(v4.z);
                dst[c + 3] = tf32f(v4.w);
            }
        }
    }

    float oacc[2][8][4];
    #pragma unroll
    for (int st = 0; st < 2; st++)
        #pragma unroll
        for (int j = 0; j < 8; j++)
            #pragma unroll
            for (int q = 0; q < 4; q++) oacc[st][j][q] = 0.f;
    float mrow[2][2], lrow[2][2];
    #pragma unroll
    for (int st = 0; st < 2; st++)
        #pragma unroll
        for (int hh = 0; hh < 2; hh++) { mrow[st][hh] = -INFINITY; lrow[st][hh] = 0.f; }

    uint32_t s_q = (uint32_t)__cvta_generic_to_shared(sQ);
    uint32_t s_p = (uint32_t)__cvta_generic_to_shared(sP);
    uint32_t qa_lane = ((uint32_t)((w * 16 + (lane & 15)) * QLD + (lane >> 4) * 4)) * 4u;
    uint32_t pa_lane = s_p + ((uint32_t)((w * 16 + (lane & 15)) * PLD + (lane >> 4) * 4)) * 4u;

    const int qrow0 = qt * 64 + w * 16;
    const int qq0 = qrow0 + g;

    for (int kt = 0; kt <= qt; kt++) {
        const bool diag = (kt == qt);
        // ---- load K0, K1, V tiles (natural layout, vectorized, pre-cvt) ----
        {
            size_t gofs = base + (size_t)(kt * 64 + frow) * DMODEL + fc0;
            const float* gk0 = k0b + gofs;
            const float* gk1 = k1b + gofs;
            const float* gv  = vb  + gofs;
            float* dk0 = sK0 + frow * KLD + fc0;
            float* dk1 = sK1 + frow * KLD + fc0;
            float* dv  = sV  + frow * VLD + fc0;
            #pragma unroll
            for (int c = 0; c < 32; c += 4) {
                float4 a4 = *(const float4*)(gk0 + c);
                dk0[c + 0] = tf32f(a4.x); dk0[c + 1] = tf32f(a4.y);
                dk0[c + 2] = tf32f(a4.z); dk0[c + 3] = tf32f(a4.w);
                float4 b4 = *(const float4*)(gk1 + c);
                dk1[c + 0] = tf32f(b4.x); dk1[c + 1] = tf32f(b4.y);
                dk1[c + 2] = tf32f(b4.z); dk1[c + 3] = tf32f(b4.w);
                float4 c4 = *(const float4*)(gv + c);
                dv[c + 0] = tf32f(c4.x); dv[c + 1] = tf32f(c4.y);
                dv[c + 2] = tf32f(c4.z); dv[c + 3] = tf32f(c4.w);
            }
        }
        __syncthreads();   // tiles ready

        #pragma unroll
        for (int st = 0; st < 2; st++) {
            const float* sK = (st == 0) ? sK0 : sK1;

            // ---- QK: scores [16 q rows x 64 kv] per warp ----
            float sc[8][4];
            #pragma unroll
            for (int j = 0; j < 8; j++)
                #pragma unroll
                for (int q = 0; q < 4; q++) sc[j][q] = 0.f;

            uint32_t qa_base = s_q + (uint32_t)(st * 64 * QLD) * 4u + qa_lane;
            #pragma unroll
            for (int k8 = 0; k8 < 8; k8++) {
                uint32_t a0, a1, a2, a3;
                uint32_t addr = qa_base + (uint32_t)(k8 * 8) * 4u;
                asm volatile("ldmatrix.sync.aligned.m8n8.x4.shared.b16 {%0,%1,%2,%3}, [%4];\n"
                             : "=r"(a0), "=r"(a1), "=r"(a2), "=r"(a3) : "r"(addr));
                #pragma unroll
                for (int j = 0; j < 8; j++) {
                    const float* kr = sK + (j * 8 + g) * KLD + k8 * 8;
                    uint32_t b0 = __float_as_uint(kr[tig]);
                    uint32_t b1 = __float_as_uint(kr[tig + 4]);
                    asm volatile(
                        "mma.sync.aligned.m16n8k8.row.col.f32.tf32.tf32.f32 "
                        "{%0,%1,%2,%3}, {%4,%5,%6,%7}, {%8,%9}, {%0,%1,%2,%3};\n"
                        : "+f"(sc[j][0]), "+f"(sc[j][1]), "+f"(sc[j][2]), "+f"(sc[j][3])
                        : "r"(a0), "r"(a1), "r"(a2), "r"(a3), "r"(b0), "r"(b1));
                }
            }

            // ---- softmax (online), rows g and g+8 ----
            #pragma unroll
            for (int hh = 0; hh < 2; hh++) {
                int qq = qq0 + hh * 8;
                float mx = -INFINITY;
                #pragma unroll
                for (int j = 0; j < 8; j++) {
                    #pragma unroll
                    for (int e = 0; e < 2; e++) {
                        int kk = kt * 64 + j * 8 + 2 * tig + e;
                        float s = sc[j][hh * 2 + e] * scale - slope * (float)(qq - kk);
                        if (diag && kk > qq) s = -INFINITY;
                        sc[j][hh * 2 + e] = s;
                        mx = fmaxf(mx, s);
                    }
                }
                mx = fmaxf(mx, __shfl_xor_sync(0xffffffffu, mx, 1));
                mx = fmaxf(mx, __shfl_xor_sync(0xffffffffu, mx, 2));
                float mn = fmaxf(mrow[st][hh], mx);
                float corr = __expf(mrow[st][hh] - mn);
                mrow[st][hh] = mn;
                float rs = 0.f;
                #pragma unroll
                for (int j = 0; j < 8; j++) {
                    #pragma unroll
                    for (int e = 0; e < 2; e++) {
                        float pv = __expf(sc[j][hh * 2 + e] - mn);
                        sc[j][hh * 2 + e] = pv;
                        rs += pv;
                    }
                }
                rs += __shfl_xor_sync(0xffffffffu, rs, 1);
                rs += __shfl_xor_sync(0xffffffffu, rs, 2);
                lrow[st][hh] = lrow[st][hh] * corr + rs;
                #pragma unroll
                for (int j = 0; j < 8; j++) {
                    oacc[st][j][hh * 2 + 0] *= corr;
                    oacc[st][j][hh * 2 + 1] *= corr;
                }
            }

            // ---- write P (tf32 bits) to own-warp rows of sP ----
            #pragma unroll
            for (int hh = 0; hh < 2; hh++) {
                float* pr = sP + (w * 16 + g + hh * 8) * PLD;
                #pragma unroll
                for (int j = 0; j < 8; j++) {
                    float2 pv = make_float2(tf32f(sc[j][hh * 2 + 0]), tf32f(sc[j][hh * 2 + 1]));
                    *(float2*)(pr + j * 8 + 2 * tig) = pv;
                }
            }
            __syncwarp();  // sP rows warp-private

            // ---- PV: oacc += P @ V ----
            #pragma unroll
            for (int k8 = 0; k8 < 8; k8++) {
                uint32_t a0, a1, a2, a3;
                uint32_t addr = pa_lane + (uint32_t)(k8 * 8) * 4u;
                asm volatile("ldmatrix.sync.aligned.m8n8.x4.shared.b16 {%0,%1,%2,%3}, [%4];\n"
                             : "=r"(a0), "=r"(a1), "=r"(a2), "=r"(a3) : "r"(addr));
                const float* vp = sV + (k8 * 8 + tig) * VLD;
                #pragma unroll
                for (int j = 0; j < 8; j++) {
                    uint32_t b0 = __float_as_uint(vp[j * 8 + g]);
                    uint32_t b1 = __float_as_uint(vp[4 * VLD + j * 8 + g]);
                    asm volatile(
                        "mma.sync.aligned.m16n8k8.row.col.f32.tf32.tf32.f32 "
                        "{%0,%1,%2,%3}, {%4,%5,%6,%7}, {%8,%9}, {%0,%1,%2,%3};\n"
                        : "+f"(oacc[st][j][0]), "+f"(oacc[st][j][1]),
                          "+f"(oacc[st][j][2]), "+f"(oacc[st][j][3])
                        : "r"(a0), "r"(a1), "r"(a2), "r"(a3), "r"(b0), "r"(b1));
                }
            }
            __syncwarp();  // stream 1 P-write must not pass stream 0 P-reads
        }
        __syncthreads();  // all reads done before next kt overwrites tiles
    }

    // --- epilogue: combine streams, per-head LayerNorm over DH, store ---
    float lam = g_lambda;
    #pragma unroll
    for (int hh = 0; hh < 2; hh++) {
        float inv0 = 1.0f / lrow[0][hh];
        float inv1 = 1.0f / lrow[1][hh];
        float o[8][2];
        float s_ = 0.f;
        #pragma unroll
        for (int j = 0; j < 8; j++) {
            #pragma unroll
            for (int e = 0; e < 2; e++) {
                float val = oacc[0][j][hh * 2 + e] * inv0
                          - lam * (oacc[1][j][hh * 2 + e] * inv1);
                o[j][e] = val;
                s_ += val;
            }
        }
        s_ += __shfl_xor_sync(0xffffffffu, s_, 1);
        s_ += __shfl_xor_sync(0xffffffffu, s_, 2);
        float mu = s_ * (1.0f / 64.0f);
        float vs = 0.f;
        #pragma unroll
        for (int j = 0; j < 8; j++) {
            #pragma unroll
            for (int e = 0; e < 2; e++) { float d = o[j][e] - mu; vs += d * d; }
        }
        vs += __shfl_xor_sync(0xffffffffu, vs, 1);
        vs += __shfl_xor_sync(0xffffffffu, vs, 2);
        float r = rsqrtf(vs * (1.0f / 64.0f) + LN_EPS);

        size_t row = (size_t)b * SEQ + (size_t)(qrow0 + g + hh * 8);
        #pragma unroll
        for (int j = 0; j < 8; j++) {
            int col = h * DHEAD + j * 8 + 2 * tig;
            float wv0 = ln_w[h * DHEAD + j * 8 + 2 * tig];
            float wv1 = ln_w[h * DHEAD + j * 8 + 2 * tig + 1];
            float bv0 = ln_b[h * DHEAD + j * 8 + 2 * tig];
            float bv1 = ln_b[h * DHEAD + j * 8 + 2 * tig + 1];
            float2 res = make_float2((o[j][0] - mu) * r * wv0 + bv0,
                                     (o[j][1] - mu) * r * wv1 + bv1);
            *(float2*)(attn + row * DMODEL + col) = res;
        }
    }
}

// ---------------------------------------------------------------------------
// Launch
// ---------------------------------------------------------------------------
extern "C" void kernel_launch(void* const* d_in, const int* in_sizes, int n_in,
                              void* d_out, int out_size) {
    const float* inp = (const float*)d_in[0];
    const float* wq0 = (const float*)d_in[1];
    const float* wq1 = (const float*)d_in[2];
    const float* wk0 = (const float*)d_in[3];
    const float* wk1 = (const float*)d_in[4];
    const float* wv  = (const float*)d_in[5];
    const float* wo  = (const float*)d_in[6];
    const float* l0  = (const float*)d_in[7];
    const float* l1  = (const float*)d_in[8];
    const float* l2  = (const float*)d_in[9];
    const float* l3  = (const float*)d_in[10];
    const float* lnw = (const float*)d_in[11];
    const float* lnb = (const float*)d_in[12];
    float* out = (float*)d_out;

    float *q0, *q1, *k0, *k1, *v, *attn;
    cudaGetSymbolAddress((void**)&q0, g_q0);
    cudaGetSymbolAddress((void**)&q1, g_q1);
    cudaGetSymbolAddress((void**)&k0, g_k0);
    cudaGetSymbolAddress((void**)&k1, g_k1);
    cudaGetSymbolAddress((void**)&v,  g_v);
    cudaGetSymbolAddress((void**)&attn, g_attn);

    cudaFuncSetAttribute(gemm_tf32, cudaFuncAttributeMaxDynamicSharedMemorySize,
                         GEMM_SMEM_BYTES);
    cudaFuncSetAttribute(attn_tc_kernel, cudaFuncAttributeMaxDynamicSharedMemorySize,
                         ATTN2_SMEM_BYTES);

    lambda_kernel<<<1, 32>>>(l0, l1, l2, l3);

    dim3 ggrid(DMODEL / 128, MTOT / 128);   // (8, 32)
    gemm_tf32<<<ggrid, 256, GEMM_SMEM_BYTES>>>(inp, wq0, q0, MTOT, DMODEL, DMODEL);
    gemm_tf32<<<ggrid, 256, GEMM_SMEM_BYTES>>>(inp, wq1, q1, MTOT, DMODEL, DMODEL);
    gemm_tf32<<<ggrid, 256, GEMM_SMEM_BYTES>>>(inp, wk0, k0, MTOT, DMODEL, DMODEL);
    gemm_tf32<<<ggrid, 256, GEMM_SMEM_BYTES>>>(inp, wk1, k1, MTOT, DMODEL, DMODEL);
    gemm_tf32<<<ggrid, 256, GEMM_SMEM_BYTES>>>(inp, wv,  v,  MTOT, DMODEL, DMODEL);

    attn_tc_kernel<<<dim3(SEQ / 64, BATCH * NHEAD), 128, ATTN2_SMEM_BYTES>>>(
        q0, q1, k0, k1, v, lnw, lnb, attn);

    gemm_tf32<<<ggrid, 256, GEMM_SMEM_BYTES>>>(attn, wo, out, MTOT, DMODEL, DMODEL);
}

// round 7
// speedup vs baseline: 1.0882x; 1.0882x over previous
#include <cuda_runtime.h>
#include <math.h>
#include <stdint.h>

// Problem constants
#define BATCH 2
#define SEQ   2048
#define DMODEL 1024
#define NHEAD 16
#define DHEAD 64
#define MTOT  (BATCH*SEQ)      // 4096
#define LAMBDA_INIT 0.8f
#define LN_EPS 1e-5f

// ---------------------------------------------------------------------------
// Scratch
// ---------------------------------------------------------------------------
__device__ float g_q0[MTOT*DMODEL];
__device__ float g_q1[MTOT*DMODEL];
__device__ float g_k0[MTOT*DMODEL];
__device__ float g_k1[MTOT*DMODEL];
__device__ float g_v [MTOT*DMODEL];
__device__ float g_attn[MTOT*DMODEL];
__device__ float g_lambda;

__device__ __forceinline__ uint32_t cvt_tf32(float x) {
    uint32_t r;
    asm("cvt.rna.tf32.f32 %0, %1;" : "=r"(r) : "f"(x));
    return r;
}
__device__ __forceinline__ float tf32f(float x) {
    return __uint_as_float(cvt_tf32(x));
}

// ---------------------------------------------------------------------------
// Lambda scalar
// ---------------------------------------------------------------------------
__global__ void lambda_kernel(const float* __restrict__ l0, const float* __restrict__ l1,
                              const float* __restrict__ l2, const float* __restrict__ l3) {
    int t = threadIdx.x; // 32 threads
    float a = l0[t]*l1[t] + l0[t+32]*l1[t+32];
    float b = l2[t]*l3[t] + l2[t+32]*l3[t+32];
    #pragma unroll
    for (int o = 16; o >= 1; o >>= 1) {
        a += __shfl_xor_sync(0xffffffffu, a, o);
        b += __shfl_xor_sync(0xffffffffu, b, o);
    }
    if (t == 0) g_lambda = (-expf(a) + LAMBDA_INIT) + (-expf(b) + LAMBDA_INIT);
}

// ---------------------------------------------------------------------------
// TF32 tensor-core GEMM (R6-measured: 75.6us, regs=127, 2 CTAs/SM)
// ---------------------------------------------------------------------------
#define BM 128
#define BN 128
#define BK 32
#define A_LD 36
#define B_LD 136
#define AS_STAGE (BM*A_LD)
#define BS_STAGE (BK*B_LD)
#define GEMM_SMEM_BYTES ((2*(AS_STAGE+BS_STAGE))*4)

__global__ __launch_bounds__(256, 2) void gemm_tf32(const float* __restrict__ A,
                                                    const float* __restrict__ B,
                                                    float* __restrict__ C,
                                                    int M, int N, int K) {
    extern __shared__ float sm[];
    float* As = sm;
    float* Bs = sm + 2 * AS_STAGE;

    int tid  = threadIdx.x;
    int lane = tid & 31;
    int warp = tid >> 5;
    int g    = lane >> 2;
    int tig  = lane & 3;
    int wm   = (warp >> 2) * 64;
    int wn   = (warp & 3) * 32;

    int bx = blockIdx.x, by = blockIdx.y;

    const float* Ag = A + (size_t)(by * BM) * K;
    const float* Bg = B + bx * BN;

    int a_row = tid >> 3;
    int a_col = (tid & 7) * 4;
    int b_row = tid >> 5;
    int b_col = (tid & 31) * 4;

    uint32_t s_as = (uint32_t)__cvta_generic_to_shared(As);
    uint32_t s_bs = (uint32_t)__cvta_generic_to_shared(Bs);

    float acc[4][4][4];
    #pragma unroll
    for (int i = 0; i < 4; i++)
        #pragma unroll
        for (int j = 0; j < 4; j++)
            #pragma unroll
            for (int q = 0; q < 4; q++) acc[i][j][q] = 0.f;

    uint32_t a_lane_off = ((uint32_t)((wm + (lane & 15)) * A_LD + (lane >> 4) * 4)) * 4u;

    const int NT = K / BK;

    auto prefetch = [&](int kt, int stage) {
        uint32_t ad = s_as + (uint32_t)stage * AS_STAGE * 4;
        const float* ag = Ag + kt * BK;
        #pragma unroll
        for (int r = 0; r < 4; r++) {
            int row = a_row + r * 32;
            uint32_t dst = ad + (uint32_t)(row * A_LD + a_col) * 4;
            const float* src = ag + (size_t)row * K + a_col;
            asm volatile("cp.async.cg.shared.global [%0], [%1], 16;\n" :: "r"(dst), "l"(src));
        }
        uint32_t bd = s_bs + (uint32_t)stage * BS_STAGE * 4;
        const float* bg = Bg + (size_t)(kt * BK) * N;
        #pragma unroll
        for (int r = 0; r < 4; r++) {
            int row = b_row + r * 8;
            uint32_t dst = bd + (uint32_t)(row * B_LD + b_col) * 4;
            const float* src = bg + (size_t)row * N + b_col;
            asm volatile("cp.async.cg.shared.global [%0], [%1], 16;\n" :: "r"(dst), "l"(src));
        }
        asm volatile("cp.async.commit_group;\n");
    };

    prefetch(0, 0);

    for (int kt = 0; kt < NT; kt++) {
        int stage = kt & 1;
        if (kt + 1 < NT) {
            prefetch(kt + 1, stage ^ 1);
            asm volatile("cp.async.wait_group 1;\n");
        } else {
            asm volatile("cp.async.wait_group 0;\n");
        }
        __syncthreads();

        uint32_t a_base = s_as + (uint32_t)stage * AS_STAGE * 4 + a_lane_off;
        const float* bsp = Bs + stage * BS_STAGE;

        #pragma unroll
        for (int k8 = 0; k8 < BK / 8; k8++) {
            uint32_t arg[4][4];
            #pragma unroll
            for (int i = 0; i < 4; i++) {
                uint32_t addr = a_base + (uint32_t)(i * 16 * A_LD + k8 * 8) * 4;
                asm volatile("ldmatrix.sync.aligned.m8n8.x4.shared.b16 {%0,%1,%2,%3}, [%4];\n"
                             : "=r"(arg[i][0]), "=r"(arg[i][1]), "=r"(arg[i][2]), "=r"(arg[i][3])
                             : "r"(addr));
            }
            uint32_t brg[4][2];
            #pragma unroll
            for (int j = 0; j < 4; j++) {
                float b0 = bsp[(k8 * 8 + tig)     * B_LD + wn + j * 8 + g];
                float b1 = bsp[(k8 * 8 + tig + 4) * B_LD + wn + j * 8 + g];
                brg[j][0] = cvt_tf32(b0);
                brg[j][1] = cvt_tf32(b1);
            }
            #pragma unroll
            for (int i = 0; i < 4; i++)
                #pragma unroll
                for (int q = 0; q < 4; q++)
                    arg[i][q] = cvt_tf32(__uint_as_float(arg[i][q]));

            #pragma unroll
            for (int i = 0; i < 4; i++)
                #pragma unroll
                for (int j = 0; j < 4; j++)
                    asm volatile(
                        "mma.sync.aligned.m16n8k8.row.col.f32.tf32.tf32.f32 "
                        "{%0,%1,%2,%3}, {%4,%5,%6,%7}, {%8,%9}, {%0,%1,%2,%3};\n"
                        : "+f"(acc[i][j][0]), "+f"(acc[i][j][1]),
                          "+f"(acc[i][j][2]), "+f"(acc[i][j][3])
                        : "r"(arg[i][0]), "r"(arg[i][1]), "r"(arg[i][2]), "r"(arg[i][3]),
                          "r"(brg[j][0]), "r"(brg[j][1]));
        }
        __syncthreads();
    }

    #pragma unroll
    for (int i = 0; i < 4; i++) {
        int row = by * BM + wm + i * 16 + g;
        #pragma unroll
        for (int j = 0; j < 4; j++) {
            int col = bx * BN + wn + j * 8 + 2 * tig;
            *(float2*)(C + (size_t)row * N + col)       = make_float2(acc[i][j][0], acc[i][j][1]);
            *(float2*)(C + (size_t)(row + 8) * N + col) = make_float2(acc[i][j][2], acc[i][j][3]);
        }
    }
}

// ---------------------------------------------------------------------------
// Tensor-core differential flash attention + per-head LayerNorm.
// R4-measured structure (690us): 128 threads, K transposed per stream,
// V loaded once per kt. Only change vs R4: causal mask applied on diagonal
// tile only (diag hoist).
// ---------------------------------------------------------------------------
#define QLD 68   // %32=4 -> ldmatrix float-quadrant geometry, conflict-free
#define PLD 68
#define KLD 72   // %32=8 -> scalar B-frag LDS conflict-free
#define VLD 72
#define SQ_OFF 0
#define SK_OFF (2*64*QLD)            // 8704
#define SV_OFF (SK_OFF + 64*KLD)     // 13312
#define SP_OFF (SV_OFF + 64*VLD)     // 17920
#define ATTN2_SMEM_FLOATS (SP_OFF + 64*PLD)   // 22272
#define ATTN2_SMEM_BYTES (ATTN2_SMEM_FLOATS*4)

__global__ __launch_bounds__(128) void attn_tc_kernel(
        const float* __restrict__ q0b, const float* __restrict__ q1b,
        const float* __restrict__ k0b, const float* __restrict__ k1b,
        const float* __restrict__ vb,
        const float* __restrict__ ln_w, const float* __restrict__ ln_b,
        float* __restrict__ attn) {
    extern __shared__ float sm[];
    float* sQ = sm + SQ_OFF;   // [2][64][QLD] tf32 bits
    float* sK = sm + SK_OFF;   // [64 dh][KLD(kv)] transposed, per-stream reuse
    float* sV = sm + SV_OFF;   // [64 kv][VLD(dh)]
    float* sP = sm + SP_OFF;   // [64 q][PLD(kv)]

    int qt = gridDim.x - 1 - blockIdx.x;   // heavy tiles first
    int bh = blockIdx.y;
    int b = bh >> 4, h = bh & 15;

    int tid = threadIdx.x;
    int lane = tid & 31;
    int w = tid >> 5;
    int g = lane >> 2;
    int tig = lane & 3;

    const float scale = 0.125f;
    const float slope = exp2f(-0.5f * (float)(h + 1));
    const size_t base = (size_t)b * SEQ * DMODEL + (size_t)h * DHEAD;

    // --- load Q (both streams), row-major, pre-cvt tf32 ---
    {
        int row = tid >> 1;             // 0..63
        int c0  = (tid & 1) * 32;
        size_t gofs = base + (size_t)(qt * 64 + row) * DMODEL + c0;
        #pragma unroll
        for (int st = 0; st < 2; st++) {
            const float* src = (st == 0) ? q0b : q1b;
            float* dst = sQ + st * 64 * QLD + row * QLD + c0;
            #pragma unroll
            for (int c = 0; c < 32; c += 4) {
                float4 v4 = *(const float4*)(src + gofs + c);
                dst[c + 0] = tf32f(v4.x);
                dst[c + 1] = tf32f(v4.y);
                dst[c + 2] = tf32f(v4.z);
                dst[c + 3] = tf32f(v4.w);
            }
        }
    }

    float oacc[2][8][4];
    #pragma unroll
    for (int st = 0; st < 2; st++)
        #pragma unroll
        for (int j = 0; j < 8; j++)
            #pragma unroll
            for (int q = 0; q < 4; q++) oacc[st][j][q] = 0.f;
    float mrow[2][2], lrow[2][2];
    #pragma unroll
    for (int st = 0; st < 2; st++)
        #pragma unroll
        for (int hh = 0; hh < 2; hh++) { mrow[st][hh] = -INFINITY; lrow[st][hh] = 0.f; }

    uint32_t s_q = (uint32_t)__cvta_generic_to_shared(sQ);
    uint32_t s_p = (uint32_t)__cvta_generic_to_shared(sP);
    uint32_t qa_lane = ((uint32_t)((w * 16 + (lane & 15)) * QLD + (lane >> 4) * 4)) * 4u;
    uint32_t pa_lane = s_p + ((uint32_t)((w * 16 + (lane & 15)) * PLD + (lane >> 4) * 4)) * 4u;

    const int qrow0 = qt * 64 + w * 16;
    const int qq0 = qrow0 + g;

    for (int kt = 0; kt <= qt; kt++) {
        const bool diag = (kt == qt);
        // load V tile (stream-independent), pre-cvt
        {
            int kv = tid >> 1;
            int c0 = (tid & 1) * 32;
            const float* gp = vb + base + (size_t)(kt * 64 + kv) * DMODEL + c0;
            float* dst = sV + kv * VLD + c0;
            #pragma unroll
            for (int c = 0; c < 32; c += 4) {
                float4 v4 = *(const float4*)(gp + c);
                dst[c + 0] = tf32f(v4.x);
                dst[c + 1] = tf32f(v4.y);
                dst[c + 2] = tf32f(v4.z);
                dst[c + 3] = tf32f(v4.w);
            }
        }

        #pragma unroll
        for (int st = 0; st < 2; st++) {
            // load K tile transposed [dh][kv], pre-cvt
            {
                int kv = tid >> 1;
                int c0 = (tid & 1) * 32;
                const float* gp = ((st == 0) ? k0b : k1b) + base
                                  + (size_t)(kt * 64 + kv) * DMODEL + c0;
                #pragma unroll
                for (int c = 0; c < 32; c += 4) {
                    float4 v4 = *(const float4*)(gp + c);
                    sK[(c0 + c + 0) * KLD + kv] = tf32f(v4.x);
                    sK[(c0 + c + 1) * KLD + kv] = tf32f(v4.y);
                    sK[(c0 + c + 2) * KLD + kv] = tf32f(v4.z);
                    sK[(c0 + c + 3) * KLD + kv] = tf32f(v4.w);
                }
            }
            __syncthreads();   // sK ready; also guarantees prior sP readers done

            // ---- QK: scores [16 q rows x 64 kv] per warp ----
            float sc[8][4];
            #pragma unroll
            for (int j = 0; j < 8; j++)
                #pragma unroll
                for (int q = 0; q < 4; q++) sc[j][q] = 0.f;

            uint32_t qa_base = s_q + (uint32_t)(st * 64 * QLD) * 4u + qa_lane;
            #pragma unroll
            for (int k8 = 0; k8 < 8; k8++) {
                uint32_t a0, a1, a2, a3;
                uint32_t addr = qa_base + (uint32_t)(k8 * 8) * 4u;
                asm volatile("ldmatrix.sync.aligned.m8n8.x4.shared.b16 {%0,%1,%2,%3}, [%4];\n"
                             : "=r"(a0), "=r"(a1), "=r"(a2), "=r"(a3) : "r"(addr));
                const float* kp = sK + (k8 * 8 + tig) * KLD;
                #pragma unroll
                for (int j = 0; j < 8; j++) {
                    uint32_t b0 = __float_as_uint(kp[j * 8 + g]);
                    uint32_t b1 = __float_as_uint(kp[4 * KLD + j * 8 + g]);
                    asm volatile(
                        "mma.sync.aligned.m16n8k8.row.col.f32.tf32.tf32.f32 "
                        "{%0,%1,%2,%3}, {%4,%5,%6,%7}, {%8,%9}, {%0,%1,%2,%3};\n"
                        : "+f"(sc[j][0]), "+f"(sc[j][1]), "+f"(sc[j][2]), "+f"(sc[j][3])
                        : "r"(a0), "r"(a1), "r"(a2), "r"(a3), "r"(b0), "r"(b1));
                }
            }

            // ---- softmax (online), rows g and g+8 ----
            #pragma unroll
            for (int hh = 0; hh < 2; hh++) {
                int qq = qq0 + hh * 8;
                float mx = -INFINITY;
                #pragma unroll
                for (int j = 0; j < 8; j++) {
                    #pragma unroll
                    for (int e = 0; e < 2; e++) {
                        int kk = kt * 64 + j * 8 + 2 * tig + e;
                        float s = sc[j][hh * 2 + e] * scale - slope * (float)(qq - kk);
                        if (diag && kk > qq) s = -INFINITY;
                        sc[j][hh * 2 + e] = s;
                        mx = fmaxf(mx, s);
                    }
                }
                mx = fmaxf(mx, __shfl_xor_sync(0xffffffffu, mx, 1));
                mx = fmaxf(mx, __shfl_xor_sync(0xffffffffu, mx, 2));
                float mn = fmaxf(mrow[st][hh], mx);
                float corr = __expf(mrow[st][hh] - mn);
                mrow[st][hh] = mn;
                float rs = 0.f;
                #pragma unroll
                for (int j = 0; j < 8; j++) {
                    #pragma unroll
                    for (int e = 0; e < 2; e++) {
                        float pv = __expf(sc[j][hh * 2 + e] - mn);
                        sc[j][hh * 2 + e] = pv;
                        rs += pv;
                    }
                }
                rs += __shfl_xor_sync(0xffffffffu, rs, 1);
                rs += __shfl_xor_sync(0xffffffffu, rs, 2);
                lrow[st][hh] = lrow[st][hh] * corr + rs;
                #pragma unroll
                for (int j = 0; j < 8; j++) {
                    oacc[st][j][hh * 2 + 0] *= corr;
                    oacc[st][j][hh * 2 + 1] *= corr;
                }
            }

            // ---- write P (tf32 bits) to own-warp rows of sP ----
            #pragma unroll
            for (int hh = 0; hh < 2; hh++) {
                float* pr = sP + (w * 16 + g + hh * 8) * PLD;
                #pragma unroll
                for (int j = 0; j < 8; j++) {
                    float2 pv = make_float2(tf32f(sc[j][hh * 2 + 0]), tf32f(sc[j][hh * 2 + 1]));
                    *(float2*)(pr + j * 8 + 2 * tig) = pv;
                }
            }
            __syncwarp();  // sP rows warp-private

            // ---- PV: oacc += P @ V ----
            #pragma unroll
            for (int k8 = 0; k8 < 8; k8++) {
                uint32_t a0, a1, a2, a3;
                uint32_t addr = pa_lane + (uint32_t)(k8 * 8) * 4u;
                asm volatile("ldmatrix.sync.aligned.m8n8.x4.shared.b16 {%0,%1,%2,%3}, [%4];\n"
                             : "=r"(a0), "=r"(a1), "=r"(a2), "=r"(a3) : "r"(addr));
                const float* vp = sV + (k8 * 8 + tig) * VLD;
                #pragma unroll
                for (int j = 0; j < 8; j++) {
                    uint32_t b0 = __float_as_uint(vp[j * 8 + g]);
                    uint32_t b1 = __float_as_uint(vp[4 * VLD + j * 8 + g]);
                    asm volatile(
                        "mma.sync.aligned.m16n8k8.row.col.f32.tf32.tf32.f32 "
                        "{%0,%1,%2,%3}, {%4,%5,%6,%7}, {%8,%9}, {%0,%1,%2,%3};\n"
                        : "+f"(oacc[st][j][0]), "+f"(oacc[st][j][1]),
                          "+f"(oacc[st][j][2]), "+f"(oacc[st][j][3])
                        : "r"(a0), "r"(a1), "r"(a2), "r"(a3), "r"(b0), "r"(b1));
                }
            }
            __syncthreads();  // all reads of sK/sV done before next overwrite
        }
    }

    // --- epilogue: combine streams, per-head LayerNorm over DH, store ---
    float lam = g_lambda;
    #pragma unroll
    for (int hh = 0; hh < 2; hh++) {
        float inv0 = 1.0f / lrow[0][hh];
        float inv1 = 1.0f / lrow[1][hh];
        float o[8][2];
        float s_ = 0.f;
        #pragma unroll
        for (int j = 0; j < 8; j++) {
            #pragma unroll
            for (int e = 0; e < 2; e++) {
                float val = oacc[0][j][hh * 2 + e] * inv0
                          - lam * (oacc[1][j][hh * 2 + e] * inv1);
                o[j][e] = val;
                s_ += val;
            }
        }
        s_ += __shfl_xor_sync(0xffffffffu, s_, 1);
        s_ += __shfl_xor_sync(0xffffffffu, s_, 2);
        float mu = s_ * (1.0f / 64.0f);
        float vs = 0.f;
        #pragma unroll
        for (int j = 0; j < 8; j++) {
            #pragma unroll
            for (int e = 0; e < 2; e++) { float d = o[j][e] - mu; vs += d * d; }
        }
        vs += __shfl_xor_sync(0xffffffffu, vs, 1);
        vs += __shfl_xor_sync(0xffffffffu, vs, 2);
        float r = rsqrtf(vs * (1.0f / 64.0f) + LN_EPS);

        size_t row = (size_t)b * SEQ + (size_t)(qrow0 + g + hh * 8);
        #pragma unroll
        for (int j = 0; j < 8; j++) {
            int col = h * DHEAD + j * 8 + 2 * tig;
            float wv0 = ln_w[h * DHEAD + j * 8 + 2 * tig];
            float wv1 = ln_w[h * DHEAD + j * 8 + 2 * tig + 1];
            float bv0 = ln_b[h * DHEAD + j * 8 + 2 * tig];
            float bv1 = ln_b[h * DHEAD + j * 8 + 2 * tig + 1];
            float2 res = make_float2((o[j][0] - mu) * r * wv0 + bv0,
                                     (o[j][1] - mu) * r * wv1 + bv1);
            *(float2*)(attn + row * DMODEL + col) = res;
        }
    }
}

// ---------------------------------------------------------------------------
// Launch
// ---------------------------------------------------------------------------
extern "C" void kernel_launch(void* const* d_in, const int* in_sizes, int n_in,
                              void* d_out, int out_size) {
    const float* inp = (const float*)d_in[0];
    const float* wq0 = (const float*)d_in[1];
    const float* wq1 = (const float*)d_in[2];
    const float* wk0 = (const float*)d_in[3];
    const float* wk1 = (const float*)d_in[4];
    const float* wv  = (const float*)d_in[5];
    const float* wo  = (const float*)d_in[6];
    const float* l0  = (const float*)d_in[7];
    const float* l1  = (const float*)d_in[8];
    const float* l2  = (const float*)d_in[9];
    const float* l3  = (const float*)d_in[10];
    const float* lnw = (const float*)d_in[11];
    const float* lnb = (const float*)d_in[12];
    float* out = (float*)d_out;

    float *q0, *q1, *k0, *k1, *v, *attn;
    cudaGetSymbolAddress((void**)&q0, g_q0);
    cudaGetSymbolAddress((void**)&q1, g_q1);
    cudaGetSymbolAddress((void**)&k0, g_k0);
    cudaGetSymbolAddress((void**)&k1, g_k1);
    cudaGetSymbolAddress((void**)&v,  g_v);
    cudaGetSymbolAddress((void**)&attn, g_attn);

    cudaFuncSetAttribute(gemm_tf32, cudaFuncAttributeMaxDynamicSharedMemorySize,
                         GEMM_SMEM_BYTES);
    cudaFuncSetAttribute(attn_tc_kernel, cudaFuncAttributeMaxDynamicSharedMemorySize,
                         ATTN2_SMEM_BYTES);

    lambda_kernel<<<1, 32>>>(l0, l1, l2, l3);

    dim3 ggrid(DMODEL / 128, MTOT / 128);   // (8, 32)
    gemm_tf32<<<ggrid, 256, GEMM_SMEM_BYTES>>>(inp, wq0, q0, MTOT, DMODEL, DMODEL);
    gemm_tf32<<<ggrid, 256, GEMM_SMEM_BYTES>>>(inp, wq1, q1, MTOT, DMODEL, DMODEL);
    gemm_tf32<<<ggrid, 256, GEMM_SMEM_BYTES>>>(inp, wk0, k0, MTOT, DMODEL, DMODEL);
    gemm_tf32<<<ggrid, 256, GEMM_SMEM_BYTES>>>(inp, wk1, k1, MTOT, DMODEL, DMODEL);
    gemm_tf32<<<ggrid, 256, GEMM_SMEM_BYTES>>>(inp, wv,  v,  MTOT, DMODEL, DMODEL);

    attn_tc_kernel<<<dim3(SEQ / 64, BATCH * NHEAD), 128, ATTN2_SMEM_BYTES>>>(
        q0, q1, k0, k1, v, lnw, lnb, attn);

    gemm_tf32<<<ggrid, 256, GEMM_SMEM_BYTES>>>(attn, wo, out, MTOT, DMODEL, DMODEL);
}

// round 8
// speedup vs baseline: 1.1312x; 1.0395x over previous
#include <cuda_runtime.h>
#include <math.h>
#include <stdint.h>

// Problem constants
#define BATCH 2
#define SEQ   2048
#define DMODEL 1024
#define NHEAD 16
#define DHEAD 64
#define MTOT  (BATCH*SEQ)      // 4096
#define LAMBDA_INIT 0.8f
#define LN_EPS 1e-5f

// ---------------------------------------------------------------------------
// Scratch
// ---------------------------------------------------------------------------
__device__ float g_q0[MTOT*DMODEL];
__device__ float g_q1[MTOT*DMODEL];
__device__ float g_k0[MTOT*DMODEL];
__device__ float g_k1[MTOT*DMODEL];
__device__ float g_v [MTOT*DMODEL];
__device__ float g_attn[MTOT*DMODEL];
__device__ float g_lambda;

__device__ __forceinline__ uint32_t cvt_tf32(float x) {
    uint32_t r;
    asm("cvt.rna.tf32.f32 %0, %1;" : "=r"(r) : "f"(x));
    return r;
}
__device__ __forceinline__ float tf32f(float x) {
    return __uint_as_float(cvt_tf32(x));
}

// ---------------------------------------------------------------------------
// Lambda scalar
// ---------------------------------------------------------------------------
__global__ void lambda_kernel(const float* __restrict__ l0, const float* __restrict__ l1,
                              const float* __restrict__ l2, const float* __restrict__ l3) {
    int t = threadIdx.x; // 32 threads
    float a = l0[t]*l1[t] + l0[t+32]*l1[t+32];
    float b = l2[t]*l3[t] + l2[t+32]*l3[t+32];
    #pragma unroll
    for (int o = 16; o >= 1; o >>= 1) {
        a += __shfl_xor_sync(0xffffffffu, a, o);
        b += __shfl_xor_sync(0xffffffffu, b, o);
    }
    if (t == 0) g_lambda = (-expf(a) + LAMBDA_INIT) + (-expf(b) + LAMBDA_INIT);
}

// ---------------------------------------------------------------------------
// TF32 tensor-core GEMM (R6/R7-measured: 75.6us, regs=127, 2 CTAs/SM)
// ---------------------------------------------------------------------------
#define BM 128
#define BN 128
#define BK 32
#define A_LD 36
#define B_LD 136
#define AS_STAGE (BM*A_LD)
#define BS_STAGE (BK*B_LD)
#define GEMM_SMEM_BYTES ((2*(AS_STAGE+BS_STAGE))*4)

__global__ __launch_bounds__(256, 2) void gemm_tf32(const float* __restrict__ A,
                                                    const float* __restrict__ B,
                                                    float* __restrict__ C,
                                                    int M, int N, int K) {
    extern __shared__ float sm[];
    float* As = sm;
    float* Bs = sm + 2 * AS_STAGE;

    int tid  = threadIdx.x;
    int lane = tid & 31;
    int warp = tid >> 5;
    int g    = lane >> 2;
    int tig  = lane & 3;
    int wm   = (warp >> 2) * 64;
    int wn   = (warp & 3) * 32;

    int bx = blockIdx.x, by = blockIdx.y;

    const float* Ag = A + (size_t)(by * BM) * K;
    const float* Bg = B + bx * BN;

    int a_row = tid >> 3;
    int a_col = (tid & 7) * 4;
    int b_row = tid >> 5;
    int b_col = (tid & 31) * 4;

    uint32_t s_as = (uint32_t)__cvta_generic_to_shared(As);
    uint32_t s_bs = (uint32_t)__cvta_generic_to_shared(Bs);

    float acc[4][4][4];
    #pragma unroll
    for (int i = 0; i < 4; i++)
        #pragma unroll
        for (int j = 0; j < 4; j++)
            #pragma unroll
            for (int q = 0; q < 4; q++) acc[i][j][q] = 0.f;

    uint32_t a_lane_off = ((uint32_t)((wm + (lane & 15)) * A_LD + (lane >> 4) * 4)) * 4u;

    const int NT = K / BK;

    auto prefetch = [&](int kt, int stage) {
        uint32_t ad = s_as + (uint32_t)stage * AS_STAGE * 4;
        const float* ag = Ag + kt * BK;
        #pragma unroll
        for (int r = 0; r < 4; r++) {
            int row = a_row + r * 32;
            uint32_t dst = ad + (uint32_t)(row * A_LD + a_col) * 4;
            const float* src = ag + (size_t)row * K + a_col;
            asm volatile("cp.async.cg.shared.global [%0], [%1], 16;\n" :: "r"(dst), "l"(src));
        }
        uint32_t bd = s_bs + (uint32_t)stage * BS_STAGE * 4;
        const float* bg = Bg + (size_t)(kt * BK) * N;
        #pragma unroll
        for (int r = 0; r < 4; r++) {
            int row = b_row + r * 8;
            uint32_t dst = bd + (uint32_t)(row * B_LD + b_col) * 4;
            const float* src = bg + (size_t)row * N + b_col;
            asm volatile("cp.async.cg.shared.global [%0], [%1], 16;\n" :: "r"(dst), "l"(src));
        }
        asm volatile("cp.async.commit_group;\n");
    };

    prefetch(0, 0);

    for (int kt = 0; kt < NT; kt++) {
        int stage = kt & 1;
        if (kt + 1 < NT) {
            prefetch(kt + 1, stage ^ 1);
            asm volatile("cp.async.wait_group 1;\n");
        } else {
            asm volatile("cp.async.wait_group 0;\n");
        }
        __syncthreads();

        uint32_t a_base = s_as + (uint32_t)stage * AS_STAGE * 4 + a_lane_off;
        const float* bsp = Bs + stage * BS_STAGE;

        #pragma unroll
        for (int k8 = 0; k8 < BK / 8; k8++) {
            uint32_t arg[4][4];
            #pragma unroll
            for (int i = 0; i < 4; i++) {
                uint32_t addr = a_base + (uint32_t)(i * 16 * A_LD + k8 * 8) * 4;
                asm volatile("ldmatrix.sync.aligned.m8n8.x4.shared.b16 {%0,%1,%2,%3}, [%4];\n"
                             : "=r"(arg[i][0]), "=r"(arg[i][1]), "=r"(arg[i][2]), "=r"(arg[i][3])
                             : "r"(addr));
            }
            uint32_t brg[4][2];
            #pragma unroll
            for (int j = 0; j < 4; j++) {
                float b0 = bsp[(k8 * 8 + tig)     * B_LD + wn + j * 8 + g];
                float b1 = bsp[(k8 * 8 + tig + 4) * B_LD + wn + j * 8 + g];
                brg[j][0] = cvt_tf32(b0);
                brg[j][1] = cvt_tf32(b1);
            }
            #pragma unroll
            for (int i = 0; i < 4; i++)
                #pragma unroll
                for (int q = 0; q < 4; q++)
                    arg[i][q] = cvt_tf32(__uint_as_float(arg[i][q]));

            #pragma unroll
            for (int i = 0; i < 4; i++)
                #pragma unroll
                for (int j = 0; j < 4; j++)
                    asm volatile(
                        "mma.sync.aligned.m16n8k8.row.col.f32.tf32.tf32.f32 "
                        "{%0,%1,%2,%3}, {%4,%5,%6,%7}, {%8,%9}, {%0,%1,%2,%3};\n"
                        : "+f"(acc[i][j][0]), "+f"(acc[i][j][1]),
                          "+f"(acc[i][j][2]), "+f"(acc[i][j][3])
                        : "r"(arg[i][0]), "r"(arg[i][1]), "r"(arg[i][2]), "r"(arg[i][3]),
                          "r"(brg[j][0]), "r"(brg[j][1]));
        }
        __syncthreads();
    }

    #pragma unroll
    for (int i = 0; i < 4; i++) {
        int row = by * BM + wm + i * 16 + g;
        #pragma unroll
        for (int j = 0; j < 4; j++) {
            int col = bx * BN + wn + j * 8 + 2 * tig;
            *(float2*)(C + (size_t)row * N + col)       = make_float2(acc[i][j][0], acc[i][j][1]);
            *(float2*)(C + (size_t)(row + 8) * N + col) = make_float2(acc[i][j][2], acc[i][j][3]);
        }
    }
}

// ---------------------------------------------------------------------------
// Tensor-core differential flash attention + per-head LayerNorm.
// 256 threads = 8 warps; q-tile = 128 rows; warp w owns rows [w*16, w*16+16).
// K0/K1/V loaded raw fp32 via cp.async, double-buffered (2 stages).
// tf32 cvt on B-fragments at use (same numerics as cvt-at-load).
// 2 block syncs per kv-tile; K/V global traffic halved vs 64-row tile.
// ---------------------------------------------------------------------------
#define QT 128
#define QLD 68   // %32=4 -> ldmatrix float-quadrant geometry, conflict-free
#define PLD 68
#define KLD 68   // %32=4 -> QK B-frag banks (4g+tig) distinct; 272B %16==0
#define VLD 72   // %32=8 -> PV B-frag banks (8tig+g) distinct; 288B %16==0
#define K_STAGE (64*KLD)   // 4352
#define V_STAGE (64*VLD)   // 4608
#define SQ_OFF  0
#define SK0_OFF (2*QT*QLD)                // 17408
#define SK1_OFF (SK0_OFF + 2*K_STAGE)     // 26112
#define SV_OFF  (SK1_OFF + 2*K_STAGE)     // 34816
#define SP_OFF  (SV_OFF + 2*V_STAGE)      // 44032
#define ATTN2_SMEM_FLOATS (SP_OFF + QT*PLD)    // 52736
#define ATTN2_SMEM_BYTES (ATTN2_SMEM_FLOATS*4) // 210944

__global__ __launch_bounds__(256) void attn_tc_kernel(
        const float* __restrict__ q0b, const float* __restrict__ q1b,
        const float* __restrict__ k0b, const float* __restrict__ k1b,
        const float* __restrict__ vb,
        const float* __restrict__ ln_w, const float* __restrict__ ln_b,
        float* __restrict__ attn) {
    extern __shared__ float sm[];
    float* sQ  = sm + SQ_OFF;    // [2][QT][QLD] tf32 bits
    float* sK0 = sm + SK0_OFF;   // [2][64][KLD] raw fp32
    float* sK1 = sm + SK1_OFF;
    float* sV  = sm + SV_OFF;    // [2][64][VLD] raw fp32
    float* sP  = sm + SP_OFF;    // [QT][PLD] tf32 bits

    int qt = gridDim.x - 1 - blockIdx.x;   // heavy tiles first
    int bh = blockIdx.y;
    int b = bh >> 4, h = bh & 15;

    int tid = threadIdx.x;
    int lane = tid & 31;
    int w = tid >> 5;            // 0..7
    int g = lane >> 2;
    int tig = lane & 3;

    const float scale = 0.125f;
    const float slope = exp2f(-0.5f * (float)(h + 1));
    const size_t base = (size_t)b * SEQ * DMODEL + (size_t)h * DHEAD;

    uint32_t s_q  = (uint32_t)__cvta_generic_to_shared(sQ);
    uint32_t s_k0 = (uint32_t)__cvta_generic_to_shared(sK0);
    uint32_t s_k1 = (uint32_t)__cvta_generic_to_shared(sK1);
    uint32_t s_v  = (uint32_t)__cvta_generic_to_shared(sV);
    uint32_t s_p  = (uint32_t)__cvta_generic_to_shared(sP);

    // --- load Q (both streams), row-major, pre-cvt tf32 ---
    {
        int row = tid >> 1;             // 0..127
        int c0  = (tid & 1) * 32;
        size_t gofs = base + (size_t)(qt * QT + row) * DMODEL + c0;
        #pragma unroll
        for (int st = 0; st < 2; st++) {
            const float* src = (st == 0) ? q0b : q1b;
            float* dst = sQ + st * QT * QLD + row * QLD + c0;
            #pragma unroll
            for (int c = 0; c < 32; c += 4) {
                float4 v4 = *(const float4*)(src + gofs + c);
                dst[c + 0] = tf32f(v4.x);
                dst[c + 1] = tf32f(v4.y);
                dst[c + 2] = tf32f(v4.z);
                dst[c + 3] = tf32f(v4.w);
            }
        }
    }

    float oacc[2][8][4];
    #pragma unroll
    for (int st = 0; st < 2; st++)
        #pragma unroll
        for (int j = 0; j < 8; j++)
            #pragma unroll
            for (int q = 0; q < 4; q++) oacc[st][j][q] = 0.f;
    float mrow[2][2], lrow[2][2];
    #pragma unroll
    for (int st = 0; st < 2; st++)
        #pragma unroll
        for (int hh = 0; hh < 2; hh++) { mrow[st][hh] = -INFINITY; lrow[st][hh] = 0.f; }

    uint32_t qa_lane = ((uint32_t)((w * 16 + (lane & 15)) * QLD + (lane >> 4) * 4)) * 4u;
    uint32_t pa_lane = s_p + ((uint32_t)((w * 16 + (lane & 15)) * PLD + (lane >> 4) * 4)) * 4u;

    const int qrow0 = qt * QT + w * 16;   // warp's first global q row
    const int qq0 = qrow0 + g;

    // cp.async fill coords: 256 threads cover one 64-row tile, 16 floats each
    const int prow = tid >> 2;            // 0..63
    const int pc0  = (tid & 3) * 16;      // 0,16,32,48

    auto prefetch = [&](int kt, int stage) {
        size_t gofs = base + (size_t)(kt * 64 + prow) * DMODEL + pc0;
        const float* gk0 = k0b + gofs;
        const float* gk1 = k1b + gofs;
        const float* gv  = vb  + gofs;
        uint32_t dk0 = s_k0 + (uint32_t)(stage * K_STAGE + prow * KLD + pc0) * 4u;
        uint32_t dk1 = s_k1 + (uint32_t)(stage * K_STAGE + prow * KLD + pc0) * 4u;
        uint32_t dv  = s_v  + (uint32_t)(stage * V_STAGE + prow * VLD + pc0) * 4u;
        #pragma unroll
        for (int c = 0; c < 16; c += 4) {
            asm volatile("cp.async.cg.shared.global [%0], [%1], 16;\n"
                         :: "r"(dk0 + c * 4u), "l"(gk0 + c));
            asm volatile("cp.async.cg.shared.global [%0], [%1], 16;\n"
                         :: "r"(dk1 + c * 4u), "l"(gk1 + c));
            asm volatile("cp.async.cg.shared.global [%0], [%1], 16;\n"
                         :: "r"(dv + c * 4u), "l"(gv + c));
        }
        asm volatile("cp.async.commit_group;\n");
    };

    const int ktmax = 2 * qt + 1;   // kv tiles 0..ktmax cover [0, qt*128+128)

    prefetch(0, 0);

    for (int kt = 0; kt <= ktmax; kt++) {
        int stage = kt & 1;
        if (kt < ktmax) {
            prefetch(kt + 1, stage ^ 1);
            asm volatile("cp.async.wait_group 1;\n");
        } else {
            asm volatile("cp.async.wait_group 0;\n");
        }
        __syncthreads();   // stage data visible

        // warp-uniform: skip tiles fully masked for this warp's 16 rows
        const bool active = (kt * 64 <= qrow0 + 15);
        const bool diag   = (kt * 64 + 63 > qrow0);

        if (active) {
            const float* sKb0 = sK0 + stage * K_STAGE;
            const float* sKb1 = sK1 + stage * K_STAGE;
            const float* sVb  = sV + stage * V_STAGE;

            #pragma unroll
            for (int st = 0; st < 2; st++) {
                const float* sK = (st == 0) ? sKb0 : sKb1;

                // ---- QK: scores [16 q rows x 64 kv] per warp ----
                float sc[8][4];
                #pragma unroll
                for (int j = 0; j < 8; j++)
                    #pragma unroll
                    for (int q = 0; q < 4; q++) sc[j][q] = 0.f;

                uint32_t qa_base = s_q + (uint32_t)(st * QT * QLD) * 4u + qa_lane;
                #pragma unroll
                for (int k8 = 0; k8 < 8; k8++) {
                    uint32_t a0, a1, a2, a3;
                    uint32_t addr = qa_base + (uint32_t)(k8 * 8) * 4u;
                    asm volatile("ldmatrix.sync.aligned.m8n8.x4.shared.b16 {%0,%1,%2,%3}, [%4];\n"
                                 : "=r"(a0), "=r"(a1), "=r"(a2), "=r"(a3) : "r"(addr));
                    #pragma unroll
                    for (int j = 0; j < 8; j++) {
                        const float* kr = sK + (j * 8 + g) * KLD + k8 * 8;
                        uint32_t b0 = cvt_tf32(kr[tig]);
                        uint32_t b1 = cvt_tf32(kr[tig + 4]);
                        asm volatile(
                            "mma.sync.aligned.m16n8k8.row.col.f32.tf32.tf32.f32 "
                            "{%0,%1,%2,%3}, {%4,%5,%6,%7}, {%8,%9}, {%0,%1,%2,%3};\n"
                            : "+f"(sc[j][0]), "+f"(sc[j][1]), "+f"(sc[j][2]), "+f"(sc[j][3])
                            : "r"(a0), "r"(a1), "r"(a2), "r"(a3), "r"(b0), "r"(b1));
                    }
                }

                // ---- softmax (online), rows g and g+8 ----
                #pragma unroll
                for (int hh = 0; hh < 2; hh++) {
                    int qq = qq0 + hh * 8;
                    float mx = -INFINITY;
                    #pragma unroll
                    for (int j = 0; j < 8; j++) {
                        #pragma unroll
                        for (int e = 0; e < 2; e++) {
                            int kk = kt * 64 + j * 8 + 2 * tig + e;
                            float s = sc[j][hh * 2 + e] * scale - slope * (float)(qq - kk);
                            if (diag && kk > qq) s = -INFINITY;
                            sc[j][hh * 2 + e] = s;
                            mx = fmaxf(mx, s);
                        }
                    }
                    mx = fmaxf(mx, __shfl_xor_sync(0xffffffffu, mx, 1));
                    mx = fmaxf(mx, __shfl_xor_sync(0xffffffffu, mx, 2));
                    float mn = fmaxf(mrow[st][hh], mx);
                    float corr = __expf(mrow[st][hh] - mn);
                    mrow[st][hh] = mn;
                    float rs = 0.f;
                    #pragma unroll
                    for (int j = 0; j < 8; j++) {
                        #pragma unroll
                        for (int e = 0; e < 2; e++) {
                            float pv = __expf(sc[j][hh * 2 + e] - mn);
                            sc[j][hh * 2 + e] = pv;
                            rs += pv;
                        }
                    }
                    rs += __shfl_xor_sync(0xffffffffu, rs, 1);
                    rs += __shfl_xor_sync(0xffffffffu, rs, 2);
                    lrow[st][hh] = lrow[st][hh] * corr + rs;
                    #pragma unroll
                    for (int j = 0; j < 8; j++) {
                        oacc[st][j][hh * 2 + 0] *= corr;
                        oacc[st][j][hh * 2 + 1] *= corr;
                    }
                }

                // ---- write P (tf32 bits) to own-warp rows of sP ----
                #pragma unroll
                for (int hh = 0; hh < 2; hh++) {
                    float* pr = sP + (w * 16 + g + hh * 8) * PLD;
                    #pragma unroll
                    for (int j = 0; j < 8; j++) {
                        float2 pv = make_float2(tf32f(sc[j][hh * 2 + 0]),
                                                tf32f(sc[j][hh * 2 + 1]));
                        *(float2*)(pr + j * 8 + 2 * tig) = pv;
                    }
                }
                __syncwarp();  // sP rows warp-private

                // ---- PV: oacc += P @ V ----
                #pragma unroll
                for (int k8 = 0; k8 < 8; k8++) {
                    uint32_t a0, a1, a2, a3;
                    uint32_t addr = pa_lane + (uint32_t)(k8 * 8) * 4u;
                    asm volatile("ldmatrix.sync.aligned.m8n8.x4.shared.b16 {%0,%1,%2,%3}, [%4];\n"
                                 : "=r"(a0), "=r"(a1), "=r"(a2), "=r"(a3) : "r"(addr));
                    const float* vp = sVb + (k8 * 8 + tig) * VLD;
                    #pragma unroll
                    for (int j = 0; j < 8; j++) {
                        uint32_t b0 = cvt_tf32(vp[j * 8 + g]);
                        uint32_t b1 = cvt_tf32(vp[4 * VLD + j * 8 + g]);
                        asm volatile(
                            "mma.sync.aligned.m16n8k8.row.col.f32.tf32.tf32.f32 "
                            "{%0,%1,%2,%3}, {%4,%5,%6,%7}, {%8,%9}, {%0,%1,%2,%3};\n"
                            : "+f"(oacc[st][j][0]), "+f"(oacc[st][j][1]),
                              "+f"(oacc[st][j][2]), "+f"(oacc[st][j][3])
                            : "r"(a0), "r"(a1), "r"(a2), "r"(a3), "r"(b0), "r"(b1));
                    }
                }
                __syncwarp();  // next stream's P write must not pass these reads
            }
        }
        __syncthreads();  // all reads of stage done before it is re-prefetched
    }

    // --- epilogue: combine streams, per-head LayerNorm over DH, store ---
    float lam = g_lambda;
    #pragma unroll
    for (int hh = 0; hh < 2; hh++) {
        float inv0 = 1.0f / lrow[0][hh];
        float inv1 = 1.0f / lrow[1][hh];
        float o[8][2];
        float s_ = 0.f;
        #pragma unroll
        for (int j = 0; j < 8; j++) {
            #pragma unroll
            for (int e = 0; e < 2; e++) {
                float val = oacc[0][j][hh * 2 + e] * inv0
                          - lam * (oacc[1][j][hh * 2 + e] * inv1);
                o[j][e] = val;
                s_ += val;
            }
        }
        s_ += __shfl_xor_sync(0xffffffffu, s_, 1);
        s_ += __shfl_xor_sync(0xffffffffu, s_, 2);
        float mu = s_ * (1.0f / 64.0f);
        float vs = 0.f;
        #pragma unroll
        for (int j = 0; j < 8; j++) {
            #pragma unroll
            for (int e = 0; e < 2; e++) { float d = o[j][e] - mu; vs += d * d; }
        }
        vs += __shfl_xor_sync(0xffffffffu, vs, 1);
        vs += __shfl_xor_sync(0xffffffffu, vs, 2);
        float r = rsqrtf(vs * (1.0f / 64.0f) + LN_EPS);

        size_t row = (size_t)b * SEQ + (size_t)(qrow0 + g + hh * 8);
        #pragma unroll
        for (int j = 0; j < 8; j++) {
            int col = h * DHEAD + j * 8 + 2 * tig;
            float wv0 = ln_w[h * DHEAD + j * 8 + 2 * tig];
            float wv1 = ln_w[h * DHEAD + j * 8 + 2 * tig + 1];
            float bv0 = ln_b[h * DHEAD + j * 8 + 2 * tig];
            float bv1 = ln_b[h * DHEAD + j * 8 + 2 * tig + 1];
            float2 res = make_float2((o[j][0] - mu) * r * wv0 + bv0,
                                     (o[j][1] - mu) * r * wv1 + bv1);
            *(float2*)(attn + row * DMODEL + col) = res;
        }
    }
}

// ---------------------------------------------------------------------------
// Launch
// ---------------------------------------------------------------------------
extern "C" void kernel_launch(void* const* d_in, const int* in_sizes, int n_in,
                              void* d_out, int out_size) {
    const float* inp = (const float*)d_in[0];
    const float* wq0 = (const float*)d_in[1];
    const float* wq1 = (const float*)d_in[2];
    const float* wk0 = (const float*)d_in[3];
    const float* wk1 = (const float*)d_in[4];
    const float* wv  = (const float*)d_in[5];
    const float* wo  = (const float*)d_in[6];
    const float* l0  = (const float*)d_in[7];
    const float* l1  = (const float*)d_in[8];
    const float* l2  = (const float*)d_in[9];
    const float* l3  = (const float*)d_in[10];
    const float* lnw = (const float*)d_in[11];
    const float* lnb = (const float*)d_in[12];
    float* out = (float*)d_out;

    float *q0, *q1, *k0, *k1, *v, *attn;
    cudaGetSymbolAddress((void**)&q0, g_q0);
    cudaGetSymbolAddress((void**)&q1, g_q1);
    cudaGetSymbolAddress((void**)&k0, g_k0);
    cudaGetSymbolAddress((void**)&k1, g_k1);
    cudaGetSymbolAddress((void**)&v,  g_v);
    cudaGetSymbolAddress((void**)&attn, g_attn);

    cudaFuncSetAttribute(gemm_tf32, cudaFuncAttributeMaxDynamicSharedMemorySize,
                         GEMM_SMEM_BYTES);
    cudaFuncSetAttribute(attn_tc_kernel, cudaFuncAttributeMaxDynamicSharedMemorySize,
                         ATTN2_SMEM_BYTES);

    lambda_kernel<<<1, 32>>>(l0, l1, l2, l3);

    dim3 ggrid(DMODEL / 128, MTOT / 128);   // (8, 32)
    gemm_tf32<<<ggrid, 256, GEMM_SMEM_BYTES>>>(inp, wq0, q0, MTOT, DMODEL, DMODEL);
    gemm_tf32<<<ggrid, 256, GEMM_SMEM_BYTES>>>(inp, wq1, q1, MTOT, DMODEL, DMODEL);
    gemm_tf32<<<ggrid, 256, GEMM_SMEM_BYTES>>>(inp, wk0, k0, MTOT, DMODEL, DMODEL);
    gemm_tf32<<<ggrid, 256, GEMM_SMEM_BYTES>>>(inp, wk1, k1, MTOT, DMODEL, DMODEL);
    gemm_tf32<<<ggrid, 256, GEMM_SMEM_BYTES>>>(inp, wv,  v,  MTOT, DMODEL, DMODEL);

    attn_tc_kernel<<<dim3(SEQ / QT, BATCH * NHEAD), 256, ATTN2_SMEM_BYTES>>>(
        q0, q1, k0, k1, v, lnw, lnb, attn);

    gemm_tf32<<<ggrid, 256, GEMM_SMEM_BYTES>>>(attn, wo, out, MTOT, DMODEL, DMODEL);
}

// round 9
// speedup vs baseline: 1.3854x; 1.2248x over previous
#include <cuda_runtime.h>
#include <cuda_fp16.h>
#include <math.h>
#include <stdint.h>

// Problem constants
#define BATCH 2
#define SEQ   2048
#define DMODEL 1024
#define NHEAD 16
#define DHEAD 64
#define MTOT  (BATCH*SEQ)      // 4096
#define LAMBDA_INIT 0.8f
#define LN_EPS 1e-5f

// ---------------------------------------------------------------------------
// Scratch
// ---------------------------------------------------------------------------
__device__ float g_q0[MTOT*DMODEL];
__device__ float g_q1[MTOT*DMODEL];
__device__ float g_k0[MTOT*DMODEL];
__device__ float g_k1[MTOT*DMODEL];
__device__ float g_v [MTOT*DMODEL];
__device__ __half g_xh[MTOT*DMODEL];
__device__ __half g_attnh[MTOT*DMODEL];
__device__ __half g_w0h[DMODEL*DMODEL];
__device__ __half g_w1h[DMODEL*DMODEL];
__device__ __half g_w2h[DMODEL*DMODEL];
__device__ __half g_w3h[DMODEL*DMODEL];
__device__ __half g_w4h[DMODEL*DMODEL];
__device__ __half g_woh[DMODEL*DMODEL];
__device__ float g_lambda;

__device__ __forceinline__ uint32_t cvt_tf32(float x) {
    uint32_t r;
    asm("cvt.rna.tf32.f32 %0, %1;" : "=r"(r) : "f"(x));
    return r;
}
__device__ __forceinline__ float tf32f(float x) {
    return __uint_as_float(cvt_tf32(x));
}

// ---------------------------------------------------------------------------
// fp32 -> fp16 conversion (n % 4 == 0)
// ---------------------------------------------------------------------------
__global__ void f2h_kernel(const float* __restrict__ in, __half* __restrict__ out, int n) {
    int i = (blockIdx.x * blockDim.x + threadIdx.x) * 4;
    if (i < n) {
        float4 v = *(const float4*)(in + i);
        __half2 h0 = __floats2half2_rn(v.x, v.y);
        __half2 h1 = __floats2half2_rn(v.z, v.w);
        *(__half2*)(out + i)     = h0;
        *(__half2*)(out + i + 2) = h1;
    }
}

// ---------------------------------------------------------------------------
// Lambda scalar
// ---------------------------------------------------------------------------
__global__ void lambda_kernel(const float* __restrict__ l0, const float* __restrict__ l1,
                              const float* __restrict__ l2, const float* __restrict__ l3) {
    int t = threadIdx.x; // 32 threads
    float a = l0[t]*l1[t] + l0[t+32]*l1[t+32];
    float b = l2[t]*l3[t] + l2[t+32]*l3[t+32];
    #pragma unroll
    for (int o = 16; o >= 1; o >>= 1) {
        a += __shfl_xor_sync(0xffffffffu, a, o);
        b += __shfl_xor_sync(0xffffffffu, b, o);
    }
    if (t == 0) g_lambda = (-expf(a) + LAMBDA_INIT) + (-expf(b) + LAMBDA_INIT);
}

// ---------------------------------------------------------------------------
// FP16 tensor-core GEMM: C[M,N](f32) = A[M,K](f16) @ B[K,N](f16).
// 128x128x64 block tile, 256 threads (8 warps 2m x 4n, 64x32 warp tiles),
// mma.m16n8k16.f16 (fp32 accum), cp.async double-buffered, ldmatrix both ops.
// ---------------------------------------------------------------------------
#define HBM 128
#define HBN 128
#define HBK 64
#define A_LDH 72    // halves; 144B pitch, 144%128=16 -> ldmatrix conflict-free
#define B_LDH 136   // halves; 272B pitch, 272%128=16 -> trans ldmatrix conflict-free
#define HAS_STAGE (HBM*A_LDH)  // 9216 halves
#define HBS_STAGE (HBK*B_LDH)  // 8704 halves
#define HGEMM_SMEM_BYTES ((2*(HAS_STAGE+HBS_STAGE))*2)  // 71680 B

__global__ __launch_bounds__(256, 2) void gemm_f16(const __half* __restrict__ A,
                                                   const __half* __restrict__ B,
                                                   float* __restrict__ C,
                                                   int M, int N, int K) {
    extern __shared__ __align__(16) char smraw[];
    __half* As = (__half*)smraw;
    __half* Bs = As + 2 * HAS_STAGE;

    int tid  = threadIdx.x;
    int lane = tid & 31;
    int warp = tid >> 5;
    int g    = lane >> 2;
    int tig  = lane & 3;
    int wm   = (warp >> 2) * 64;
    int wn   = (warp & 3) * 32;

    int bx = blockIdx.x, by = blockIdx.y;

    const __half* Ag = A + (size_t)(by * HBM) * K;
    const __half* Bg = B + bx * HBN;

    uint32_t s_as = (uint32_t)__cvta_generic_to_shared(As);
    uint32_t s_bs = (uint32_t)__cvta_generic_to_shared(Bs);

    float acc[4][4][4];
    #pragma unroll
    for (int i = 0; i < 4; i++)
        #pragma unroll
        for (int j = 0; j < 4; j++)
            #pragma unroll
            for (int q = 0; q < 4; q++) acc[i][j][q] = 0.f;

    // ldmatrix lane base offsets (bytes)
    uint32_t a_lane = ((uint32_t)((wm + (lane & 15)) * A_LDH + (lane >> 4) * 8)) * 2u;
    uint32_t b_lane = ((uint32_t)((lane & 15) * B_LDH + wn + (lane >> 4) * 8)) * 2u;

    const int NT = K / HBK;

    auto prefetch = [&](int kt, int stage) {
        uint32_t ad = s_as + (uint32_t)(stage * HAS_STAGE) * 2u;
        uint32_t bd = s_bs + (uint32_t)(stage * HBS_STAGE) * 2u;
        const __half* agk = Ag + kt * HBK;
        const __half* bgk = Bg + (size_t)(kt * HBK) * N;
        #pragma unroll
        for (int r = 0; r < 4; r++) {
            int c = tid + r * 256;
            int arow = c >> 3, acol = (c & 7) * 8;
            asm volatile("cp.async.cg.shared.global [%0], [%1], 16;\n"
                         :: "r"(ad + (uint32_t)(arow * A_LDH + acol) * 2u),
                            "l"(agk + (size_t)arow * K + acol));
            int brow = c >> 4, bcol = (c & 15) * 8;
            asm volatile("cp.async.cg.shared.global [%0], [%1], 16;\n"
                         :: "r"(bd + (uint32_t)(brow * B_LDH + bcol) * 2u),
                            "l"(bgk + (size_t)brow * N + bcol));
        }
        asm volatile("cp.async.commit_group;\n");
    };

    prefetch(0, 0);

    for (int kt = 0; kt < NT; kt++) {
        int stage = kt & 1;
        if (kt + 1 < NT) {
            prefetch(kt + 1, stage ^ 1);
            asm volatile("cp.async.wait_group 1;\n");
        } else {
            asm volatile("cp.async.wait_group 0;\n");
        }
        __syncthreads();

        uint32_t a_base = s_as + (uint32_t)(stage * HAS_STAGE) * 2u + a_lane;
        uint32_t b_base = s_bs + (uint32_t)(stage * HBS_STAGE) * 2u + b_lane;

        #pragma unroll
        for (int k16 = 0; k16 < HBK / 16; k16++) {
            uint32_t a[4][4];
            #pragma unroll
            for (int i = 0; i < 4; i++) {
                uint32_t addr = a_base + (uint32_t)(i * 16 * A_LDH + k16 * 16) * 2u;
                asm volatile("ldmatrix.sync.aligned.m8n8.x4.shared.b16 {%0,%1,%2,%3}, [%4];\n"
                             : "=r"(a[i][0]), "=r"(a[i][1]), "=r"(a[i][2]), "=r"(a[i][3])
                             : "r"(addr));
            }
            uint32_t bf[4][2];
            #pragma unroll
            for (int jp = 0; jp < 2; jp++) {
                uint32_t addr = b_base + (uint32_t)(k16 * 16 * B_LDH + jp * 16) * 2u;
                asm volatile("ldmatrix.sync.aligned.m8n8.x4.trans.shared.b16 {%0,%1,%2,%3}, [%4];\n"
                             : "=r"(bf[2*jp][0]), "=r"(bf[2*jp][1]),
                               "=r"(bf[2*jp+1][0]), "=r"(bf[2*jp+1][1])
                             : "r"(addr));
            }
            #pragma unroll
            for (int i = 0; i < 4; i++)
                #pragma unroll
                for (int j = 0; j < 4; j++)
                    asm volatile(
                        "mma.sync.aligned.m16n8k16.row.col.f32.f16.f16.f32 "
                        "{%0,%1,%2,%3}, {%4,%5,%6,%7}, {%8,%9}, {%0,%1,%2,%3};\n"
                        : "+f"(acc[i][j][0]), "+f"(acc[i][j][1]),
                          "+f"(acc[i][j][2]), "+f"(acc[i][j][3])
                        : "r"(a[i][0]), "r"(a[i][1]), "r"(a[i][2]), "r"(a[i][3]),
                          "r"(bf[j][0]), "r"(bf[j][1]));
        }
        __syncthreads();
    }

    #pragma unroll
    for (int i = 0; i < 4; i++) {
        int row = by * HBM + wm + i * 16 + g;
        #pragma unroll
        for (int j = 0; j < 4; j++) {
            int col = bx * HBN + wn + j * 8 + 2 * tig;
            *(float2*)(C + (size_t)row * N + col)       = make_float2(acc[i][j][0], acc[i][j][1]);
            *(float2*)(C + (size_t)(row + 8) * N + col) = make_float2(acc[i][j][2], acc[i][j][3]);
        }
    }
}

// ---------------------------------------------------------------------------
// Tensor-core differential flash attention + per-head LayerNorm.
// R8-measured structure; only change: epilogue writes fp16 directly.
// ---------------------------------------------------------------------------
#define QT 128
#define QLD 68
#define PLD 68
#define KLD 68
#define VLD 72
#define K_STAGE (64*KLD)   // 4352
#define V_STAGE (64*VLD)   // 4608
#define SQ_OFF  0
#define SK0_OFF (2*QT*QLD)
#define SK1_OFF (SK0_OFF + 2*K_STAGE)
#define SV_OFF  (SK1_OFF + 2*K_STAGE)
#define SP_OFF  (SV_OFF + 2*V_STAGE)
#define ATTN2_SMEM_FLOATS (SP_OFF + QT*PLD)
#define ATTN2_SMEM_BYTES (ATTN2_SMEM_FLOATS*4)

__global__ __launch_bounds__(256) void attn_tc_kernel(
        const float* __restrict__ q0b, const float* __restrict__ q1b,
        const float* __restrict__ k0b, const float* __restrict__ k1b,
        const float* __restrict__ vb,
        const float* __restrict__ ln_w, const float* __restrict__ ln_b,
        __half* __restrict__ attnh) {
    extern __shared__ float sm[];
    float* sQ  = sm + SQ_OFF;
    float* sK0 = sm + SK0_OFF;
    float* sK1 = sm + SK1_OFF;
    float* sV  = sm + SV_OFF;
    float* sP  = sm + SP_OFF;

    int qt = gridDim.x - 1 - blockIdx.x;
    int bh = blockIdx.y;
    int b = bh >> 4, h = bh & 15;

    int tid = threadIdx.x;
    int lane = tid & 31;
    int w = tid >> 5;
    int g = lane >> 2;
    int tig = lane & 3;

    const float scale = 0.125f;
    const float slope = exp2f(-0.5f * (float)(h + 1));
    const size_t base = (size_t)b * SEQ * DMODEL + (size_t)h * DHEAD;

    uint32_t s_q  = (uint32_t)__cvta_generic_to_shared(sQ);
    uint32_t s_k0 = (uint32_t)__cvta_generic_to_shared(sK0);
    uint32_t s_k1 = (uint32_t)__cvta_generic_to_shared(sK1);
    uint32_t s_v  = (uint32_t)__cvta_generic_to_shared(sV);
    uint32_t s_p  = (uint32_t)__cvta_generic_to_shared(sP);

    {
        int row = tid >> 1;
        int c0  = (tid & 1) * 32;
        size_t gofs = base + (size_t)(qt * QT + row) * DMODEL + c0;
        #pragma unroll
        for (int st = 0; st < 2; st++) {
            const float* src = (st == 0) ? q0b : q1b;
            float* dst = sQ + st * QT * QLD + row * QLD + c0;
            #pragma unroll
            for (int c = 0; c < 32; c += 4) {
                float4 v4 = *(const float4*)(src + gofs + c);
                dst[c + 0] = tf32f(v4.x);
                dst[c + 1] = tf32f(v4.y);
                dst[c + 2] = tf32f(v4.z);
                dst[c + 3] = tf32f(v4.w);
            }
        }
    }

    float oacc[2][8][4];
    #pragma unroll
    for (int st = 0; st < 2; st++)
        #pragma unroll
        for (int j = 0; j < 8; j++)
            #pragma unroll
            for (int q = 0; q < 4; q++) oacc[st][j][q] = 0.f;
    float mrow[2][2], lrow[2][2];
    #pragma unroll
    for (int st = 0; st < 2; st++)
        #pragma unroll
        for (int hh = 0; hh < 2; hh++) { mrow[st][hh] = -INFINITY; lrow[st][hh] = 0.f; }

    uint32_t qa_lane = ((uint32_t)((w * 16 + (lane & 15)) * QLD + (lane >> 4) * 4)) * 4u;
    uint32_t pa_lane = s_p + ((uint32_t)((w * 16 + (lane & 15)) * PLD + (lane >> 4) * 4)) * 4u;

    const int qrow0 = qt * QT + w * 16;
    const int qq0 = qrow0 + g;

    const int prow = tid >> 2;
    const int pc0  = (tid & 3) * 16;

    auto prefetch = [&](int kt, int stage) {
        size_t gofs = base + (size_t)(kt * 64 + prow) * DMODEL + pc0;
        const float* gk0 = k0b + gofs;
        const float* gk1 = k1b + gofs;
        const float* gv  = vb  + gofs;
        uint32_t dk0 = s_k0 + (uint32_t)(stage * K_STAGE + prow * KLD + pc0) * 4u;
        uint32_t dk1 = s_k1 + (uint32_t)(stage * K_STAGE + prow * KLD + pc0) * 4u;
        uint32_t dv  = s_v  + (uint32_t)(stage * V_STAGE + prow * VLD + pc0) * 4u;
        #pragma unroll
        for (int c = 0; c < 16; c += 4) {
            asm volatile("cp.async.cg.shared.global [%0], [%1], 16;\n"
                         :: "r"(dk0 + c * 4u), "l"(gk0 + c));
            asm volatile("cp.async.cg.shared.global [%0], [%1], 16;\n"
                         :: "r"(dk1 + c * 4u), "l"(gk1 + c));
            asm volatile("cp.async.cg.shared.global [%0], [%1], 16;\n"
                         :: "r"(dv + c * 4u), "l"(gv + c));
        }
        asm volatile("cp.async.commit_group;\n");
    };

    const int ktmax = 2 * qt + 1;

    prefetch(0, 0);

    for (int kt = 0; kt <= ktmax; kt++) {
        int stage = kt & 1;
        if (kt < ktmax) {
            prefetch(kt + 1, stage ^ 1);
            asm volatile("cp.async.wait_group 1;\n");
        } else {
            asm volatile("cp.async.wait_group 0;\n");
        }
        __syncthreads();

        const bool active = (kt * 64 <= qrow0 + 15);
        const bool diag   = (kt * 64 + 63 > qrow0);

        if (active) {
            const float* sKb0 = sK0 + stage * K_STAGE;
            const float* sKb1 = sK1 + stage * K_STAGE;
            const float* sVb  = sV + stage * V_STAGE;

            #pragma unroll
            for (int st = 0; st < 2; st++) {
                const float* sK = (st == 0) ? sKb0 : sKb1;

                float sc[8][4];
                #pragma unroll
                for (int j = 0; j < 8; j++)
                    #pragma unroll
                    for (int q = 0; q < 4; q++) sc[j][q] = 0.f;

                uint32_t qa_base = s_q + (uint32_t)(st * QT * QLD) * 4u + qa_lane;
                #pragma unroll
                for (int k8 = 0; k8 < 8; k8++) {
                    uint32_t a0, a1, a2, a3;
                    uint32_t addr = qa_base + (uint32_t)(k8 * 8) * 4u;
                    asm volatile("ldmatrix.sync.aligned.m8n8.x4.shared.b16 {%0,%1,%2,%3}, [%4];\n"
                                 : "=r"(a0), "=r"(a1), "=r"(a2), "=r"(a3) : "r"(addr));
                    #pragma unroll
                    for (int j = 0; j < 8; j++) {
                        const float* kr = sK + (j * 8 + g) * KLD + k8 * 8;
                        uint32_t b0 = cvt_tf32(kr[tig]);
                        uint32_t b1 = cvt_tf32(kr[tig + 4]);
                        asm volatile(
                            "mma.sync.aligned.m16n8k8.row.col.f32.tf32.tf32.f32 "
                            "{%0,%1,%2,%3}, {%4,%5,%6,%7}, {%8,%9}, {%0,%1,%2,%3};\n"
                            : "+f"(sc[j][0]), "+f"(sc[j][1]), "+f"(sc[j][2]), "+f"(sc[j][3])
                            : "r"(a0), "r"(a1), "r"(a2), "r"(a3), "r"(b0), "r"(b1));
                    }
                }

                #pragma unroll
                for (int hh = 0; hh < 2; hh++) {
                    int qq = qq0 + hh * 8;
                    float mx = -INFINITY;
                    #pragma unroll
                    for (int j = 0; j < 8; j++) {
                        #pragma unroll
                        for (int e = 0; e < 2; e++) {
                            int kk = kt * 64 + j * 8 + 2 * tig + e;
                            float s = sc[j][hh * 2 + e] * scale - slope * (float)(qq - kk);
                            if (diag && kk > qq) s = -INFINITY;
                            sc[j][hh * 2 + e] = s;
                            mx = fmaxf(mx, s);
                        }
                    }
                    mx = fmaxf(mx, __shfl_xor_sync(0xffffffffu, mx, 1));
                    mx = fmaxf(mx, __shfl_xor_sync(0xffffffffu, mx, 2));
                    float mn = fmaxf(mrow[st][hh], mx);
                    float corr = __expf(mrow[st][hh] - mn);
                    mrow[st][hh] = mn;
                    float rs = 0.f;
                    #pragma unroll
                    for (int j = 0; j < 8; j++) {
                        #pragma unroll
                        for (int e = 0; e < 2; e++) {
                            float pv = __expf(sc[j][hh * 2 + e] - mn);
                            sc[j][hh * 2 + e] = pv;
                            rs += pv;
                        }
                    }
                    rs += __shfl_xor_sync(0xffffffffu, rs, 1);
                    rs += __shfl_xor_sync(0xffffffffu, rs, 2);
                    lrow[st][hh] = lrow[st][hh] * corr + rs;
                    #pragma unroll
                    for (int j = 0; j < 8; j++) {
                        oacc[st][j][hh * 2 + 0] *= corr;
                        oacc[st][j][hh * 2 + 1] *= corr;
                    }
                }

                #pragma unroll
                for (int hh = 0; hh < 2; hh++) {
                    float* pr = sP + (w * 16 + g + hh * 8) * PLD;
                    #pragma unroll
                    for (int j = 0; j < 8; j++) {
                        float2 pv = make_float2(tf32f(sc[j][hh * 2 + 0]),
                                                tf32f(sc[j][hh * 2 + 1]));
                        *(float2*)(pr + j * 8 + 2 * tig) = pv;
                    }
                }
                __syncwarp();

                #pragma unroll
                for (int k8 = 0; k8 < 8; k8++) {
                    uint32_t a0, a1, a2, a3;
                    uint32_t addr = pa_lane + (uint32_t)(k8 * 8) * 4u;
                    asm volatile("ldmatrix.sync.aligned.m8n8.x4.shared.b16 {%0,%1,%2,%3}, [%4];\n"
                                 : "=r"(a0), "=r"(a1), "=r"(a2), "=r"(a3) : "r"(addr));
                    const float* vp = sVb + (k8 * 8 + tig) * VLD;
                    #pragma unroll
                    for (int j = 0; j < 8; j++) {
                        uint32_t b0 = cvt_tf32(vp[j * 8 + g]);
                        uint32_t b1 = cvt_tf32(vp[4 * VLD + j * 8 + g]);
                        asm volatile(
                            "mma.sync.aligned.m16n8k8.row.col.f32.tf32.tf32.f32 "
                            "{%0,%1,%2,%3}, {%4,%5,%6,%7}, {%8,%9}, {%0,%1,%2,%3};\n"
                            : "+f"(oacc[st][j][0]), "+f"(oacc[st][j][1]),
                              "+f"(oacc[st][j][2]), "+f"(oacc[st][j][3])
                            : "r"(a0), "r"(a1), "r"(a2), "r"(a3), "r"(b0), "r"(b1));
                    }
                }
                __syncwarp();
            }
        }
        __syncthreads();
    }

    // --- epilogue: combine streams, per-head LayerNorm over DH, store fp16 ---
    float lam = g_lambda;
    #pragma unroll
    for (int hh = 0; hh < 2; hh++) {
        float inv0 = 1.0f / lrow[0][hh];
        float inv1 = 1.0f / lrow[1][hh];
        float o[8][2];
        float s_ = 0.f;
        #pragma unroll
        for (int j = 0; j < 8; j++) {
            #pragma unroll
            for (int e = 0; e < 2; e++) {
                float val = oacc[0][j][hh * 2 + e] * inv0
                          - lam * (oacc[1][j][hh * 2 + e] * inv1);
                o[j][e] = val;
                s_ += val;
            }
        }
        s_ += __shfl_xor_sync(0xffffffffu, s_, 1);
        s_ += __shfl_xor_sync(0xffffffffu, s_, 2);
        float mu = s_ * (1.0f / 64.0f);
        float vs = 0.f;
        #pragma unroll
        for (int j = 0; j < 8; j++) {
            #pragma unroll
            for (int e = 0; e < 2; e++) { float d = o[j][e] - mu; vs += d * d; }
        }
        vs += __shfl_xor_sync(0xffffffffu, vs, 1);
        vs += __shfl_xor_sync(0xffffffffu, vs, 2);
        float r = rsqrtf(vs * (1.0f / 64.0f) + LN_EPS);

        size_t row = (size_t)b * SEQ + (size_t)(qrow0 + g + hh * 8);
        #pragma unroll
        for (int j = 0; j < 8; j++) {
            int col = h * DHEAD + j * 8 + 2 * tig;
            float wv0 = ln_w[h * DHEAD + j * 8 + 2 * tig];
            float wv1 = ln_w[h * DHEAD + j * 8 + 2 * tig + 1];
            float bv0 = ln_b[h * DHEAD + j * 8 + 2 * tig];
            float bv1 = ln_b[h * DHEAD + j * 8 + 2 * tig + 1];
            __half2 hres = __floats2half2_rn((o[j][0] - mu) * r * wv0 + bv0,
                                             (o[j][1] - mu) * r * wv1 + bv1);
            *(__half2*)(attnh + row * DMODEL + col) = hres;
        }
    }
}

// ---------------------------------------------------------------------------
// Launch
// ---------------------------------------------------------------------------
extern "C" void kernel_launch(void* const* d_in, const int* in_sizes, int n_in,
                              void* d_out, int out_size) {
    const float* inp = (const float*)d_in[0];
    const float* wq0 = (const float*)d_in[1];
    const float* wq1 = (const float*)d_in[2];
    const float* wk0 = (const float*)d_in[3];
    const float* wk1 = (const float*)d_in[4];
    const float* wv  = (const float*)d_in[5];
    const float* wo  = (const float*)d_in[6];
    const float* l0  = (const float*)d_in[7];
    const float* l1  = (const float*)d_in[8];
    const float* l2  = (const float*)d_in[9];
    const float* l3  = (const float*)d_in[10];
    const float* lnw = (const float*)d_in[11];
    const float* lnb = (const float*)d_in[12];
    float* out = (float*)d_out;

    float *q0, *q1, *k0, *k1, *v;
    __half *xh, *attnh, *w0h, *w1h, *w2h, *w3h, *w4h, *woh;
    cudaGetSymbolAddress((void**)&q0, g_q0);
    cudaGetSymbolAddress((void**)&q1, g_q1);
    cudaGetSymbolAddress((void**)&k0, g_k0);
    cudaGetSymbolAddress((void**)&k1, g_k1);
    cudaGetSymbolAddress((void**)&v,  g_v);
    cudaGetSymbolAddress((void**)&xh, g_xh);
    cudaGetSymbolAddress((void**)&attnh, g_attnh);
    cudaGetSymbolAddress((void**)&w0h, g_w0h);
    cudaGetSymbolAddress((void**)&w1h, g_w1h);
    cudaGetSymbolAddress((void**)&w2h, g_w2h);
    cudaGetSymbolAddress((void**)&w3h, g_w3h);
    cudaGetSymbolAddress((void**)&w4h, g_w4h);
    cudaGetSymbolAddress((void**)&woh, g_woh);

    cudaFuncSetAttribute(gemm_f16, cudaFuncAttributeMaxDynamicSharedMemorySize,
                         HGEMM_SMEM_BYTES);
    cudaFuncSetAttribute(attn_tc_kernel, cudaFuncAttributeMaxDynamicSharedMemorySize,
                         ATTN2_SMEM_BYTES);

    lambda_kernel<<<1, 32>>>(l0, l1, l2, l3);

    const int NX = MTOT * DMODEL;       // 4M
    const int NW = DMODEL * DMODEL;     // 1M
    f2h_kernel<<<NX / 1024, 256>>>(inp, xh, NX);
    f2h_kernel<<<NW / 1024, 256>>>(wq0, w0h, NW);
    f2h_kernel<<<NW / 1024, 256>>>(wq1, w1h, NW);
    f2h_kernel<<<NW / 1024, 256>>>(wk0, w2h, NW);
    f2h_kernel<<<NW / 1024, 256>>>(wk1, w3h, NW);
    f2h_kernel<<<NW / 1024, 256>>>(wv,  w4h, NW);
    f2h_kernel<<<NW / 1024, 256>>>(wo,  woh, NW);

    dim3 ggrid(DMODEL / 128, MTOT / 128);   // (8, 32)
    gemm_f16<<<ggrid, 256, HGEMM_SMEM_BYTES>>>(xh, w0h, q0, MTOT, DMODEL, DMODEL);
    gemm_f16<<<ggrid, 256, HGEMM_SMEM_BYTES>>>(xh, w1h, q1, MTOT, DMODEL, DMODEL);
    gemm_f16<<<ggrid, 256, HGEMM_SMEM_BYTES>>>(xh, w2h, k0, MTOT, DMODEL, DMODEL);
    gemm_f16<<<ggrid, 256, HGEMM_SMEM_BYTES>>>(xh, w3h, k1, MTOT, DMODEL, DMODEL);
    gemm_f16<<<ggrid, 256, HGEMM_SMEM_BYTES>>>(xh, w4h, v,  MTOT, DMODEL, DMODEL);

    attn_tc_kernel<<<dim3(SEQ / QT, BATCH * NHEAD), 256, ATTN2_SMEM_BYTES>>>(
        q0, q1, k0, k1, v, lnw, lnb, attnh);

    gemm_f16<<<ggrid, 256, HGEMM_SMEM_BYTES>>>(attnh, woh, out, MTOT, DMODEL, DMODEL);
}

// round 10
// speedup vs baseline: 2.2883x; 1.6517x over previous
#include <cuda_runtime.h>
#include <cuda_fp16.h>
#include <math.h>
#include <stdint.h>

// Problem constants
#define BATCH 2
#define SEQ   2048
#define DMODEL 1024
#define NHEAD 16
#define DHEAD 64
#define MTOT  (BATCH*SEQ)      // 4096
#define LAMBDA_INIT 0.8f
#define LN_EPS 1e-5f

// ---------------------------------------------------------------------------
// Scratch
// ---------------------------------------------------------------------------
__device__ __half g_q0[MTOT*DMODEL];
__device__ __half g_q1[MTOT*DMODEL];
__device__ __half g_k0[MTOT*DMODEL];
__device__ __half g_k1[MTOT*DMODEL];
__device__ __half g_v [MTOT*DMODEL];
__device__ __half g_xh[MTOT*DMODEL];
__device__ __half g_attnh[MTOT*DMODEL];
__device__ __half g_w0h[DMODEL*DMODEL];
__device__ __half g_w1h[DMODEL*DMODEL];
__device__ __half g_w2h[DMODEL*DMODEL];
__device__ __half g_w3h[DMODEL*DMODEL];
__device__ __half g_w4h[DMODEL*DMODEL];
__device__ __half g_woh[DMODEL*DMODEL];
__device__ float g_lambda;

// ---------------------------------------------------------------------------
// fp32 -> fp16 conversion (n % 4 == 0)
// ---------------------------------------------------------------------------
__global__ void f2h_kernel(const float* __restrict__ in, __half* __restrict__ out, int n) {
    int i = (blockIdx.x * blockDim.x + threadIdx.x) * 4;
    if (i < n) {
        float4 v = *(const float4*)(in + i);
        *(__half2*)(out + i)     = __floats2half2_rn(v.x, v.y);
        *(__half2*)(out + i + 2) = __floats2half2_rn(v.z, v.w);
    }
}

// ---------------------------------------------------------------------------
// Lambda scalar
// ---------------------------------------------------------------------------
__global__ void lambda_kernel(const float* __restrict__ l0, const float* __restrict__ l1,
                              const float* __restrict__ l2, const float* __restrict__ l3) {
    int t = threadIdx.x;
    float a = l0[t]*l1[t] + l0[t+32]*l1[t+32];
    float b = l2[t]*l3[t] + l2[t+32]*l3[t+32];
    #pragma unroll
    for (int o = 16; o >= 1; o >>= 1) {
        a += __shfl_xor_sync(0xffffffffu, a, o);
        b += __shfl_xor_sync(0xffffffffu, b, o);
    }
    if (t == 0) g_lambda = (-expf(a) + LAMBDA_INIT) + (-expf(b) + LAMBDA_INIT);
}

// ---------------------------------------------------------------------------
// FP16 tensor-core GEMM: C[M,N] = A[M,K](f16) @ B[K,N](f16), fp32 accum.
// Output type templated: float (final) or __half (q/k/v).
// ---------------------------------------------------------------------------
#define HBM 128
#define HBN 128
#define HBK 64
#define A_LDH 72
#define B_LDH 136
#define HAS_STAGE (HBM*A_LDH)
#define HBS_STAGE (HBK*B_LDH)
#define HGEMM_SMEM_BYTES ((2*(HAS_STAGE+HBS_STAGE))*2)

template <typename CT>
__global__ __launch_bounds__(256, 2) void gemm_f16(const __half* __restrict__ A,
                                                   const __half* __restrict__ B,
                                                   CT* __restrict__ C,
                                                   int M, int N, int K) {
    extern __shared__ __align__(16) char smraw[];
    __half* As = (__half*)smraw;
    __half* Bs = As + 2 * HAS_STAGE;

    int tid  = threadIdx.x;
    int lane = tid & 31;
    int warp = tid >> 5;
    int g    = lane >> 2;
    int tig  = lane & 3;
    int wm   = (warp >> 2) * 64;
    int wn   = (warp & 3) * 32;

    int bx = blockIdx.x, by = blockIdx.y;

    const __half* Ag = A + (size_t)(by * HBM) * K;
    const __half* Bg = B + bx * HBN;

    uint32_t s_as = (uint32_t)__cvta_generic_to_shared(As);
    uint32_t s_bs = (uint32_t)__cvta_generic_to_shared(Bs);

    float acc[4][4][4];
    #pragma unroll
    for (int i = 0; i < 4; i++)
        #pragma unroll
        for (int j = 0; j < 4; j++)
            #pragma unroll
            for (int q = 0; q < 4; q++) acc[i][j][q] = 0.f;

    uint32_t a_lane = ((uint32_t)((wm + (lane & 15)) * A_LDH + (lane >> 4) * 8)) * 2u;
    uint32_t b_lane = ((uint32_t)((lane & 15) * B_LDH + wn + (lane >> 4) * 8)) * 2u;

    const int NT = K / HBK;

    auto prefetch = [&](int kt, int stage) {
        uint32_t ad = s_as + (uint32_t)(stage * HAS_STAGE) * 2u;
        uint32_t bd = s_bs + (uint32_t)(stage * HBS_STAGE) * 2u;
        const __half* agk = Ag + kt * HBK;
        const __half* bgk = Bg + (size_t)(kt * HBK) * N;
        #pragma unroll
        for (int r = 0; r < 4; r++) {
            int c = tid + r * 256;
            int arow = c >> 3, acol = (c & 7) * 8;
            asm volatile("cp.async.cg.shared.global [%0], [%1], 16;\n"
                         :: "r"(ad + (uint32_t)(arow * A_LDH + acol) * 2u),
                            "l"(agk + (size_t)arow * K + acol));
            int brow = c >> 4, bcol = (c & 15) * 8;
            asm volatile("cp.async.cg.shared.global [%0], [%1], 16;\n"
                         :: "r"(bd + (uint32_t)(brow * B_LDH + bcol) * 2u),
                            "l"(bgk + (size_t)brow * N + bcol));
        }
        asm volatile("cp.async.commit_group;\n");
    };

    prefetch(0, 0);

    for (int kt = 0; kt < NT; kt++) {
        int stage = kt & 1;
        if (kt + 1 < NT) {
            prefetch(kt + 1, stage ^ 1);
            asm volatile("cp.async.wait_group 1;\n");
        } else {
            asm volatile("cp.async.wait_group 0;\n");
        }
        __syncthreads();

        uint32_t a_base = s_as + (uint32_t)(stage * HAS_STAGE) * 2u + a_lane;
        uint32_t b_base = s_bs + (uint32_t)(stage * HBS_STAGE) * 2u + b_lane;

        #pragma unroll
        for (int k16 = 0; k16 < HBK / 16; k16++) {
            uint32_t a[4][4];
            #pragma unroll
            for (int i = 0; i < 4; i++) {
                uint32_t addr = a_base + (uint32_t)(i * 16 * A_LDH + k16 * 16) * 2u;
                asm volatile("ldmatrix.sync.aligned.m8n8.x4.shared.b16 {%0,%1,%2,%3}, [%4];\n"
                             : "=r"(a[i][0]), "=r"(a[i][1]), "=r"(a[i][2]), "=r"(a[i][3])
                             : "r"(addr));
            }
            uint32_t bf[4][2];
            #pragma unroll
            for (int jp = 0; jp < 2; jp++) {
                uint32_t addr = b_base + (uint32_t)(k16 * 16 * B_LDH + jp * 16) * 2u;
                asm volatile("ldmatrix.sync.aligned.m8n8.x4.trans.shared.b16 {%0,%1,%2,%3}, [%4];\n"
                             : "=r"(bf[2*jp][0]), "=r"(bf[2*jp][1]),
                               "=r"(bf[2*jp+1][0]), "=r"(bf[2*jp+1][1])
                             : "r"(addr));
            }
            #pragma unroll
            for (int i = 0; i < 4; i++)
                #pragma unroll
                for (int j = 0; j < 4; j++)
                    asm volatile(
                        "mma.sync.aligned.m16n8k16.row.col.f32.f16.f16.f32 "
                        "{%0,%1,%2,%3}, {%4,%5,%6,%7}, {%8,%9}, {%0,%1,%2,%3};\n"
                        : "+f"(acc[i][j][0]), "+f"(acc[i][j][1]),
                          "+f"(acc[i][j][2]), "+f"(acc[i][j][3])
                        : "r"(a[i][0]), "r"(a[i][1]), "r"(a[i][2]), "r"(a[i][3]),
                          "r"(bf[j][0]), "r"(bf[j][1]));
        }
        __syncthreads();
    }

    #pragma unroll
    for (int i = 0; i < 4; i++) {
        int row = by * HBM + wm + i * 16 + g;
        #pragma unroll
        for (int j = 0; j < 4; j++) {
            int col = bx * HBN + wn + j * 8 + 2 * tig;
            if (sizeof(CT) == 4) {
                *(float2*)((float*)C + (size_t)row * N + col) =
                    make_float2(acc[i][j][0], acc[i][j][1]);
                *(float2*)((float*)C + (size_t)(row + 8) * N + col) =
                    make_float2(acc[i][j][2], acc[i][j][3]);
            } else {
                *(__half2*)((__half*)C + (size_t)row * N + col) =
                    __floats2half2_rn(acc[i][j][0], acc[i][j][1]);
                *(__half2*)((__half*)C + (size_t)(row + 8) * N + col) =
                    __floats2half2_rn(acc[i][j][2], acc[i][j][3]);
            }
        }
    }
}

// ---------------------------------------------------------------------------
// FP16 tensor-core differential flash attention + per-head LayerNorm.
// 256 threads = 8 warps; q-tile 128; warp w owns rows [w*16, w*16+16).
// QK: K natural [kv][dh] = col-major B -> non-trans ldmatrix.
// PV: V natural [kv][dh] = row-major B -> trans ldmatrix.
// P fp16 in smem, ldmatrix as A. All pitches 72 halves (144B, %128=16).
// ---------------------------------------------------------------------------
#define QT 128
#define QLDH 72
#define PLDH 72
#define KLDH 72
#define VLDH 72
#define KH_STAGE (64*KLDH)       // 4608 halves
#define VH_STAGE (64*VLDH)
#define SQH_OFF  0
#define SK0H_OFF (2*QT*QLDH)                 // 18432
#define SK1H_OFF (SK0H_OFF + 2*KH_STAGE)     // 27648
#define SVH_OFF  (SK1H_OFF + 2*KH_STAGE)     // 36864
#define SPH_OFF  (SVH_OFF + 2*VH_STAGE)      // 46080
#define ATTN3_SMEM_HALVES (SPH_OFF + QT*PLDH)    // 55296
#define ATTN3_SMEM_BYTES (ATTN3_SMEM_HALVES*2)   // 110592

__global__ __launch_bounds__(256, 2) void attn_tc_kernel(
        const __half* __restrict__ q0b, const __half* __restrict__ q1b,
        const __half* __restrict__ k0b, const __half* __restrict__ k1b,
        const __half* __restrict__ vb,
        const float* __restrict__ ln_w, const float* __restrict__ ln_b,
        __half* __restrict__ attnh) {
    extern __shared__ __align__(16) char smraw[];
    __half* smh = (__half*)smraw;
    __half* sQ  = smh + SQH_OFF;
    __half* sK0 = smh + SK0H_OFF;
    __half* sK1 = smh + SK1H_OFF;
    __half* sV  = smh + SVH_OFF;
    __half* sP  = smh + SPH_OFF;

    int qt = gridDim.x - 1 - blockIdx.x;   // heavy tiles first
    int bh = blockIdx.y;
    int b = bh >> 4, h = bh & 15;

    int tid = threadIdx.x;
    int lane = tid & 31;
    int w = tid >> 5;
    int g = lane >> 2;
    int tig = lane & 3;

    const float scale = 0.125f;
    const float slope = exp2f(-0.5f * (float)(h + 1));
    const size_t base = (size_t)b * SEQ * DMODEL + (size_t)h * DHEAD;

    uint32_t s_q  = (uint32_t)__cvta_generic_to_shared(sQ);
    uint32_t s_k0 = (uint32_t)__cvta_generic_to_shared(sK0);
    uint32_t s_k1 = (uint32_t)__cvta_generic_to_shared(sK1);
    uint32_t s_v  = (uint32_t)__cvta_generic_to_shared(sV);
    uint32_t s_p  = (uint32_t)__cvta_generic_to_shared(sP);

    // --- load Q (both streams) via cp.async: 128 rows x 64 halves ---
    {
        int row = tid >> 1;             // 0..127
        int c0  = (tid & 1) * 32;       // halves
        size_t gofs = base + (size_t)(qt * QT + row) * DMODEL + c0;
        #pragma unroll
        for (int st = 0; st < 2; st++) {
            const __half* src = ((st == 0) ? q0b : q1b) + gofs;
            uint32_t dst = s_q + (uint32_t)(st * QT * QLDH + row * QLDH + c0) * 2u;
            #pragma unroll
            for (int c = 0; c < 32; c += 8)
                asm volatile("cp.async.cg.shared.global [%0], [%1], 16;\n"
                             :: "r"(dst + c * 2u), "l"(src + c));
        }
        asm volatile("cp.async.commit_group;\n");
    }

    float oacc[2][8][4];
    #pragma unroll
    for (int st = 0; st < 2; st++)
        #pragma unroll
        for (int j = 0; j < 8; j++)
            #pragma unroll
            for (int q = 0; q < 4; q++) oacc[st][j][q] = 0.f;
    float mrow[2][2], lrow[2][2];
    #pragma unroll
    for (int st = 0; st < 2; st++)
        #pragma unroll
        for (int hh = 0; hh < 2; hh++) { mrow[st][hh] = -INFINITY; lrow[st][hh] = 0.f; }

    // A-operand lane bases (bytes)
    uint32_t qa_lane = ((uint32_t)((w * 16 + (lane & 15)) * QLDH + (lane >> 4) * 8)) * 2u;
    uint32_t pa_lane = s_p + ((uint32_t)((w * 16 + (lane & 15)) * PLDH + (lane >> 4) * 8)) * 2u;
    // K B-operand (non-trans): n_off rows, k_off cols
    uint32_t kb_lane = ((uint32_t)(((lane & 7) + ((lane >> 4) & 1) * 8) * KLDH
                                   + ((lane >> 3) & 1) * 8)) * 2u;
    // V B-operand (trans): k rows, n cols
    uint32_t vb_lane = ((uint32_t)((lane & 15) * VLDH + (lane >> 4) * 8)) * 2u;

    const int qrow0 = qt * QT + w * 16;
    const int qq0 = qrow0 + g;

    // K/V prefetch coords: 64 rows, 64 halves each; 256 threads
    const int prow = tid >> 2;            // 0..63
    const int pc0  = (tid & 3) * 16;      // halves: 0,16,32,48

    auto prefetch = [&](int kt, int stage) {
        size_t gofs = base + (size_t)(kt * 64 + prow) * DMODEL + pc0;
        const __half* gk0 = k0b + gofs;
        const __half* gk1 = k1b + gofs;
        const __half* gv  = vb  + gofs;
        uint32_t dk0 = s_k0 + (uint32_t)(stage * KH_STAGE + prow * KLDH + pc0) * 2u;
        uint32_t dk1 = s_k1 + (uint32_t)(stage * KH_STAGE + prow * KLDH + pc0) * 2u;
        uint32_t dv  = s_v  + (uint32_t)(stage * VH_STAGE + prow * VLDH + pc0) * 2u;
        #pragma unroll
        for (int c = 0; c < 16; c += 8) {
            asm volatile("cp.async.cg.shared.global [%0], [%1], 16;\n"
                         :: "r"(dk0 + c * 2u), "l"(gk0 + c));
            asm volatile("cp.async.cg.shared.global [%0], [%1], 16;\n"
                         :: "r"(dk1 + c * 2u), "l"(gk1 + c));
            asm volatile("cp.async.cg.shared.global [%0], [%1], 16;\n"
                         :: "r"(dv + c * 2u), "l"(gv + c));
        }
        asm volatile("cp.async.commit_group;\n");
    };

    const int ktmax = 2 * qt + 1;

    prefetch(0, 0);

    for (int kt = 0; kt <= ktmax; kt++) {
        int stage = kt & 1;
        if (kt < ktmax) {
            prefetch(kt + 1, stage ^ 1);
            asm volatile("cp.async.wait_group 1;\n");
        } else {
            asm volatile("cp.async.wait_group 0;\n");
        }
        __syncthreads();

        const bool active = (kt * 64 <= qrow0 + 15);
        const bool diag   = (kt * 64 + 63 > qrow0);

        if (active) {
            uint32_t kbase0 = s_k0 + (uint32_t)(stage * KH_STAGE) * 2u + kb_lane;
            uint32_t kbase1 = s_k1 + (uint32_t)(stage * KH_STAGE) * 2u + kb_lane;
            uint32_t vbase  = s_v  + (uint32_t)(stage * VH_STAGE) * 2u + vb_lane;

            #pragma unroll
            for (int st = 0; st < 2; st++) {
                uint32_t kb = (st == 0) ? kbase0 : kbase1;

                // ---- QK: scores [16 q x 64 kv] per warp, 4 k16 x 8 j mmas ----
                float sc[8][4];
                #pragma unroll
                for (int j = 0; j < 8; j++)
                    #pragma unroll
                    for (int q = 0; q < 4; q++) sc[j][q] = 0.f;

                uint32_t qa_base = s_q + (uint32_t)(st * QT * QLDH) * 2u + qa_lane;
                #pragma unroll
                for (int k16 = 0; k16 < 4; k16++) {
                    uint32_t a0, a1, a2, a3;
                    asm volatile("ldmatrix.sync.aligned.m8n8.x4.shared.b16 {%0,%1,%2,%3}, [%4];\n"
                                 : "=r"(a0), "=r"(a1), "=r"(a2), "=r"(a3)
                                 : "r"(qa_base + (uint32_t)(k16 * 16) * 2u));
                    #pragma unroll
                    for (int jp = 0; jp < 4; jp++) {
                        uint32_t b0, b1, b2, b3;
                        uint32_t addr = kb + (uint32_t)(jp * 16 * KLDH + k16 * 16) * 2u;
                        asm volatile("ldmatrix.sync.aligned.m8n8.x4.shared.b16 {%0,%1,%2,%3}, [%4];\n"
                                     : "=r"(b0), "=r"(b1), "=r"(b2), "=r"(b3) : "r"(addr));
                        asm volatile(
                            "mma.sync.aligned.m16n8k16.row.col.f32.f16.f16.f32 "
                            "{%0,%1,%2,%3}, {%4,%5,%6,%7}, {%8,%9}, {%0,%1,%2,%3};\n"
                            : "+f"(sc[2*jp][0]), "+f"(sc[2*jp][1]),
                              "+f"(sc[2*jp][2]), "+f"(sc[2*jp][3])
                            : "r"(a0), "r"(a1), "r"(a2), "r"(a3), "r"(b0), "r"(b1));
                        asm volatile(
                            "mma.sync.aligned.m16n8k16.row.col.f32.f16.f16.f32 "
                            "{%0,%1,%2,%3}, {%4,%5,%6,%7}, {%8,%9}, {%0,%1,%2,%3};\n"
                            : "+f"(sc[2*jp+1][0]), "+f"(sc[2*jp+1][1]),
                              "+f"(sc[2*jp+1][2]), "+f"(sc[2*jp+1][3])
                            : "r"(a0), "r"(a1), "r"(a2), "r"(a3), "r"(b2), "r"(b3));
                    }
                }

                // ---- softmax (online), rows g and g+8 ----
                #pragma unroll
                for (int hh = 0; hh < 2; hh++) {
                    int qq = qq0 + hh * 8;
                    float mx = -INFINITY;
                    #pragma unroll
                    for (int j = 0; j < 8; j++) {
                        #pragma unroll
                        for (int e = 0; e < 2; e++) {
                            int kk = kt * 64 + j * 8 + 2 * tig + e;
                            float s = sc[j][hh * 2 + e] * scale - slope * (float)(qq - kk);
                            if (diag && kk > qq) s = -INFINITY;
                            sc[j][hh * 2 + e] = s;
                            mx = fmaxf(mx, s);
                        }
                    }
                    mx = fmaxf(mx, __shfl_xor_sync(0xffffffffu, mx, 1));
                    mx = fmaxf(mx, __shfl_xor_sync(0xffffffffu, mx, 2));
                    float mn = fmaxf(mrow[st][hh], mx);
                    float corr = __expf(mrow[st][hh] - mn);
                    mrow[st][hh] = mn;
                    float rs = 0.f;
                    #pragma unroll
                    for (int j = 0; j < 8; j++) {
                        #pragma unroll
                        for (int e = 0; e < 2; e++) {
                            float pv = __expf(sc[j][hh * 2 + e] - mn);
                            sc[j][hh * 2 + e] = pv;
                            rs += pv;
                        }
                    }
                    rs += __shfl_xor_sync(0xffffffffu, rs, 1);
                    rs += __shfl_xor_sync(0xffffffffu, rs, 2);
                    lrow[st][hh] = lrow[st][hh] * corr + rs;
                    #pragma unroll
                    for (int j = 0; j < 8; j++) {
                        oacc[st][j][hh * 2 + 0] *= corr;
                        oacc[st][j][hh * 2 + 1] *= corr;
                    }
                }

                // ---- write P (fp16) to own-warp rows of sP ----
                #pragma unroll
                for (int hh = 0; hh < 2; hh++) {
                    __half* pr = sP + (w * 16 + g + hh * 8) * PLDH;
                    #pragma unroll
                    for (int j = 0; j < 8; j++)
                        *(__half2*)(pr + j * 8 + 2 * tig) =
                            __floats2half2_rn(sc[j][hh * 2 + 0], sc[j][hh * 2 + 1]);
                }
                __syncwarp();

                // ---- PV: oacc += P @ V ; 4 k16, V via trans ldmatrix ----
                #pragma unroll
                for (int k16 = 0; k16 < 4; k16++) {
                    uint32_t a0, a1, a2, a3;
                    asm volatile("ldmatrix.sync.aligned.m8n8.x4.shared.b16 {%0,%1,%2,%3}, [%4];\n"
                                 : "=r"(a0), "=r"(a1), "=r"(a2), "=r"(a3)
                                 : "r"(pa_lane + (uint32_t)(k16 * 16) * 2u));
                    #pragma unroll
                    for (int jp = 0; jp < 4; jp++) {
                        uint32_t b0, b1, b2, b3;
                        uint32_t addr = vbase + (uint32_t)(k16 * 16 * VLDH + jp * 16) * 2u;
                        asm volatile("ldmatrix.sync.aligned.m8n8.x4.trans.shared.b16 {%0,%1,%2,%3}, [%4];\n"
                                     : "=r"(b0), "=r"(b1), "=r"(b2), "=r"(b3) : "r"(addr));
                        asm volatile(
                            "mma.sync.aligned.m16n8k16.row.col.f32.f16.f16.f32 "
                            "{%0,%1,%2,%3}, {%4,%5,%6,%7}, {%8,%9}, {%0,%1,%2,%3};\n"
                            : "+f"(oacc[st][2*jp][0]), "+f"(oacc[st][2*jp][1]),
                              "+f"(oacc[st][2*jp][2]), "+f"(oacc[st][2*jp][3])
                            : "r"(a0), "r"(a1), "r"(a2), "r"(a3), "r"(b0), "r"(b1));
                        asm volatile(
                            "mma.sync.aligned.m16n8k16.row.col.f32.f16.f16.f32 "
                            "{%0,%1,%2,%3}, {%4,%5,%6,%7}, {%8,%9}, {%0,%1,%2,%3};\n"
                            : "+f"(oacc[st][2*jp+1][0]), "+f"(oacc[st][2*jp+1][1]),
                              "+f"(oacc[st][2*jp+1][2]), "+f"(oacc[st][2*jp+1][3])
                            : "r"(a0), "r"(a1), "r"(a2), "r"(a3), "r"(b2), "r"(b3));
                    }
                }
                __syncwarp();
            }
        }
        __syncthreads();
    }

    // --- epilogue: combine streams, per-head LayerNorm over DH, store fp16 ---
    float lam = g_lambda;
    #pragma unroll
    for (int hh = 0; hh < 2; hh++) {
        float inv0 = 1.0f / lrow[0][hh];
        float inv1 = 1.0f / lrow[1][hh];
        float o[8][2];
        float s_ = 0.f;
        #pragma unroll
        for (int j = 0; j < 8; j++) {
            #pragma unroll
            for (int e = 0; e < 2; e++) {
                float val = oacc[0][j][hh * 2 + e] * inv0
                          - lam * (oacc[1][j][hh * 2 + e] * inv1);
                o[j][e] = val;
                s_ += val;
            }
        }
        s_ += __shfl_xor_sync(0xffffffffu, s_, 1);
        s_ += __shfl_xor_sync(0xffffffffu, s_, 2);
        float mu = s_ * (1.0f / 64.0f);
        float vs = 0.f;
        #pragma unroll
        for (int j = 0; j < 8; j++) {
            #pragma unroll
            for (int e = 0; e < 2; e++) { float d = o[j][e] - mu; vs += d * d; }
        }
        vs += __shfl_xor_sync(0xffffffffu, vs, 1);
        vs += __shfl_xor_sync(0xffffffffu, vs, 2);
        float r = rsqrtf(vs * (1.0f / 64.0f) + LN_EPS);

        size_t row = (size_t)b * SEQ + (size_t)(qrow0 + g + hh * 8);
        #pragma unroll
        for (int j = 0; j < 8; j++) {
            int col = h * DHEAD + j * 8 + 2 * tig;
            float wv0 = ln_w[h * DHEAD + j * 8 + 2 * tig];
            float wv1 = ln_w[h * DHEAD + j * 8 + 2 * tig + 1];
            float bv0 = ln_b[h * DHEAD + j * 8 + 2 * tig];
            float bv1 = ln_b[h * DHEAD + j * 8 + 2 * tig + 1];
            *(__half2*)(attnh + row * DMODEL + col) =
                __floats2half2_rn((o[j][0] - mu) * r * wv0 + bv0,
                                  (o[j][1] - mu) * r * wv1 + bv1);
        }
    }
}

// ---------------------------------------------------------------------------
// Launch
// ---------------------------------------------------------------------------
extern "C" void kernel_launch(void* const* d_in, const int* in_sizes, int n_in,
                              void* d_out, int out_size) {
    const float* inp = (const float*)d_in[0];
    const float* wq0 = (const float*)d_in[1];
    const float* wq1 = (const float*)d_in[2];
    const float* wk0 = (const float*)d_in[3];
    const float* wk1 = (const float*)d_in[4];
    const float* wv  = (const float*)d_in[5];
    const float* wo  = (const float*)d_in[6];
    const float* l0  = (const float*)d_in[7];
    const float* l1  = (const float*)d_in[8];
    const float* l2  = (const float*)d_in[9];
    const float* l3  = (const float*)d_in[10];
    const float* lnw = (const float*)d_in[11];
    const float* lnb = (const float*)d_in[12];
    float* out = (float*)d_out;

    __half *q0, *q1, *k0, *k1, *v;
    __half *xh, *attnh, *w0h, *w1h, *w2h, *w3h, *w4h, *woh;
    cudaGetSymbolAddress((void**)&q0, g_q0);
    cudaGetSymbolAddress((void**)&q1, g_q1);
    cudaGetSymbolAddress((void**)&k0, g_k0);
    cudaGetSymbolAddress((void**)&k1, g_k1);
    cudaGetSymbolAddress((void**)&v,  g_v);
    cudaGetSymbolAddress((void**)&xh, g_xh);
    cudaGetSymbolAddress((void**)&attnh, g_attnh);
    cudaGetSymbolAddress((void**)&w0h, g_w0h);
    cudaGetSymbolAddress((void**)&w1h, g_w1h);
    cudaGetSymbolAddress((void**)&w2h, g_w2h);
    cudaGetSymbolAddress((void**)&w3h, g_w3h);
    cudaGetSymbolAddress((void**)&w4h, g_w4h);
    cudaGetSymbolAddress((void**)&woh, g_woh);

    cudaFuncSetAttribute(gemm_f16<float>, cudaFuncAttributeMaxDynamicSharedMemorySize,
                         HGEMM_SMEM_BYTES);
    cudaFuncSetAttribute(gemm_f16<__half>, cudaFuncAttributeMaxDynamicSharedMemorySize,
                         HGEMM_SMEM_BYTES);
    cudaFuncSetAttribute(attn_tc_kernel, cudaFuncAttributeMaxDynamicSharedMemorySize,
                         ATTN3_SMEM_BYTES);

    lambda_kernel<<<1, 32>>>(l0, l1, l2, l3);

    const int NX = MTOT * DMODEL;
    const int NW = DMODEL * DMODEL;
    f2h_kernel<<<NX / 1024, 256>>>(inp, xh, NX);
    f2h_kernel<<<NW / 1024, 256>>>(wq0, w0h, NW);
    f2h_kernel<<<NW / 1024, 256>>>(wq1, w1h, NW);
    f2h_kernel<<<NW / 1024, 256>>>(wk0, w2h, NW);
    f2h_kernel<<<NW / 1024, 256>>>(wk1, w3h, NW);
    f2h_kernel<<<NW / 1024, 256>>>(wv,  w4h, NW);
    f2h_kernel<<<NW / 1024, 256>>>(wo,  woh, NW);

    dim3 ggrid(DMODEL / 128, MTOT / 128);   // (8, 32)
    gemm_f16<__half><<<ggrid, 256, HGEMM_SMEM_BYTES>>>(xh, w0h, q0, MTOT, DMODEL, DMODEL);
    gemm_f16<__half><<<ggrid, 256, HGEMM_SMEM_BYTES>>>(xh, w1h, q1, MTOT, DMODEL, DMODEL);
    gemm_f16<__half><<<ggrid, 256, HGEMM_SMEM_BYTES>>>(xh, w2h, k0, MTOT, DMODEL, DMODEL);
    gemm_f16<__half><<<ggrid, 256, HGEMM_SMEM_BYTES>>>(xh, w3h, k1, MTOT, DMODEL, DMODEL);
    gemm_f16<__half><<<ggrid, 256, HGEMM_SMEM_BYTES>>>(xh, w4h, v,  MTOT, DMODEL, DMODEL);

    attn_tc_kernel<<<dim3(SEQ / QT, BATCH * NHEAD), 256, ATTN3_SMEM_BYTES>>>(
        q0, q1, k0, k1, v, lnw, lnb, attnh);

    gemm_f16<float><<<ggrid, 256, HGEMM_SMEM_BYTES>>>(attnh, woh, out, MTOT, DMODEL, DMODEL);
}

// round 11
// speedup vs baseline: 2.4439x; 1.0680x over previous
#include <cuda_runtime.h>
#include <cuda_fp16.h>
#include <math.h>
#include <stdint.h>

// Problem constants
#define BATCH 2
#define SEQ   2048
#define DMODEL 1024
#define NHEAD 16
#define DHEAD 64
#define MTOT  (BATCH*SEQ)      // 4096
#define NQKV  (5*DMODEL)       // 5120 (q0,q1,k0,k1,v concatenated)
#define LAMBDA_INIT 0.8f
#define LN_EPS 1e-5f
#define LOG2E 1.44269504088896340736f

// ---------------------------------------------------------------------------
// Scratch
// ---------------------------------------------------------------------------
__device__ __half g_qkvh[MTOT*NQKV];        // merged projection output
__device__ __half g_xh[MTOT*DMODEL];
__device__ __half g_attnh[MTOT*DMODEL];
__device__ __half g_wcat[DMODEL*NQKV];      // concatenated weights
__device__ __half g_woh[DMODEL*DMODEL];
__device__ float g_lambda;

// ---------------------------------------------------------------------------
// fp32 -> fp16 conversion (n % 4 == 0)
// ---------------------------------------------------------------------------
__global__ void f2h_kernel(const float* __restrict__ in, __half* __restrict__ out, int n) {
    int i = (blockIdx.x * blockDim.x + threadIdx.x) * 4;
    if (i < n) {
        float4 v = *(const float4*)(in + i);
        *(__half2*)(out + i)     = __floats2half2_rn(v.x, v.y);
        *(__half2*)(out + i + 2) = __floats2half2_rn(v.z, v.w);
    }
}

// Pack one [DMODEL, DMODEL] fp32 weight into fp16 at column block col0 of
// a [DMODEL, NQKV] row-major matrix.
__global__ void packw_kernel(const float* __restrict__ in, __half* __restrict__ out,
                             int col0) {
    int i = (blockIdx.x * blockDim.x + threadIdx.x) * 4;
    int k = i >> 10;
    int n = i & 1023;
    float4 v = *(const float4*)(in + i);
    __half* dst = out + (size_t)k * NQKV + col0 + n;
    *(__half2*)(dst)     = __floats2half2_rn(v.x, v.y);
    *(__half2*)(dst + 2) = __floats2half2_rn(v.z, v.w);
}

// ---------------------------------------------------------------------------
// Lambda scalar
// ---------------------------------------------------------------------------
__global__ void lambda_kernel(const float* __restrict__ l0, const float* __restrict__ l1,
                              const float* __restrict__ l2, const float* __restrict__ l3) {
    int t = threadIdx.x;
    float a = l0[t]*l1[t] + l0[t+32]*l1[t+32];
    float b = l2[t]*l3[t] + l2[t+32]*l3[t+32];
    #pragma unroll
    for (int o = 16; o >= 1; o >>= 1) {
        a += __shfl_xor_sync(0xffffffffu, a, o);
        b += __shfl_xor_sync(0xffffffffu, b, o);
    }
    if (t == 0) g_lambda = (-expf(a) + LAMBDA_INIT) + (-expf(b) + LAMBDA_INIT);
}

__device__ __forceinline__ float ex2f(float x) {
    float r;
    asm("ex2.approx.f32 %0, %1;" : "=f"(r) : "f"(x));
    return r;
}

// ---------------------------------------------------------------------------
// FP16 tensor-core GEMM: C[M,N] = A[M,K](f16) @ B[K,N](f16), fp32 accum.
// ---------------------------------------------------------------------------
#define HBM 128
#define HBN 128
#define HBK 64
#define A_LDH 72
#define B_LDH 136
#define HAS_STAGE (HBM*A_LDH)
#define HBS_STAGE (HBK*B_LDH)
#define HGEMM_SMEM_BYTES ((2*(HAS_STAGE+HBS_STAGE))*2)

template <typename CT>
__global__ __launch_bounds__(256, 2) void gemm_f16(const __half* __restrict__ A,
                                                   const __half* __restrict__ B,
                                                   CT* __restrict__ C,
                                                   int M, int N, int K) {
    extern __shared__ __align__(16) char smraw[];
    __half* As = (__half*)smraw;
    __half* Bs = As + 2 * HAS_STAGE;

    int tid  = threadIdx.x;
    int lane = tid & 31;
    int warp = tid >> 5;
    int g    = lane >> 2;
    int tig  = lane & 3;
    int wm   = (warp >> 2) * 64;
    int wn   = (warp & 3) * 32;

    int bx = blockIdx.x, by = blockIdx.y;

    const __half* Ag = A + (size_t)(by * HBM) * K;
    const __half* Bg = B + bx * HBN;

    uint32_t s_as = (uint32_t)__cvta_generic_to_shared(As);
    uint32_t s_bs = (uint32_t)__cvta_generic_to_shared(Bs);

    float acc[4][4][4];
    #pragma unroll
    for (int i = 0; i < 4; i++)
        #pragma unroll
        for (int j = 0; j < 4; j++)
            #pragma unroll
            for (int q = 0; q < 4; q++) acc[i][j][q] = 0.f;

    uint32_t a_lane = ((uint32_t)((wm + (lane & 15)) * A_LDH + (lane >> 4) * 8)) * 2u;
    uint32_t b_lane = ((uint32_t)((lane & 15) * B_LDH + wn + (lane >> 4) * 8)) * 2u;

    const int NT = K / HBK;

    auto prefetch = [&](int kt, int stage) {
        uint32_t ad = s_as + (uint32_t)(stage * HAS_STAGE) * 2u;
        uint32_t bd = s_bs + (uint32_t)(stage * HBS_STAGE) * 2u;
        const __half* agk = Ag + kt * HBK;
        const __half* bgk = Bg + (size_t)(kt * HBK) * N;
        #pragma unroll
        for (int r = 0; r < 4; r++) {
            int c = tid + r * 256;
            int arow = c >> 3, acol = (c & 7) * 8;
            asm volatile("cp.async.cg.shared.global [%0], [%1], 16;\n"
                         :: "r"(ad + (uint32_t)(arow * A_LDH + acol) * 2u),
                            "l"(agk + (size_t)arow * K + acol));
            int brow = c >> 4, bcol = (c & 15) * 8;
            asm volatile("cp.async.cg.shared.global [%0], [%1], 16;\n"
                         :: "r"(bd + (uint32_t)(brow * B_LDH + bcol) * 2u),
                            "l"(bgk + (size_t)brow * N + bcol));
        }
        asm volatile("cp.async.commit_group;\n");
    };

    prefetch(0, 0);

    for (int kt = 0; kt < NT; kt++) {
        int stage = kt & 1;
        if (kt + 1 < NT) {
            prefetch(kt + 1, stage ^ 1);
            asm volatile("cp.async.wait_group 1;\n");
        } else {
            asm volatile("cp.async.wait_group 0;\n");
        }
        __syncthreads();

        uint32_t a_base = s_as + (uint32_t)(stage * HAS_STAGE) * 2u + a_lane;
        uint32_t b_base = s_bs + (uint32_t)(stage * HBS_STAGE) * 2u + b_lane;

        #pragma unroll
        for (int k16 = 0; k16 < HBK / 16; k16++) {
            uint32_t a[4][4];
            #pragma unroll
            for (int i = 0; i < 4; i++) {
                uint32_t addr = a_base + (uint32_t)(i * 16 * A_LDH + k16 * 16) * 2u;
                asm volatile("ldmatrix.sync.aligned.m8n8.x4.shared.b16 {%0,%1,%2,%3}, [%4];\n"
                             : "=r"(a[i][0]), "=r"(a[i][1]), "=r"(a[i][2]), "=r"(a[i][3])
                             : "r"(addr));
            }
            uint32_t bf[4][2];
            #pragma unroll
            for (int jp = 0; jp < 2; jp++) {
                uint32_t addr = b_base + (uint32_t)(k16 * 16 * B_LDH + jp * 16) * 2u;
                asm volatile("ldmatrix.sync.aligned.m8n8.x4.trans.shared.b16 {%0,%1,%2,%3}, [%4];\n"
                             : "=r"(bf[2*jp][0]), "=r"(bf[2*jp][1]),
                               "=r"(bf[2*jp+1][0]), "=r"(bf[2*jp+1][1])
                             : "r"(addr));
            }
            #pragma unroll
            for (int i = 0; i < 4; i++)
                #pragma unroll
                for (int j = 0; j < 4; j++)
                    asm volatile(
                        "mma.sync.aligned.m16n8k16.row.col.f32.f16.f16.f32 "
                        "{%0,%1,%2,%3}, {%4,%5,%6,%7}, {%8,%9}, {%0,%1,%2,%3};\n"
                        : "+f"(acc[i][j][0]), "+f"(acc[i][j][1]),
                          "+f"(acc[i][j][2]), "+f"(acc[i][j][3])
                        : "r"(a[i][0]), "r"(a[i][1]), "r"(a[i][2]), "r"(a[i][3]),
                          "r"(bf[j][0]), "r"(bf[j][1]));
        }
        __syncthreads();
    }

    #pragma unroll
    for (int i = 0; i < 4; i++) {
        int row = by * HBM + wm + i * 16 + g;
        #pragma unroll
        for (int j = 0; j < 4; j++) {
            int col = bx * HBN + wn + j * 8 + 2 * tig;
            if (sizeof(CT) == 4) {
                *(float2*)((float*)C + (size_t)row * N + col) =
                    make_float2(acc[i][j][0], acc[i][j][1]);
                *(float2*)((float*)C + (size_t)(row + 8) * N + col) =
                    make_float2(acc[i][j][2], acc[i][j][3]);
            } else {
                *(__half2*)((__half*)C + (size_t)row * N + col) =
                    __floats2half2_rn(acc[i][j][0], acc[i][j][1]);
                *(__half2*)((__half*)C + (size_t)(row + 8) * N + col) =
                    __floats2half2_rn(acc[i][j][2], acc[i][j][3]);
            }
        }
    }
}

// ---------------------------------------------------------------------------
// FP16 tensor-core differential flash attention + per-head LayerNorm.
// Reads q0/q1/k0/k1/v as column blocks of the merged [MTOT, NQKV] buffer.
// Softmax in log2 domain: scores pre-scaled by log2(e), bare ex2.approx.
// ---------------------------------------------------------------------------
#define QT 128
#define QLDH 72
#define PLDH 72
#define KLDH 72
#define VLDH 72
#define KH_STAGE (64*KLDH)
#define VH_STAGE (64*VLDH)
#define SQH_OFF  0
#define SK0H_OFF (2*QT*QLDH)
#define SK1H_OFF (SK0H_OFF + 2*KH_STAGE)
#define SVH_OFF  (SK1H_OFF + 2*KH_STAGE)
#define SPH_OFF  (SVH_OFF + 2*VH_STAGE)
#define ATTN3_SMEM_HALVES (SPH_OFF + QT*PLDH)
#define ATTN3_SMEM_BYTES (ATTN3_SMEM_HALVES*2)   // 110592

__global__ __launch_bounds__(256, 2) void attn_tc_kernel(
        const __half* __restrict__ qkv,
        const float* __restrict__ ln_w, const float* __restrict__ ln_b,
        __half* __restrict__ attnh) {
    extern __shared__ __align__(16) char smraw[];
    __half* smh = (__half*)smraw;
    __half* sQ  = smh + SQH_OFF;
    __half* sK0 = smh + SK0H_OFF;
    __half* sK1 = smh + SK1H_OFF;
    __half* sV  = smh + SVH_OFF;
    __half* sP  = smh + SPH_OFF;

    int qt = gridDim.x - 1 - blockIdx.x;   // heavy tiles first
    int bh = blockIdx.y;
    int b = bh >> 4, h = bh & 15;

    int tid = threadIdx.x;
    int lane = tid & 31;
    int w = tid >> 5;
    int g = lane >> 2;
    int tig = lane & 3;

    const float scale2 = 0.125f * LOG2E;                       // log2-domain
    const float slope2 = exp2f(-0.5f * (float)(h + 1)) * LOG2E;
    const size_t basec = (size_t)b * SEQ * NQKV + (size_t)h * DHEAD;

    uint32_t s_q  = (uint32_t)__cvta_generic_to_shared(sQ);
    uint32_t s_k0 = (uint32_t)__cvta_generic_to_shared(sK0);
    uint32_t s_k1 = (uint32_t)__cvta_generic_to_shared(sK1);
    uint32_t s_v  = (uint32_t)__cvta_generic_to_shared(sV);
    uint32_t s_p  = (uint32_t)__cvta_generic_to_shared(sP);

    // --- load Q (both streams) via cp.async: 128 rows x 64 halves ---
    {
        int row = tid >> 1;
        int c0  = (tid & 1) * 32;
        size_t gofs = basec + (size_t)(qt * QT + row) * NQKV + c0;
        #pragma unroll
        for (int st = 0; st < 2; st++) {
            const __half* src = qkv + gofs + st * DMODEL;
            uint32_t dst = s_q + (uint32_t)(st * QT * QLDH + row * QLDH + c0) * 2u;
            #pragma unroll
            for (int c = 0; c < 32; c += 8)
                asm volatile("cp.async.cg.shared.global [%0], [%1], 16;\n"
                             :: "r"(dst + c * 2u), "l"(src + c));
        }
        asm volatile("cp.async.commit_group;\n");
    }

    float oacc[2][8][4];
    #pragma unroll
    for (int st = 0; st < 2; st++)
        #pragma unroll
        for (int j = 0; j < 8; j++)
            #pragma unroll
            for (int q = 0; q < 4; q++) oacc[st][j][q] = 0.f;
    float mrow[2][2], lrow[2][2];
    #pragma unroll
    for (int st = 0; st < 2; st++)
        #pragma unroll
        for (int hh = 0; hh < 2; hh++) { mrow[st][hh] = -INFINITY; lrow[st][hh] = 0.f; }

    uint32_t qa_lane = ((uint32_t)((w * 16 + (lane & 15)) * QLDH + (lane >> 4) * 8)) * 2u;
    uint32_t pa_lane = s_p + ((uint32_t)((w * 16 + (lane & 15)) * PLDH + (lane >> 4) * 8)) * 2u;
    uint32_t kb_lane = ((uint32_t)(((lane & 7) + ((lane >> 4) & 1) * 8) * KLDH
                                   + ((lane >> 3) & 1) * 8)) * 2u;
    uint32_t vb_lane = ((uint32_t)((lane & 15) * VLDH + (lane >> 4) * 8)) * 2u;

    const int qrow0 = qt * QT + w * 16;
    const int qq0 = qrow0 + g;

    const int prow = tid >> 2;
    const int pc0  = (tid & 3) * 16;

    auto prefetch = [&](int kt, int stage) {
        size_t gofs = basec + (size_t)(kt * 64 + prow) * NQKV + pc0;
        const __half* gk0 = qkv + gofs + 2 * DMODEL;
        const __half* gk1 = qkv + gofs + 3 * DMODEL;
        const __half* gv  = qkv + gofs + 4 * DMODEL;
        uint32_t dk0 = s_k0 + (uint32_t)(stage * KH_STAGE + prow * KLDH + pc0) * 2u;
        uint32_t dk1 = s_k1 + (uint32_t)(stage * KH_STAGE + prow * KLDH + pc0) * 2u;
        uint32_t dv  = s_v  + (uint32_t)(stage * VH_STAGE + prow * VLDH + pc0) * 2u;
        #pragma unroll
        for (int c = 0; c < 16; c += 8) {
            asm volatile("cp.async.cg.shared.global [%0], [%1], 16;\n"
                         :: "r"(dk0 + c * 2u), "l"(gk0 + c));
            asm volatile("cp.async.cg.shared.global [%0], [%1], 16;\n"
                         :: "r"(dk1 + c * 2u), "l"(gk1 + c));
            asm volatile("cp.async.cg.shared.global [%0], [%1], 16;\n"
                         :: "r"(dv + c * 2u), "l"(gv + c));
        }
        asm volatile("cp.async.commit_group;\n");
    };

    const int ktmax = 2 * qt + 1;

    prefetch(0, 0);

    for (int kt = 0; kt <= ktmax; kt++) {
        int stage = kt & 1;
        if (kt < ktmax) {
            prefetch(kt + 1, stage ^ 1);
            asm volatile("cp.async.wait_group 1;\n");
        } else {
            asm volatile("cp.async.wait_group 0;\n");
        }
        __syncthreads();

        const bool active = (kt * 64 <= qrow0 + 15);
        const bool diag   = (kt * 64 + 63 > qrow0);

        if (active) {
            uint32_t kbase0 = s_k0 + (uint32_t)(stage * KH_STAGE) * 2u + kb_lane;
            uint32_t kbase1 = s_k1 + (uint32_t)(stage * KH_STAGE) * 2u + kb_lane;
            uint32_t vbase  = s_v  + (uint32_t)(stage * VH_STAGE) * 2u + vb_lane;

            #pragma unroll
            for (int st = 0; st < 2; st++) {
                uint32_t kb = (st == 0) ? kbase0 : kbase1;

                float sc[8][4];
                #pragma unroll
                for (int j = 0; j < 8; j++)
                    #pragma unroll
                    for (int q = 0; q < 4; q++) sc[j][q] = 0.f;

                uint32_t qa_base = s_q + (uint32_t)(st * QT * QLDH) * 2u + qa_lane;
                #pragma unroll
                for (int k16 = 0; k16 < 4; k16++) {
                    uint32_t a0, a1, a2, a3;
                    asm volatile("ldmatrix.sync.aligned.m8n8.x4.shared.b16 {%0,%1,%2,%3}, [%4];\n"
                                 : "=r"(a0), "=r"(a1), "=r"(a2), "=r"(a3)
                                 : "r"(qa_base + (uint32_t)(k16 * 16) * 2u));
                    #pragma unroll
                    for (int jp = 0; jp < 4; jp++) {
                        uint32_t b0, b1, b2, b3;
                        uint32_t addr = kb + (uint32_t)(jp * 16 * KLDH + k16 * 16) * 2u;
                        asm volatile("ldmatrix.sync.aligned.m8n8.x4.shared.b16 {%0,%1,%2,%3}, [%4];\n"
                                     : "=r"(b0), "=r"(b1), "=r"(b2), "=r"(b3) : "r"(addr));
                        asm volatile(
                            "mma.sync.aligned.m16n8k16.row.col.f32.f16.f16.f32 "
                            "{%0,%1,%2,%3}, {%4,%5,%6,%7}, {%8,%9}, {%0,%1,%2,%3};\n"
                            : "+f"(sc[2*jp][0]), "+f"(sc[2*jp][1]),
                              "+f"(sc[2*jp][2]), "+f"(sc[2*jp][3])
                            : "r"(a0), "r"(a1), "r"(a2), "r"(a3), "r"(b0), "r"(b1));
                        asm volatile(
                            "mma.sync.aligned.m16n8k16.row.col.f32.f16.f16.f32 "
                            "{%0,%1,%2,%3}, {%4,%5,%6,%7}, {%8,%9}, {%0,%1,%2,%3};\n"
                            : "+f"(sc[2*jp+1][0]), "+f"(sc[2*jp+1][1]),
                              "+f"(sc[2*jp+1][2]), "+f"(sc[2*jp+1][3])
                            : "r"(a0), "r"(a1), "r"(a2), "r"(a3), "r"(b2), "r"(b3));
                    }
                }

                // ---- softmax (online, log2 domain), rows g and g+8 ----
                #pragma unroll
                for (int hh = 0; hh < 2; hh++) {
                    int qq = qq0 + hh * 8;
                    float mx = -INFINITY;
                    #pragma unroll
                    for (int j = 0; j < 8; j++) {
                        #pragma unroll
                        for (int e = 0; e < 2; e++) {
                            int kk = kt * 64 + j * 8 + 2 * tig + e;
                            float s = sc[j][hh * 2 + e] * scale2 - slope2 * (float)(qq - kk);
                            if (diag && kk > qq) s = -INFINITY;
                            sc[j][hh * 2 + e] = s;
                            mx = fmaxf(mx, s);
                        }
                    }
                    mx = fmaxf(mx, __shfl_xor_sync(0xffffffffu, mx, 1));
                    mx = fmaxf(mx, __shfl_xor_sync(0xffffffffu, mx, 2));
                    float mn = fmaxf(mrow[st][hh], mx);
                    float corr = ex2f(mrow[st][hh] - mn);
                    mrow[st][hh] = mn;
                    float rs = 0.f;
                    #pragma unroll
                    for (int j = 0; j < 8; j++) {
                        #pragma unroll
                        for (int e = 0; e < 2; e++) {
                            float pv = ex2f(sc[j][hh * 2 + e] - mn);
                            sc[j][hh * 2 + e] = pv;
                            rs += pv;
                        }
                    }
                    rs += __shfl_xor_sync(0xffffffffu, rs, 1);
                    rs += __shfl_xor_sync(0xffffffffu, rs, 2);
                    lrow[st][hh] = lrow[st][hh] * corr + rs;
                    #pragma unroll
                    for (int j = 0; j < 8; j++) {
                        oacc[st][j][hh * 2 + 0] *= corr;
                        oacc[st][j][hh * 2 + 1] *= corr;
                    }
                }

                // ---- write P (fp16) to own-warp rows of sP ----
                #pragma unroll
                for (int hh = 0; hh < 2; hh++) {
                    __half* pr = sP + (w * 16 + g + hh * 8) * PLDH;
                    #pragma unroll
                    for (int j = 0; j < 8; j++)
                        *(__half2*)(pr + j * 8 + 2 * tig) =
                            __floats2half2_rn(sc[j][hh * 2 + 0], sc[j][hh * 2 + 1]);
                }
                __syncwarp();

                // ---- PV: oacc += P @ V ----
                #pragma unroll
                for (int k16 = 0; k16 < 4; k16++) {
                    uint32_t a0, a1, a2, a3;
                    asm volatile("ldmatrix.sync.aligned.m8n8.x4.shared.b16 {%0,%1,%2,%3}, [%4];\n"
                                 : "=r"(a0), "=r"(a1), "=r"(a2), "=r"(a3)
                                 : "r"(pa_lane + (uint32_t)(k16 * 16) * 2u));
                    #pragma unroll
                    for (int jp = 0; jp < 4; jp++) {
                        uint32_t b0, b1, b2, b3;
                        uint32_t addr = vbase + (uint32_t)(k16 * 16 * VLDH + jp * 16) * 2u;
                        asm volatile("ldmatrix.sync.aligned.m8n8.x4.trans.shared.b16 {%0,%1,%2,%3}, [%4];\n"
                                     : "=r"(b0), "=r"(b1), "=r"(b2), "=r"(b3) : "r"(addr));
                        asm volatile(
                            "mma.sync.aligned.m16n8k16.row.col.f32.f16.f16.f32 "
                            "{%0,%1,%2,%3}, {%4,%5,%6,%7}, {%8,%9}, {%0,%1,%2,%3};\n"
                            : "+f"(oacc[st][2*jp][0]), "+f"(oacc[st][2*jp][1]),
                              "+f"(oacc[st][2*jp][2]), "+f"(oacc[st][2*jp][3])
                            : "r"(a0), "r"(a1), "r"(a2), "r"(a3), "r"(b0), "r"(b1));
                        asm volatile(
                            "mma.sync.aligned.m16n8k16.row.col.f32.f16.f16.f32 "
                            "{%0,%1,%2,%3}, {%4,%5,%6,%7}, {%8,%9}, {%0,%1,%2,%3};\n"
                            : "+f"(oacc[st][2*jp+1][0]), "+f"(oacc[st][2*jp+1][1]),
                              "+f"(oacc[st][2*jp+1][2]), "+f"(oacc[st][2*jp+1][3])
                            : "r"(a0), "r"(a1), "r"(a2), "r"(a3), "r"(b2), "r"(b3));
                    }
                }
                __syncwarp();
            }
        }
        __syncthreads();
    }

    // --- epilogue: combine streams, per-head LayerNorm over DH, store fp16 ---
    float lam = g_lambda;
    #pragma unroll
    for (int hh = 0; hh < 2; hh++) {
        float inv0 = 1.0f / lrow[0][hh];
        float inv1 = 1.0f / lrow[1][hh];
        float o[8][2];
        float s_ = 0.f;
        #pragma unroll
        for (int j = 0; j < 8; j++) {
            #pragma unroll
            for (int e = 0; e < 2; e++) {
                float val = oacc[0][j][hh * 2 + e] * inv0
                          - lam * (oacc[1][j][hh * 2 + e] * inv1);
                o[j][e] = val;
                s_ += val;
            }
        }
        s_ += __shfl_xor_sync(0xffffffffu, s_, 1);
        s_ += __shfl_xor_sync(0xffffffffu, s_, 2);
        float mu = s_ * (1.0f / 64.0f);
        float vs = 0.f;
        #pragma unroll
        for (int j = 0; j < 8; j++) {
            #pragma unroll
            for (int e = 0; e < 2; e++) { float d = o[j][e] - mu; vs += d * d; }
        }
        vs += __shfl_xor_sync(0xffffffffu, vs, 1);
        vs += __shfl_xor_sync(0xffffffffu, vs, 2);
        float r = rsqrtf(vs * (1.0f / 64.0f) + LN_EPS);

        size_t row = (size_t)b * SEQ + (size_t)(qrow0 + g + hh * 8);
        #pragma unroll
        for (int j = 0; j < 8; j++) {
            int col = h * DHEAD + j * 8 + 2 * tig;
            float wv0 = ln_w[h * DHEAD + j * 8 + 2 * tig];
            float wv1 = ln_w[h * DHEAD + j * 8 + 2 * tig + 1];
            float bv0 = ln_b[h * DHEAD + j * 8 + 2 * tig];
            float bv1 = ln_b[h * DHEAD + j * 8 + 2 * tig + 1];
            *(__half2*)(attnh + row * DMODEL + col) =
                __floats2half2_rn((o[j][0] - mu) * r * wv0 + bv0,
                                  (o[j][1] - mu) * r * wv1 + bv1);
        }
    }
}

// ---------------------------------------------------------------------------
// Launch
// ---------------------------------------------------------------------------
extern "C" void kernel_launch(void* const* d_in, const int* in_sizes, int n_in,
                              void* d_out, int out_size) {
    const float* inp = (const float*)d_in[0];
    const float* wq0 = (const float*)d_in[1];
    const float* wq1 = (const float*)d_in[2];
    const float* wk0 = (const float*)d_in[3];
    const float* wk1 = (const float*)d_in[4];
    const float* wv  = (const float*)d_in[5];
    const float* wo  = (const float*)d_in[6];
    const float* l0  = (const float*)d_in[7];
    const float* l1  = (const float*)d_in[8];
    const float* l2  = (const float*)d_in[9];
    const float* l3  = (const float*)d_in[10];
    const float* lnw = (const float*)d_in[11];
    const float* lnb = (const float*)d_in[12];
    float* out = (float*)d_out;

    __half *qkvh, *xh, *attnh, *wcat, *woh;
    cudaGetSymbolAddress((void**)&qkvh, g_qkvh);
    cudaGetSymbolAddress((void**)&xh, g_xh);
    cudaGetSymbolAddress((void**)&attnh, g_attnh);
    cudaGetSymbolAddress((void**)&wcat, g_wcat);
    cudaGetSymbolAddress((void**)&woh, g_woh);

    cudaFuncSetAttribute(gemm_f16<float>, cudaFuncAttributeMaxDynamicSharedMemorySize,
                         HGEMM_SMEM_BYTES);
    cudaFuncSetAttribute(gemm_f16<__half>, cudaFuncAttributeMaxDynamicSharedMemorySize,
                         HGEMM_SMEM_BYTES);
    cudaFuncSetAttribute(attn_tc_kernel, cudaFuncAttributeMaxDynamicSharedMemorySize,
                         ATTN3_SMEM_BYTES);

    lambda_kernel<<<1, 32>>>(l0, l1, l2, l3);

    const int NX = MTOT * DMODEL;
    const int NW = DMODEL * DMODEL;
    f2h_kernel<<<NX / 1024, 256>>>(inp, xh, NX);
    packw_kernel<<<NW / 1024, 256>>>(wq0, wcat, 0 * DMODEL);
    packw_kernel<<<NW / 1024, 256>>>(wq1, wcat, 1 * DMODEL);
    packw_kernel<<<NW / 1024, 256>>>(wk0, wcat, 2 * DMODEL);
    packw_kernel<<<NW / 1024, 256>>>(wk1, wcat, 3 * DMODEL);
    packw_kernel<<<NW / 1024, 256>>>(wv,  wcat, 4 * DMODEL);
    f2h_kernel<<<NW / 1024, 256>>>(wo, woh, NW);

    // Merged projection GEMM: [4096,1024] x [1024,5120] -> [4096,5120]
    dim3 pgrid(NQKV / 128, MTOT / 128);     // (40, 32) = 1280 CTAs
    gemm_f16<__half><<<pgrid, 256, HGEMM_SMEM_BYTES>>>(xh, wcat, qkvh,
                                                       MTOT, NQKV, DMODEL);

    attn_tc_kernel<<<dim3(SEQ / QT, BATCH * NHEAD), 256, ATTN3_SMEM_BYTES>>>(
        qkvh, lnw, lnb, attnh);

    dim3 ggrid(DMODEL / 128, MTOT / 128);   // (8, 32)
    gemm_f16<float><<<ggrid, 256, HGEMM_SMEM_BYTES>>>(attnh, woh, out, MTOT, DMODEL, DMODEL);
}

// round 12
// speedup vs baseline: 2.5230x; 1.0324x over previous
#include <cuda_runtime.h>
#include <cuda_fp16.h>
#include <math.h>
#include <stdint.h>

// Problem constants
#define BATCH 2
#define SEQ   2048
#define DMODEL 1024
#define NHEAD 16
#define DHEAD 64
#define MTOT  (BATCH*SEQ)      // 4096
#define NQKV  (5*DMODEL)       // 5120 (q0,q1,k0,k1,v concatenated)
#define LAMBDA_INIT 0.8f
#define LN_EPS 1e-5f
#define LOG2E 1.44269504088896340736f

// ---------------------------------------------------------------------------
// Scratch
// ---------------------------------------------------------------------------
__device__ __half g_qkvh[MTOT*NQKV];        // merged projection output
__device__ __half g_xh[MTOT*DMODEL];
__device__ __half g_attnh[MTOT*DMODEL];
__device__ __half g_wcat[DMODEL*NQKV];      // concatenated weights
__device__ __half g_woh[DMODEL*DMODEL];
__device__ float g_lambda;

// ---------------------------------------------------------------------------
// Fused preamble: one launch does X->fp16, 5 weights packed into wcat,
// WO->fp16, and the lambda scalar.
// Block map: [0,4096) X | [4096,9216) weights | [9216,10240) WO | 10240 lambda
// ---------------------------------------------------------------------------
__global__ void convert_all_kernel(
        const float* __restrict__ inp,
        const float* __restrict__ wq0, const float* __restrict__ wq1,
        const float* __restrict__ wk0, const float* __restrict__ wk1,
        const float* __restrict__ wv,  const float* __restrict__ wo,
        const float* __restrict__ l0,  const float* __restrict__ l1,
        const float* __restrict__ l2,  const float* __restrict__ l3,
        __half* __restrict__ xh, __half* __restrict__ wcat,
        __half* __restrict__ woh) {
    int blk = blockIdx.x;
    int tid = threadIdx.x;

    if (blk < 4096) {
        // X -> fp16
        int i = blk * 1024 + tid * 4;
        float4 v = *(const float4*)(inp + i);
        *(__half2*)(xh + i)     = __floats2half2_rn(v.x, v.y);
        *(__half2*)(xh + i + 2) = __floats2half2_rn(v.z, v.w);
    } else if (blk < 9216) {
        // weight wi packed into wcat column block wi*1024
        int r = blk - 4096;
        int wi = r >> 10;
        const float* src;
        switch (wi) {
            case 0: src = wq0; break;
            case 1: src = wq1; break;
            case 2: src = wk0; break;
            case 3: src = wk1; break;
            default: src = wv; break;
        }
        int i = (r & 1023) * 1024 + tid * 4;
        int k = i >> 10;
        int n = i & 1023;
        float4 v = *(const float4*)(src + i);
        __half* dst = wcat + (size_t)k * NQKV + wi * DMODEL + n;
        *(__half2*)(dst)     = __floats2half2_rn(v.x, v.y);
        *(__half2*)(dst + 2) = __floats2half2_rn(v.z, v.w);
    } else if (blk < 10240) {
        // WO -> fp16
        int i = (blk - 9216) * 1024 + tid * 4;
        float4 v = *(const float4*)(wo + i);
        *(__half2*)(woh + i)     = __floats2half2_rn(v.x, v.y);
        *(__half2*)(woh + i + 2) = __floats2half2_rn(v.z, v.w);
    } else {
        // lambda scalar (warp 0 only)
        if (tid < 32) {
            float a = l0[tid]*l1[tid] + l0[tid+32]*l1[tid+32];
            float b = l2[tid]*l3[tid] + l2[tid+32]*l3[tid+32];
            #pragma unroll
            for (int o = 16; o >= 1; o >>= 1) {
                a += __shfl_xor_sync(0xffffffffu, a, o);
                b += __shfl_xor_sync(0xffffffffu, b, o);
            }
            if (tid == 0)
                g_lambda = (-expf(a) + LAMBDA_INIT) + (-expf(b) + LAMBDA_INIT);
        }
    }
}

__device__ __forceinline__ float ex2f(float x) {
    float r;
    asm("ex2.approx.f32 %0, %1;" : "=f"(r) : "f"(x));
    return r;
}

// ---------------------------------------------------------------------------
// FP16 tensor-core GEMM: C[M,N] = A[M,K](f16) @ B[K,N](f16), fp32 accum.
// ---------------------------------------------------------------------------
#define HBM 128
#define HBN 128
#define HBK 64
#define A_LDH 72
#define B_LDH 136
#define HAS_STAGE (HBM*A_LDH)
#define HBS_STAGE (HBK*B_LDH)
#define HGEMM_SMEM_BYTES ((2*(HAS_STAGE+HBS_STAGE))*2)

template <typename CT>
__global__ __launch_bounds__(256, 2) void gemm_f16(const __half* __restrict__ A,
                                                   const __half* __restrict__ B,
                                                   CT* __restrict__ C,
                                                   int M, int N, int K) {
    extern __shared__ __align__(16) char smraw[];
    __half* As = (__half*)smraw;
    __half* Bs = As + 2 * HAS_STAGE;

    int tid  = threadIdx.x;
    int lane = tid & 31;
    int warp = tid >> 5;
    int g    = lane >> 2;
    int tig  = lane & 3;
    int wm   = (warp >> 2) * 64;
    int wn   = (warp & 3) * 32;

    int bx = blockIdx.x, by = blockIdx.y;

    const __half* Ag = A + (size_t)(by * HBM) * K;
    const __half* Bg = B + bx * HBN;

    uint32_t s_as = (uint32_t)__cvta_generic_to_shared(As);
    uint32_t s_bs = (uint32_t)__cvta_generic_to_shared(Bs);

    float acc[4][4][4];
    #pragma unroll
    for (int i = 0; i < 4; i++)
        #pragma unroll
        for (int j = 0; j < 4; j++)
            #pragma unroll
            for (int q = 0; q < 4; q++) acc[i][j][q] = 0.f;

    uint32_t a_lane = ((uint32_t)((wm + (lane & 15)) * A_LDH + (lane >> 4) * 8)) * 2u;
    uint32_t b_lane = ((uint32_t)((lane & 15) * B_LDH + wn + (lane >> 4) * 8)) * 2u;

    const int NT = K / HBK;

    auto prefetch = [&](int kt, int stage) {
        uint32_t ad = s_as + (uint32_t)(stage * HAS_STAGE) * 2u;
        uint32_t bd = s_bs + (uint32_t)(stage * HBS_STAGE) * 2u;
        const __half* agk = Ag + kt * HBK;
        const __half* bgk = Bg + (size_t)(kt * HBK) * N;
        #pragma unroll
        for (int r = 0; r < 4; r++) {
            int c = tid + r * 256;
            int arow = c >> 3, acol = (c & 7) * 8;
            asm volatile("cp.async.cg.shared.global [%0], [%1], 16;\n"
                         :: "r"(ad + (uint32_t)(arow * A_LDH + acol) * 2u),
                            "l"(agk + (size_t)arow * K + acol));
            int brow = c >> 4, bcol = (c & 15) * 8;
            asm volatile("cp.async.cg.shared.global [%0], [%1], 16;\n"
                         :: "r"(bd + (uint32_t)(brow * B_LDH + bcol) * 2u),
                            "l"(bgk + (size_t)brow * N + bcol));
        }
        asm volatile("cp.async.commit_group;\n");
    };

    prefetch(0, 0);

    for (int kt = 0; kt < NT; kt++) {
        int stage = kt & 1;
        if (kt + 1 < NT) {
            prefetch(kt + 1, stage ^ 1);
            asm volatile("cp.async.wait_group 1;\n");
        } else {
            asm volatile("cp.async.wait_group 0;\n");
        }
        __syncthreads();

        uint32_t a_base = s_as + (uint32_t)(stage * HAS_STAGE) * 2u + a_lane;
        uint32_t b_base = s_bs + (uint32_t)(stage * HBS_STAGE) * 2u + b_lane;

        #pragma unroll
        for (int k16 = 0; k16 < HBK / 16; k16++) {
            uint32_t a[4][4];
            #pragma unroll
            for (int i = 0; i < 4; i++) {
                uint32_t addr = a_base + (uint32_t)(i * 16 * A_LDH + k16 * 16) * 2u;
                asm volatile("ldmatrix.sync.aligned.m8n8.x4.shared.b16 {%0,%1,%2,%3}, [%4];\n"
                             : "=r"(a[i][0]), "=r"(a[i][1]), "=r"(a[i][2]), "=r"(a[i][3])
                             : "r"(addr));
            }
            uint32_t bf[4][2];
            #pragma unroll
            for (int jp = 0; jp < 2; jp++) {
                uint32_t addr = b_base + (uint32_t)(k16 * 16 * B_LDH + jp * 16) * 2u;
                asm volatile("ldmatrix.sync.aligned.m8n8.x4.trans.shared.b16 {%0,%1,%2,%3}, [%4];\n"
                             : "=r"(bf[2*jp][0]), "=r"(bf[2*jp][1]),
                               "=r"(bf[2*jp+1][0]), "=r"(bf[2*jp+1][1])
                             : "r"(addr));
            }
            #pragma unroll
            for (int i = 0; i < 4; i++)
                #pragma unroll
                for (int j = 0; j < 4; j++)
                    asm volatile(
                        "mma.sync.aligned.m16n8k16.row.col.f32.f16.f16.f32 "
                        "{%0,%1,%2,%3}, {%4,%5,%6,%7}, {%8,%9}, {%0,%1,%2,%3};\n"
                        : "+f"(acc[i][j][0]), "+f"(acc[i][j][1]),
                          "+f"(acc[i][j][2]), "+f"(acc[i][j][3])
                        : "r"(a[i][0]), "r"(a[i][1]), "r"(a[i][2]), "r"(a[i][3]),
                          "r"(bf[j][0]), "r"(bf[j][1]));
        }
        __syncthreads();
    }

    #pragma unroll
    for (int i = 0; i < 4; i++) {
        int row = by * HBM + wm + i * 16 + g;
        #pragma unroll
        for (int j = 0; j < 4; j++) {
            int col = bx * HBN + wn + j * 8 + 2 * tig;
            if (sizeof(CT) == 4) {
                *(float2*)((float*)C + (size_t)row * N + col) =
                    make_float2(acc[i][j][0], acc[i][j][1]);
                *(float2*)((float*)C + (size_t)(row + 8) * N + col) =
                    make_float2(acc[i][j][2], acc[i][j][3]);
            } else {
                *(__half2*)((__half*)C + (size_t)row * N + col) =
                    __floats2half2_rn(acc[i][j][0], acc[i][j][1]);
                *(__half2*)((__half*)C + (size_t)(row + 8) * N + col) =
                    __floats2half2_rn(acc[i][j][2], acc[i][j][3]);
            }
        }
    }
}

// ---------------------------------------------------------------------------
// FP16 tensor-core differential flash attention + per-head LayerNorm.
// ---------------------------------------------------------------------------
#define QT 128
#define QLDH 72
#define PLDH 72
#define KLDH 72
#define VLDH 72
#define KH_STAGE (64*KLDH)
#define VH_STAGE (64*VLDH)
#define SQH_OFF  0
#define SK0H_OFF (2*QT*QLDH)
#define SK1H_OFF (SK0H_OFF + 2*KH_STAGE)
#define SVH_OFF  (SK1H_OFF + 2*KH_STAGE)
#define SPH_OFF  (SVH_OFF + 2*VH_STAGE)
#define ATTN3_SMEM_HALVES (SPH_OFF + QT*PLDH)
#define ATTN3_SMEM_BYTES (ATTN3_SMEM_HALVES*2)   // 110592

__global__ __launch_bounds__(256, 2) void attn_tc_kernel(
        const __half* __restrict__ qkv,
        const float* __restrict__ ln_w, const float* __restrict__ ln_b,
        __half* __restrict__ attnh) {
    extern __shared__ __align__(16) char smraw[];
    __half* smh = (__half*)smraw;
    __half* sQ  = smh + SQH_OFF;
    __half* sK0 = smh + SK0H_OFF;
    __half* sK1 = smh + SK1H_OFF;
    __half* sV  = smh + SVH_OFF;
    __half* sP  = smh + SPH_OFF;

    int qt = gridDim.x - 1 - blockIdx.x;   // heavy tiles first
    int bh = blockIdx.y;
    int b = bh >> 4, h = bh & 15;

    int tid = threadIdx.x;
    int lane = tid & 31;
    int w = tid >> 5;
    int g = lane >> 2;
    int tig = lane & 3;

    const float scale2 = 0.125f * LOG2E;
    const float slope2 = exp2f(-0.5f * (float)(h + 1)) * LOG2E;
    const size_t basec = (size_t)b * SEQ * NQKV + (size_t)h * DHEAD;

    uint32_t s_q  = (uint32_t)__cvta_generic_to_shared(sQ);
    uint32_t s_k0 = (uint32_t)__cvta_generic_to_shared(sK0);
    uint32_t s_k1 = (uint32_t)__cvta_generic_to_shared(sK1);
    uint32_t s_v  = (uint32_t)__cvta_generic_to_shared(sV);
    uint32_t s_p  = (uint32_t)__cvta_generic_to_shared(sP);

    // --- load Q (both streams) via cp.async ---
    {
        int row = tid >> 1;
        int c0  = (tid & 1) * 32;
        size_t gofs = basec + (size_t)(qt * QT + row) * NQKV + c0;
        #pragma unroll
        for (int st = 0; st < 2; st++) {
            const __half* src = qkv + gofs + st * DMODEL;
            uint32_t dst = s_q + (uint32_t)(st * QT * QLDH + row * QLDH + c0) * 2u;
            #pragma unroll
            for (int c = 0; c < 32; c += 8)
                asm volatile("cp.async.cg.shared.global [%0], [%1], 16;\n"
                             :: "r"(dst + c * 2u), "l"(src + c));
        }
        asm volatile("cp.async.commit_group;\n");
    }

    float oacc[2][8][4];
    #pragma unroll
    for (int st = 0; st < 2; st++)
        #pragma unroll
        for (int j = 0; j < 8; j++)
            #pragma unroll
            for (int q = 0; q < 4; q++) oacc[st][j][q] = 0.f;
    float mrow[2][2], lrow[2][2];
    #pragma unroll
    for (int st = 0; st < 2; st++)
        #pragma unroll
        for (int hh = 0; hh < 2; hh++) { mrow[st][hh] = -INFINITY; lrow[st][hh] = 0.f; }

    uint32_t qa_lane = ((uint32_t)((w * 16 + (lane & 15)) * QLDH + (lane >> 4) * 8)) * 2u;
    uint32_t pa_lane = s_p + ((uint32_t)((w * 16 + (lane & 15)) * PLDH + (lane >> 4) * 8)) * 2u;
    uint32_t kb_lane = ((uint32_t)(((lane & 7) + ((lane >> 4) & 1) * 8) * KLDH
                                   + ((lane >> 3) & 1) * 8)) * 2u;
    uint32_t vb_lane = ((uint32_t)((lane & 15) * VLDH + (lane >> 4) * 8)) * 2u;

    const int qrow0 = qt * QT + w * 16;
    const int qq0 = qrow0 + g;

    const int prow = tid >> 2;
    const int pc0  = (tid & 3) * 16;

    auto prefetch = [&](int kt, int stage) {
        size_t gofs = basec + (size_t)(kt * 64 + prow) * NQKV + pc0;
        const __half* gk0 = qkv + gofs + 2 * DMODEL;
        const __half* gk1 = qkv + gofs + 3 * DMODEL;
        const __half* gv  = qkv + gofs + 4 * DMODEL;
        uint32_t dk0 = s_k0 + (uint32_t)(stage * KH_STAGE + prow * KLDH + pc0) * 2u;
        uint32_t dk1 = s_k1 + (uint32_t)(stage * KH_STAGE + prow * KLDH + pc0) * 2u;
        uint32_t dv  = s_v  + (uint32_t)(stage * VH_STAGE + prow * VLDH + pc0) * 2u;
        #pragma unroll
        for (int c = 0; c < 16; c += 8) {
            asm volatile("cp.async.cg.shared.global [%0], [%1], 16;\n"
                         :: "r"(dk0 + c * 2u), "l"(gk0 + c));
            asm volatile("cp.async.cg.shared.global [%0], [%1], 16;\n"
                         :: "r"(dk1 + c * 2u), "l"(gk1 + c));
            asm volatile("cp.async.cg.shared.global [%0], [%1], 16;\n"
                         :: "r"(dv + c * 2u), "l"(gv + c));
        }
        asm volatile("cp.async.commit_group;\n");
    };

    const int ktmax = 2 * qt + 1;

    prefetch(0, 0);

    for (int kt = 0; kt <= ktmax; kt++) {
        int stage = kt & 1;
        if (kt < ktmax) {
            prefetch(kt + 1, stage ^ 1);
            asm volatile("cp.async.wait_group 1;\n");
        } else {
            asm volatile("cp.async.wait_group 0;\n");
        }
        __syncthreads();

        const bool active = (kt * 64 <= qrow0 + 15);
        const bool diag   = (kt * 64 + 63 > qrow0);

        if (active) {
            uint32_t kbase0 = s_k0 + (uint32_t)(stage * KH_STAGE) * 2u + kb_lane;
            uint32_t kbase1 = s_k1 + (uint32_t)(stage * KH_STAGE) * 2u + kb_lane;
            uint32_t vbase  = s_v  + (uint32_t)(stage * VH_STAGE) * 2u + vb_lane;

            #pragma unroll
            for (int st = 0; st < 2; st++) {
                uint32_t kb = (st == 0) ? kbase0 : kbase1;

                float sc[8][4];
                #pragma unroll
                for (int j = 0; j < 8; j++)
                    #pragma unroll
                    for (int q = 0; q < 4; q++) sc[j][q] = 0.f;

                uint32_t qa_base = s_q + (uint32_t)(st * QT * QLDH) * 2u + qa_lane;
                #pragma unroll
                for (int k16 = 0; k16 < 4; k16++) {
                    uint32_t a0, a1, a2, a3;
                    asm volatile("ldmatrix.sync.aligned.m8n8.x4.shared.b16 {%0,%1,%2,%3}, [%4];\n"
                                 : "=r"(a0), "=r"(a1), "=r"(a2), "=r"(a3)
                                 : "r"(qa_base + (uint32_t)(k16 * 16) * 2u));
                    #pragma unroll
                    for (int jp = 0; jp < 4; jp++) {
                        uint32_t b0, b1, b2, b3;
                        uint32_t addr = kb + (uint32_t)(jp * 16 * KLDH + k16 * 16) * 2u;
                        asm volatile("ldmatrix.sync.aligned.m8n8.x4.shared.b16 {%0,%1,%2,%3}, [%4];\n"
                                     : "=r"(b0), "=r"(b1), "=r"(b2), "=r"(b3) : "r"(addr));
                        asm volatile(
                            "mma.sync.aligned.m16n8k16.row.col.f32.f16.f16.f32 "
                            "{%0,%1,%2,%3}, {%4,%5,%6,%7}, {%8,%9}, {%0,%1,%2,%3};\n"
                            : "+f"(sc[2*jp][0]), "+f"(sc[2*jp][1]),
                              "+f"(sc[2*jp][2]), "+f"(sc[2*jp][3])
                            : "r"(a0), "r"(a1), "r"(a2), "r"(a3), "r"(b0), "r"(b1));
                        asm volatile(
                            "mma.sync.aligned.m16n8k16.row.col.f32.f16.f16.f32 "
                            "{%0,%1,%2,%3}, {%4,%5,%6,%7}, {%8,%9}, {%0,%1,%2,%3};\n"
                            : "+f"(sc[2*jp+1][0]), "+f"(sc[2*jp+1][1]),
                              "+f"(sc[2*jp+1][2]), "+f"(sc[2*jp+1][3])
                            : "r"(a0), "r"(a1), "r"(a2), "r"(a3), "r"(b2), "r"(b3));
                    }
                }

                // ---- softmax (online, log2 domain), rows g and g+8 ----
                #pragma unroll
                for (int hh = 0; hh < 2; hh++) {
                    int qq = qq0 + hh * 8;
                    float mx = -INFINITY;
                    #pragma unroll
                    for (int j = 0; j < 8; j++) {
                        #pragma unroll
                        for (int e = 0; e < 2; e++) {
                            int kk = kt * 64 + j * 8 + 2 * tig + e;
                            float s = sc[j][hh * 2 + e] * scale2 - slope2 * (float)(qq - kk);
                            if (diag && kk > qq) s = -INFINITY;
                            sc[j][hh * 2 + e] = s;
                            mx = fmaxf(mx, s);
                        }
                    }
                    mx = fmaxf(mx, __shfl_xor_sync(0xffffffffu, mx, 1));
                    mx = fmaxf(mx, __shfl_xor_sync(0xffffffffu, mx, 2));
                    float mn = fmaxf(mrow[st][hh], mx);
                    float corr = ex2f(mrow[st][hh] - mn);
                    mrow[st][hh] = mn;
                    float rs = 0.f;
                    #pragma unroll
                    for (int j = 0; j < 8; j++) {
                        #pragma unroll
                        for (int e = 0; e < 2; e++) {
                            float pv = ex2f(sc[j][hh * 2 + e] - mn);
                            sc[j][hh * 2 + e] = pv;
                            rs += pv;
                        }
                    }
                    rs += __shfl_xor_sync(0xffffffffu, rs, 1);
                    rs += __shfl_xor_sync(0xffffffffu, rs, 2);
                    lrow[st][hh] = lrow[st][hh] * corr + rs;
                    #pragma unroll
                    for (int j = 0; j < 8; j++) {
                        oacc[st][j][hh * 2 + 0] *= corr;
                        oacc[st][j][hh * 2 + 1] *= corr;
                    }
                }

                // ---- write P (fp16) to own-warp rows of sP ----
                #pragma unroll
                for (int hh = 0; hh < 2; hh++) {
                    __half* pr = sP + (w * 16 + g + hh * 8) * PLDH;
                    #pragma unroll
                    for (int j = 0; j < 8; j++)
                        *(__half2*)(pr + j * 8 + 2 * tig) =
                            __floats2half2_rn(sc[j][hh * 2 + 0], sc[j][hh * 2 + 1]);
                }
                __syncwarp();

                // ---- PV: oacc += P @ V ----
                #pragma unroll
                for (int k16 = 0; k16 < 4; k16++) {
                    uint32_t a0, a1, a2, a3;
                    asm volatile("ldmatrix.sync.aligned.m8n8.x4.shared.b16 {%0,%1,%2,%3}, [%4];\n"
                                 : "=r"(a0), "=r"(a1), "=r"(a2), "=r"(a3)
                                 : "r"(pa_lane + (uint32_t)(k16 * 16) * 2u));
                    #pragma unroll
                    for (int jp = 0; jp < 4; jp++) {
                        uint32_t b0, b1, b2, b3;
                        uint32_t addr = vbase + (uint32_t)(k16 * 16 * VLDH + jp * 16) * 2u;
                        asm volatile("ldmatrix.sync.aligned.m8n8.x4.trans.shared.b16 {%0,%1,%2,%3}, [%4];\n"
                                     : "=r"(b0), "=r"(b1), "=r"(b2), "=r"(b3) : "r"(addr));
                        asm volatile(
                            "mma.sync.aligned.m16n8k16.row.col.f32.f16.f16.f32 "
                            "{%0,%1,%2,%3}, {%4,%5,%6,%7}, {%8,%9}, {%0,%1,%2,%3};\n"
                            : "+f"(oacc[st][2*jp][0]), "+f"(oacc[st][2*jp][1]),
                              "+f"(oacc[st][2*jp][2]), "+f"(oacc[st][2*jp][3])
                            : "r"(a0), "r"(a1), "r"(a2), "r"(a3), "r"(b0), "r"(b1));
                        asm volatile(
                            "mma.sync.aligned.m16n8k16.row.col.f32.f16.f16.f32 "
                            "{%0,%1,%2,%3}, {%4,%5,%6,%7}, {%8,%9}, {%0,%1,%2,%3};\n"
                            : "+f"(oacc[st][2*jp+1][0]), "+f"(oacc[st][2*jp+1][1]),
                              "+f"(oacc[st][2*jp+1][2]), "+f"(oacc[st][2*jp+1][3])
                            : "r"(a0), "r"(a1), "r"(a2), "r"(a3), "r"(b2), "r"(b3));
                    }
                }
                __syncwarp();
            }
        }
        __syncthreads();
    }

    // --- epilogue: combine streams, per-head LayerNorm over DH, store fp16 ---
    float lam = g_lambda;
    #pragma unroll
    for (int hh = 0; hh < 2; hh++) {
        float inv0 = 1.0f / lrow[0][hh];
        float inv1 = 1.0f / lrow[1][hh];
        float o[8][2];
        float s_ = 0.f;
        #pragma unroll
        for (int j = 0; j < 8; j++) {
            #pragma unroll
            for (int e = 0; e < 2; e++) {
                float val = oacc[0][j][hh * 2 + e] * inv0
                          - lam * (oacc[1][j][hh * 2 + e] * inv1);
                o[j][e] = val;
                s_ += val;
            }
        }
        s_ += __shfl_xor_sync(0xffffffffu, s_, 1);
        s_ += __shfl_xor_sync(0xffffffffu, s_, 2);
        float mu = s_ * (1.0f / 64.0f);
        float vs = 0.f;
        #pragma unroll
        for (int j = 0; j < 8; j++) {
            #pragma unroll
            for (int e = 0; e < 2; e++) { float d = o[j][e] - mu; vs += d * d; }
        }
        vs += __shfl_xor_sync(0xffffffffu, vs, 1);
        vs += __shfl_xor_sync(0xffffffffu, vs, 2);
        float r = rsqrtf(vs * (1.0f / 64.0f) + LN_EPS);

        size_t row = (size_t)b * SEQ + (size_t)(qrow0 + g + hh * 8);
        #pragma unroll
        for (int j = 0; j < 8; j++) {
            int col = h * DHEAD + j * 8 + 2 * tig;
            float wv0 = ln_w[h * DHEAD + j * 8 + 2 * tig];
            float wv1 = ln_w[h * DHEAD + j * 8 + 2 * tig + 1];
            float bv0 = ln_b[h * DHEAD + j * 8 + 2 * tig];
            float bv1 = ln_b[h * DHEAD + j * 8 + 2 * tig + 1];
            *(__half2*)(attnh + row * DMODEL + col) =
                __floats2half2_rn((o[j][0] - mu) * r * wv0 + bv0,
                                  (o[j][1] - mu) * r * wv1 + bv1);
        }
    }
}

// ---------------------------------------------------------------------------
// Launch
// ---------------------------------------------------------------------------
extern "C" void kernel_launch(void* const* d_in, const int* in_sizes, int n_in,
                              void* d_out, int out_size) {
    const float* inp = (const float*)d_in[0];
    const float* wq0 = (const float*)d_in[1];
    const float* wq1 = (const float*)d_in[2];
    const float* wk0 = (const float*)d_in[3];
    const float* wk1 = (const float*)d_in[4];
    const float* wv  = (const float*)d_in[5];
    const float* wo  = (const float*)d_in[6];
    const float* l0  = (const float*)d_in[7];
    const float* l1  = (const float*)d_in[8];
    const float* l2  = (const float*)d_in[9];
    const float* l3  = (const float*)d_in[10];
    const float* lnw = (const float*)d_in[11];
    const float* lnb = (const float*)d_in[12];
    float* out = (float*)d_out;

    __half *qkvh, *xh, *attnh, *wcat, *woh;
    cudaGetSymbolAddress((void**)&qkvh, g_qkvh);
    cudaGetSymbolAddress((void**)&xh, g_xh);
    cudaGetSymbolAddress((void**)&attnh, g_attnh);
    cudaGetSymbolAddress((void**)&wcat, g_wcat);
    cudaGetSymbolAddress((void**)&woh, g_woh);

    cudaFuncSetAttribute(gemm_f16<float>, cudaFuncAttributeMaxDynamicSharedMemorySize,
                         HGEMM_SMEM_BYTES);
    cudaFuncSetAttribute(gemm_f16<__half>, cudaFuncAttributeMaxDynamicSharedMemorySize,
                         HGEMM_SMEM_BYTES);
    cudaFuncSetAttribute(attn_tc_kernel, cudaFuncAttributeMaxDynamicSharedMemorySize,
                         ATTN3_SMEM_BYTES);

    // One fused preamble launch: X/W/WO conversions + lambda
    convert_all_kernel<<<10241, 256>>>(inp, wq0, wq1, wk0, wk1, wv, wo,
                                       l0, l1, l2, l3, xh, wcat, woh);

    // Merged projection GEMM: [4096,1024] x [1024,5120] -> [4096,5120]
    dim3 pgrid(NQKV / 128, MTOT / 128);     // (40, 32) = 1280 CTAs
    gemm_f16<__half><<<pgrid, 256, HGEMM_SMEM_BYTES>>>(xh, wcat, qkvh,
                                                       MTOT, NQKV, DMODEL);

    attn_tc_kernel<<<dim3(SEQ / QT, BATCH * NHEAD), 256, ATTN3_SMEM_BYTES>>>(
        qkvh, lnw, lnb, attnh);

    dim3 ggrid(DMODEL / 128, MTOT / 128);   // (8, 32)
    gemm_f16<float><<<ggrid, 256, HGEMM_SMEM_BYTES>>>(attnh, woh, out, MTOT, DMODEL, DMODEL);
}

// round 13
// speedup vs baseline: 2.6832x; 1.0635x over previous
#include <cuda_runtime.h>
#include <cuda_fp16.h>
#include <math.h>
#include <stdint.h>

// Problem constants
#define BATCH 2
#define SEQ   2048
#define DMODEL 1024
#define NHEAD 16
#define DHEAD 64
#define MTOT  (BATCH*SEQ)      // 4096
#define NQKV  (5*DMODEL)       // 5120 (q0,q1,k0,k1,v concatenated)
#define LAMBDA_INIT 0.8f
#define LN_EPS 1e-5f
#define LOG2E 1.44269504088896340736f

// ---------------------------------------------------------------------------
// Scratch
// ---------------------------------------------------------------------------
__device__ __half g_qkvh[MTOT*NQKV];        // merged projection output
__device__ __half g_xh[MTOT*DMODEL];
__device__ __half g_attnh[MTOT*DMODEL];
__device__ __half g_wcat[DMODEL*NQKV];      // concatenated weights
__device__ __half g_woh[DMODEL*DMODEL];
__device__ float g_lambda;

// ---------------------------------------------------------------------------
// Fused preamble: one launch does X->fp16, 5 weights packed into wcat,
// WO->fp16, and the lambda scalar.
// ---------------------------------------------------------------------------
__global__ void convert_all_kernel(
        const float* __restrict__ inp,
        const float* __restrict__ wq0, const float* __restrict__ wq1,
        const float* __restrict__ wk0, const float* __restrict__ wk1,
        const float* __restrict__ wv,  const float* __restrict__ wo,
        const float* __restrict__ l0,  const float* __restrict__ l1,
        const float* __restrict__ l2,  const float* __restrict__ l3,
        __half* __restrict__ xh, __half* __restrict__ wcat,
        __half* __restrict__ woh) {
    int blk = blockIdx.x;
    int tid = threadIdx.x;

    if (blk < 4096) {
        int i = blk * 1024 + tid * 4;
        float4 v = *(const float4*)(inp + i);
        *(__half2*)(xh + i)     = __floats2half2_rn(v.x, v.y);
        *(__half2*)(xh + i + 2) = __floats2half2_rn(v.z, v.w);
    } else if (blk < 9216) {
        int r = blk - 4096;
        int wi = r >> 10;
        const float* src;
        switch (wi) {
            case 0: src = wq0; break;
            case 1: src = wq1; break;
            case 2: src = wk0; break;
            case 3: src = wk1; break;
            default: src = wv; break;
        }
        int i = (r & 1023) * 1024 + tid * 4;
        int k = i >> 10;
        int n = i & 1023;
        float4 v = *(const float4*)(src + i);
        __half* dst = wcat + (size_t)k * NQKV + wi * DMODEL + n;
        *(__half2*)(dst)     = __floats2half2_rn(v.x, v.y);
        *(__half2*)(dst + 2) = __floats2half2_rn(v.z, v.w);
    } else if (blk < 10240) {
        int i = (blk - 9216) * 1024 + tid * 4;
        float4 v = *(const float4*)(wo + i);
        *(__half2*)(woh + i)     = __floats2half2_rn(v.x, v.y);
        *(__half2*)(woh + i + 2) = __floats2half2_rn(v.z, v.w);
    } else {
        if (tid < 32) {
            float a = l0[tid]*l1[tid] + l0[tid+32]*l1[tid+32];
            float b = l2[tid]*l3[tid] + l2[tid+32]*l3[tid+32];
            #pragma unroll
            for (int o = 16; o >= 1; o >>= 1) {
                a += __shfl_xor_sync(0xffffffffu, a, o);
                b += __shfl_xor_sync(0xffffffffu, b, o);
            }
            if (tid == 0)
                g_lambda = (-expf(a) + LAMBDA_INIT) + (-expf(b) + LAMBDA_INIT);
        }
    }
}

__device__ __forceinline__ float ex2f(float x) {
    float r;
    asm("ex2.approx.f32 %0, %1;" : "=f"(r) : "f"(x));
    return r;
}

// ---------------------------------------------------------------------------
// FP16 tensor-core GEMM: C[M,N] = A[M,K](f16) @ B[K,N](f16), fp32 accum.
// 3-stage cp.async pipeline, 1 syncthreads per k-tile.
// ---------------------------------------------------------------------------
#define HBM 128
#define HBN 128
#define HBK 64
#define A_LDH 72
#define B_LDH 136
#define HAS_STAGE (HBM*A_LDH)
#define HBS_STAGE (HBK*B_LDH)
#define GSTAGES 3
#define HGEMM_SMEM_BYTES ((GSTAGES*(HAS_STAGE+HBS_STAGE))*2)   // 107520

template <typename CT>
__global__ __launch_bounds__(256, 2) void gemm_f16(const __half* __restrict__ A,
                                                   const __half* __restrict__ B,
                                                   CT* __restrict__ C,
                                                   int M, int N, int K) {
    extern __shared__ __align__(16) char smraw[];
    __half* As = (__half*)smraw;
    __half* Bs = As + GSTAGES * HAS_STAGE;

    int tid  = threadIdx.x;
    int lane = tid & 31;
    int warp = tid >> 5;
    int g    = lane >> 2;
    int tig  = lane & 3;
    int wm   = (warp >> 2) * 64;
    int wn   = (warp & 3) * 32;

    int bx = blockIdx.x, by = blockIdx.y;

    const __half* Ag = A + (size_t)(by * HBM) * K;
    const __half* Bg = B + bx * HBN;

    uint32_t s_as = (uint32_t)__cvta_generic_to_shared(As);
    uint32_t s_bs = (uint32_t)__cvta_generic_to_shared(Bs);

    float acc[4][4][4];
    #pragma unroll
    for (int i = 0; i < 4; i++)
        #pragma unroll
        for (int j = 0; j < 4; j++)
            #pragma unroll
            for (int q = 0; q < 4; q++) acc[i][j][q] = 0.f;

    uint32_t a_lane = ((uint32_t)((wm + (lane & 15)) * A_LDH + (lane >> 4) * 8)) * 2u;
    uint32_t b_lane = ((uint32_t)((lane & 15) * B_LDH + wn + (lane >> 4) * 8)) * 2u;

    const int NT = K / HBK;

    auto prefetch = [&](int kt, int stage) {
        uint32_t ad = s_as + (uint32_t)(stage * HAS_STAGE) * 2u;
        uint32_t bd = s_bs + (uint32_t)(stage * HBS_STAGE) * 2u;
        const __half* agk = Ag + kt * HBK;
        const __half* bgk = Bg + (size_t)(kt * HBK) * N;
        #pragma unroll
        for (int r = 0; r < 4; r++) {
            int c = tid + r * 256;
            int arow = c >> 3, acol = (c & 7) * 8;
            asm volatile("cp.async.cg.shared.global [%0], [%1], 16;\n"
                         :: "r"(ad + (uint32_t)(arow * A_LDH + acol) * 2u),
                            "l"(agk + (size_t)arow * K + acol));
            int brow = c >> 4, bcol = (c & 15) * 8;
            asm volatile("cp.async.cg.shared.global [%0], [%1], 16;\n"
                         :: "r"(bd + (uint32_t)(brow * B_LDH + bcol) * 2u),
                            "l"(bgk + (size_t)brow * N + bcol));
        }
        asm volatile("cp.async.commit_group;\n");
    };

    prefetch(0, 0);
    prefetch(1, 1);

    int cs = 0;        // compute stage
    int ps = 2;        // prefetch stage = (kt+2) % 3

    for (int kt = 0; kt < NT; kt++) {
        asm volatile("cp.async.wait_group 1;\n");   // stage cs data complete
        __syncthreads();                            // visible block-wide; also
                                                    // proves stage ps reads done
        if (kt + 2 < NT) prefetch(kt + 2, ps);
        else asm volatile("cp.async.commit_group;\n");   // keep group count exact

        uint32_t a_base = s_as + (uint32_t)(cs * HAS_STAGE) * 2u + a_lane;
        uint32_t b_base = s_bs + (uint32_t)(cs * HBS_STAGE) * 2u + b_lane;

        #pragma unroll
        for (int k16 = 0; k16 < HBK / 16; k16++) {
            uint32_t a[4][4];
            #pragma unroll
            for (int i = 0; i < 4; i++) {
                uint32_t addr = a_base + (uint32_t)(i * 16 * A_LDH + k16 * 16) * 2u;
                asm volatile("ldmatrix.sync.aligned.m8n8.x4.shared.b16 {%0,%1,%2,%3}, [%4];\n"
                             : "=r"(a[i][0]), "=r"(a[i][1]), "=r"(a[i][2]), "=r"(a[i][3])
                             : "r"(addr));
            }
            uint32_t bf[4][2];
            #pragma unroll
            for (int jp = 0; jp < 2; jp++) {
                uint32_t addr = b_base + (uint32_t)(k16 * 16 * B_LDH + jp * 16) * 2u;
                asm volatile("ldmatrix.sync.aligned.m8n8.x4.trans.shared.b16 {%0,%1,%2,%3}, [%4];\n"
                             : "=r"(bf[2*jp][0]), "=r"(bf[2*jp][1]),
                               "=r"(bf[2*jp+1][0]), "=r"(bf[2*jp+1][1])
                             : "r"(addr));
            }
            #pragma unroll
            for (int i = 0; i < 4; i++)
                #pragma unroll
                for (int j = 0; j < 4; j++)
                    asm volatile(
                        "mma.sync.aligned.m16n8k16.row.col.f32.f16.f16.f32 "
                        "{%0,%1,%2,%3}, {%4,%5,%6,%7}, {%8,%9}, {%0,%1,%2,%3};\n"
                        : "+f"(acc[i][j][0]), "+f"(acc[i][j][1]),
                          "+f"(acc[i][j][2]), "+f"(acc[i][j][3])
                        : "r"(a[i][0]), "r"(a[i][1]), "r"(a[i][2]), "r"(a[i][3]),
                          "r"(bf[j][0]), "r"(bf[j][1]));
        }
        cs = (cs == GSTAGES - 1) ? 0 : cs + 1;
        ps = (ps == GSTAGES - 1) ? 0 : ps + 1;
    }

    #pragma unroll
    for (int i = 0; i < 4; i++) {
        int row = by * HBM + wm + i * 16 + g;
        #pragma unroll
        for (int j = 0; j < 4; j++) {
            int col = bx * HBN + wn + j * 8 + 2 * tig;
            if (sizeof(CT) == 4) {
                *(float2*)((float*)C + (size_t)row * N + col) =
                    make_float2(acc[i][j][0], acc[i][j][1]);
                *(float2*)((float*)C + (size_t)(row + 8) * N + col) =
                    make_float2(acc[i][j][2], acc[i][j][3]);
            } else {
                *(__half2*)((__half*)C + (size_t)row * N + col) =
                    __floats2half2_rn(acc[i][j][0], acc[i][j][1]);
                *(__half2*)((__half*)C + (size_t)(row + 8) * N + col) =
                    __floats2half2_rn(acc[i][j][2], acc[i][j][3]);
            }
        }
    }
}

// ---------------------------------------------------------------------------
// FP16 tensor-core differential flash attention + per-head LayerNorm.
// Single syncthreads per kv-tile; softmax bias folded (per-row -slope*q term
// dropped: softmax-invariant), score = fma(sc, scale2, slope2*kk).
// ---------------------------------------------------------------------------
#define QT 128
#define QLDH 72
#define PLDH 72
#define KLDH 72
#define VLDH 72
#define KH_STAGE (64*KLDH)
#define VH_STAGE (64*VLDH)
#define SQH_OFF  0
#define SK0H_OFF (2*QT*QLDH)
#define SK1H_OFF (SK0H_OFF + 2*KH_STAGE)
#define SVH_OFF  (SK1H_OFF + 2*KH_STAGE)
#define SPH_OFF  (SVH_OFF + 2*VH_STAGE)
#define ATTN3_SMEM_HALVES (SPH_OFF + QT*PLDH)
#define ATTN3_SMEM_BYTES (ATTN3_SMEM_HALVES*2)   // 110592

__global__ __launch_bounds__(256, 2) void attn_tc_kernel(
        const __half* __restrict__ qkv,
        const float* __restrict__ ln_w, const float* __restrict__ ln_b,
        __half* __restrict__ attnh) {
    extern __shared__ __align__(16) char smraw[];
    __half* smh = (__half*)smraw;
    __half* sQ  = smh + SQH_OFF;
    __half* sK0 = smh + SK0H_OFF;
    __half* sK1 = smh + SK1H_OFF;
    __half* sV  = smh + SVH_OFF;
    __half* sP  = smh + SPH_OFF;

    int qt = gridDim.x - 1 - blockIdx.x;   // heavy tiles first
    int bh = blockIdx.y;
    int b = bh >> 4, h = bh & 15;

    int tid = threadIdx.x;
    int lane = tid & 31;
    int w = tid >> 5;
    int g = lane >> 2;
    int tig = lane & 3;

    const float scale2 = 0.125f * LOG2E;
    const float slope2 = exp2f(-0.5f * (float)(h + 1)) * LOG2E;
    const size_t basec = (size_t)b * SEQ * NQKV + (size_t)h * DHEAD;

    uint32_t s_q  = (uint32_t)__cvta_generic_to_shared(sQ);
    uint32_t s_k0 = (uint32_t)__cvta_generic_to_shared(sK0);
    uint32_t s_k1 = (uint32_t)__cvta_generic_to_shared(sK1);
    uint32_t s_v  = (uint32_t)__cvta_generic_to_shared(sV);
    uint32_t s_p  = (uint32_t)__cvta_generic_to_shared(sP);

    // --- load Q (both streams) via cp.async ---
    {
        int row = tid >> 1;
        int c0  = (tid & 1) * 32;
        size_t gofs = basec + (size_t)(qt * QT + row) * NQKV + c0;
        #pragma unroll
        for (int st = 0; st < 2; st++) {
            const __half* src = qkv + gofs + st * DMODEL;
            uint32_t dst = s_q + (uint32_t)(st * QT * QLDH + row * QLDH + c0) * 2u;
            #pragma unroll
            for (int c = 0; c < 32; c += 8)
                asm volatile("cp.async.cg.shared.global [%0], [%1], 16;\n"
                             :: "r"(dst + c * 2u), "l"(src + c));
        }
        asm volatile("cp.async.commit_group;\n");
    }

    float oacc[2][8][4];
    #pragma unroll
    for (int st = 0; st < 2; st++)
        #pragma unroll
        for (int j = 0; j < 8; j++)
            #pragma unroll
            for (int q = 0; q < 4; q++) oacc[st][j][q] = 0.f;
    float mrow[2][2], lrow[2][2];
    #pragma unroll
    for (int st = 0; st < 2; st++)
        #pragma unroll
        for (int hh = 0; hh < 2; hh++) { mrow[st][hh] = -INFINITY; lrow[st][hh] = 0.f; }

    uint32_t qa_lane = ((uint32_t)((w * 16 + (lane & 15)) * QLDH + (lane >> 4) * 8)) * 2u;
    uint32_t pa_lane = s_p + ((uint32_t)((w * 16 + (lane & 15)) * PLDH + (lane >> 4) * 8)) * 2u;
    uint32_t kb_lane = ((uint32_t)(((lane & 7) + ((lane >> 4) & 1) * 8) * KLDH
                                   + ((lane >> 3) & 1) * 8)) * 2u;
    uint32_t vb_lane = ((uint32_t)((lane & 15) * VLDH + (lane >> 4) * 8)) * 2u;

    const int qrow0 = qt * QT + w * 16;
    const int qq0 = qrow0 + g;

    const int prow = tid >> 2;
    const int pc0  = (tid & 3) * 16;

    auto prefetch = [&](int kt, int stage) {
        size_t gofs = basec + (size_t)(kt * 64 + prow) * NQKV + pc0;
        const __half* gk0 = qkv + gofs + 2 * DMODEL;
        const __half* gk1 = qkv + gofs + 3 * DMODEL;
        const __half* gv  = qkv + gofs + 4 * DMODEL;
        uint32_t dk0 = s_k0 + (uint32_t)(stage * KH_STAGE + prow * KLDH + pc0) * 2u;
        uint32_t dk1 = s_k1 + (uint32_t)(stage * KH_STAGE + prow * KLDH + pc0) * 2u;
        uint32_t dv  = s_v  + (uint32_t)(stage * VH_STAGE + prow * VLDH + pc0) * 2u;
        #pragma unroll
        for (int c = 0; c < 16; c += 8) {
            asm volatile("cp.async.cg.shared.global [%0], [%1], 16;\n"
                         :: "r"(dk0 + c * 2u), "l"(gk0 + c));
            asm volatile("cp.async.cg.shared.global [%0], [%1], 16;\n"
                         :: "r"(dk1 + c * 2u), "l"(gk1 + c));
            asm volatile("cp.async.cg.shared.global [%0], [%1], 16;\n"
                         :: "r"(dv + c * 2u), "l"(gv + c));
        }
        asm volatile("cp.async.commit_group;\n");
    };

    const int ktmax = 2 * qt + 1;

    prefetch(0, 0);

    for (int kt = 0; kt <= ktmax; kt++) {
        int stage = kt & 1;
        asm volatile("cp.async.wait_group 0;\n");  // stage kt ready
        __syncthreads();                           // visible; stage^1 reads done
        if (kt < ktmax) prefetch(kt + 1, stage ^ 1);  // overlaps compute below

        const bool active = (kt * 64 <= qrow0 + 15);
        const bool diag   = (kt * 64 + 63 > qrow0);

        if (active) {
            uint32_t kbase0 = s_k0 + (uint32_t)(stage * KH_STAGE) * 2u + kb_lane;
            uint32_t kbase1 = s_k1 + (uint32_t)(stage * KH_STAGE) * 2u + kb_lane;
            uint32_t vbase  = s_v  + (uint32_t)(stage * VH_STAGE) * 2u + vb_lane;
            // per-tile lane-row bias base: slope2 * (kt*64 + 2*tig)
            const float kb = slope2 * (float)(kt * 64 + 2 * tig);

            #pragma unroll
            for (int st = 0; st < 2; st++) {
                uint32_t kbb = (st == 0) ? kbase0 : kbase1;

                float sc[8][4];
                #pragma unroll
                for (int j = 0; j < 8; j++)
                    #pragma unroll
                    for (int q = 0; q < 4; q++) sc[j][q] = 0.f;

                uint32_t qa_base = s_q + (uint32_t)(st * QT * QLDH) * 2u + qa_lane;
                #pragma unroll
                for (int k16 = 0; k16 < 4; k16++) {
                    uint32_t a0, a1, a2, a3;
                    asm volatile("ldmatrix.sync.aligned.m8n8.x4.shared.b16 {%0,%1,%2,%3}, [%4];\n"
                                 : "=r"(a0), "=r"(a1), "=r"(a2), "=r"(a3)
                                 : "r"(qa_base + (uint32_t)(k16 * 16) * 2u));
                    #pragma unroll
                    for (int jp = 0; jp < 4; jp++) {
                        uint32_t b0, b1, b2, b3;
                        uint32_t addr = kbb + (uint32_t)(jp * 16 * KLDH + k16 * 16) * 2u;
                        asm volatile("ldmatrix.sync.aligned.m8n8.x4.shared.b16 {%0,%1,%2,%3}, [%4];\n"
                                     : "=r"(b0), "=r"(b1), "=r"(b2), "=r"(b3) : "r"(addr));
                        asm volatile(
                            "mma.sync.aligned.m16n8k16.row.col.f32.f16.f16.f32 "
                            "{%0,%1,%2,%3}, {%4,%5,%6,%7}, {%8,%9}, {%0,%1,%2,%3};\n"
                            : "+f"(sc[2*jp][0]), "+f"(sc[2*jp][1]),
                              "+f"(sc[2*jp][2]), "+f"(sc[2*jp][3])
                            : "r"(a0), "r"(a1), "r"(a2), "r"(a3), "r"(b0), "r"(b1));
                        asm volatile(
                            "mma.sync.aligned.m16n8k16.row.col.f32.f16.f16.f32 "
                            "{%0,%1,%2,%3}, {%4,%5,%6,%7}, {%8,%9}, {%0,%1,%2,%3};\n"
                            : "+f"(sc[2*jp+1][0]), "+f"(sc[2*jp+1][1]),
                              "+f"(sc[2*jp+1][2]), "+f"(sc[2*jp+1][3])
                            : "r"(a0), "r"(a1), "r"(a2), "r"(a3), "r"(b2), "r"(b3));
                    }
                }

                // ---- softmax (online, log2 domain, folded bias) ----
                #pragma unroll
                for (int hh = 0; hh < 2; hh++) {
                    int qq = qq0 + hh * 8;
                    float mx = -INFINITY;
                    #pragma unroll
                    for (int j = 0; j < 8; j++) {
                        #pragma unroll
                        for (int e = 0; e < 2; e++) {
                            // bias = slope2*kk with kk = kt*64 + j*8 + 2*tig + e
                            float s = fmaf(sc[j][hh * 2 + e], scale2,
                                           fmaf((float)(j * 8 + e), slope2, kb));
                            if (diag) {
                                int kk = kt * 64 + j * 8 + 2 * tig + e;
                                if (kk > qq) s = -INFINITY;
                            }
                            sc[j][hh * 2 + e] = s;
                            mx = fmaxf(mx, s);
                        }
                    }
                    mx = fmaxf(mx, __shfl_xor_sync(0xffffffffu, mx, 1));
                    mx = fmaxf(mx, __shfl_xor_sync(0xffffffffu, mx, 2));
                    float mn = fmaxf(mrow[st][hh], mx);
                    float corr = ex2f(mrow[st][hh] - mn);
                    mrow[st][hh] = mn;
                    float rs = 0.f;
                    #pragma unroll
                    for (int j = 0; j < 8; j++) {
                        #pragma unroll
                        for (int e = 0; e < 2; e++) {
                            float pv = ex2f(sc[j][hh * 2 + e] - mn);
                            sc[j][hh * 2 + e] = pv;
                            rs += pv;
                        }
                    }
                    rs += __shfl_xor_sync(0xffffffffu, rs, 1);
                    rs += __shfl_xor_sync(0xffffffffu, rs, 2);
                    lrow[st][hh] = lrow[st][hh] * corr + rs;
                    #pragma unroll
                    for (int j = 0; j < 8; j++) {
                        oacc[st][j][hh * 2 + 0] *= corr;
                        oacc[st][j][hh * 2 + 1] *= corr;
                    }
                }

                // ---- write P (fp16) to own-warp rows of sP ----
                #pragma unroll
                for (int hh = 0; hh < 2; hh++) {
                    __half* pr = sP + (w * 16 + g + hh * 8) * PLDH;
                    #pragma unroll
                    for (int j = 0; j < 8; j++)
                        *(__half2*)(pr + j * 8 + 2 * tig) =
                            __floats2half2_rn(sc[j][hh * 2 + 0], sc[j][hh * 2 + 1]);
                }
                __syncwarp();

                // ---- PV: oacc += P @ V ----
                #pragma unroll
                for (int k16 = 0; k16 < 4; k16++) {
                    uint32_t a0, a1, a2, a3;
                    asm volatile("ldmatrix.sync.aligned.m8n8.x4.shared.b16 {%0,%1,%2,%3}, [%4];\n"
                                 : "=r"(a0), "=r"(a1), "=r"(a2), "=r"(a3)
                                 : "r"(pa_lane + (uint32_t)(k16 * 16) * 2u));
                    #pragma unroll
                    for (int jp = 0; jp < 4; jp++) {
                        uint32_t b0, b1, b2, b3;
                        uint32_t addr = vbase + (uint32_t)(k16 * 16 * VLDH + jp * 16) * 2u;
                        asm volatile("ldmatrix.sync.aligned.m8n8.x4.trans.shared.b16 {%0,%1,%2,%3}, [%4];\n"
                                     : "=r"(b0), "=r"(b1), "=r"(b2), "=r"(b3) : "r"(addr));
                        asm volatile(
                            "mma.sync.aligned.m16n8k16.row.col.f32.f16.f16.f32 "
                            "{%0,%1,%2,%3}, {%4,%5,%6,%7}, {%8,%9}, {%0,%1,%2,%3};\n"
                            : "+f"(oacc[st][2*jp][0]), "+f"(oacc[st][2*jp][1]),
                              "+f"(oacc[st][2*jp][2]), "+f"(oacc[st][2*jp][3])
                            : "r"(a0), "r"(a1), "r"(a2), "r"(a3), "r"(b0), "r"(b1));
                        asm volatile(
                            "mma.sync.aligned.m16n8k16.row.col.f32.f16.f16.f32 "
                            "{%0,%1,%2,%3}, {%4,%5,%6,%7}, {%8,%9}, {%0,%1,%2,%3};\n"
                            : "+f"(oacc[st][2*jp+1][0]), "+f"(oacc[st][2*jp+1][1]),
                              "+f"(oacc[st][2*jp+1][2]), "+f"(oacc[st][2*jp+1][3])
                            : "r"(a0), "r"(a1), "r"(a2), "r"(a3), "r"(b2), "r"(b3));
                    }
                }
                __syncwarp();
            }
        }
    }

    // --- epilogue: combine streams, per-head LayerNorm over DH, store fp16 ---
    float lam = g_lambda;
    #pragma unroll
    for (int hh = 0; hh < 2; hh++) {
        float inv0 = 1.0f / lrow[0][hh];
        float inv1 = 1.0f / lrow[1][hh];
        float o[8][2];
        float s_ = 0.f;
        #pragma unroll
        for (int j = 0; j < 8; j++) {
            #pragma unroll
            for (int e = 0; e < 2; e++) {
                float val = oacc[0][j][hh * 2 + e] * inv0
                          - lam * (oacc[1][j][hh * 2 + e] * inv1);
                o[j][e] = val;
                s_ += val;
            }
        }
        s_ += __shfl_xor_sync(0xffffffffu, s_, 1);
        s_ += __shfl_xor_sync(0xffffffffu, s_, 2);
        float mu = s_ * (1.0f / 64.0f);
        float vs = 0.f;
        #pragma unroll
        for (int j = 0; j < 8; j++) {
            #pragma unroll
            for (int e = 0; e < 2; e++) { float d = o[j][e] - mu; vs += d * d; }
        }
        vs += __shfl_xor_sync(0xffffffffu, vs, 1);
        vs += __shfl_xor_sync(0xffffffffu, vs, 2);
        float r = rsqrtf(vs * (1.0f / 64.0f) + LN_EPS);

        size_t row = (size_t)b * SEQ + (size_t)(qrow0 + g + hh * 8);
        #pragma unroll
        for (int j = 0; j < 8; j++) {
            int col = h * DHEAD + j * 8 + 2 * tig;
            float wv0 = ln_w[h * DHEAD + j * 8 + 2 * tig];
            float wv1 = ln_w[h * DHEAD + j * 8 + 2 * tig + 1];
            float bv0 = ln_b[h * DHEAD + j * 8 + 2 * tig];
            float bv1 = ln_b[h * DHEAD + j * 8 + 2 * tig + 1];
            *(__half2*)(attnh + row * DMODEL + col) =
                __floats2half2_rn((o[j][0] - mu) * r * wv0 + bv0,
                                  (o[j][1] - mu) * r * wv1 + bv1);
        }
    }
}

// ---------------------------------------------------------------------------
// Launch
// ---------------------------------------------------------------------------
extern "C" void kernel_launch(void* const* d_in, const int* in_sizes, int n_in,
                              void* d_out, int out_size) {
    const float* inp = (const float*)d_in[0];
    const float* wq0 = (const float*)d_in[1];
    const float* wq1 = (const float*)d_in[2];
    const float* wk0 = (const float*)d_in[3];
    const float* wk1 = (const float*)d_in[4];
    const float* wv  = (const float*)d_in[5];
    const float* wo  = (const float*)d_in[6];
    const float* l0  = (const float*)d_in[7];
    const float* l1  = (const float*)d_in[8];
    const float* l2  = (const float*)d_in[9];
    const float* l3  = (const float*)d_in[10];
    const float* lnw = (const float*)d_in[11];
    const float* lnb = (const float*)d_in[12];
    float* out = (float*)d_out;

    __half *qkvh, *xh, *attnh, *wcat, *woh;
    cudaGetSymbolAddress((void**)&qkvh, g_qkvh);
    cudaGetSymbolAddress((void**)&xh, g_xh);
    cudaGetSymbolAddress((void**)&attnh, g_attnh);
    cudaGetSymbolAddress((void**)&wcat, g_wcat);
    cudaGetSymbolAddress((void**)&woh, g_woh);

    cudaFuncSetAttribute(gemm_f16<float>, cudaFuncAttributeMaxDynamicSharedMemorySize,
                         HGEMM_SMEM_BYTES);
    cudaFuncSetAttribute(gemm_f16<__half>, cudaFuncAttributeMaxDynamicSharedMemorySize,
                         HGEMM_SMEM_BYTES);
    cudaFuncSetAttribute(attn_tc_kernel, cudaFuncAttributeMaxDynamicSharedMemorySize,
                         ATTN3_SMEM_BYTES);

    convert_all_kernel<<<10241, 256>>>(inp, wq0, wq1, wk0, wk1, wv, wo,
                                       l0, l1, l2, l3, xh, wcat, woh);

    dim3 pgrid(NQKV / 128, MTOT / 128);     // (40, 32) = 1280 CTAs
    gemm_f16<__half><<<pgrid, 256, HGEMM_SMEM_BYTES>>>(xh, wcat, qkvh,
                                                       MTOT, NQKV, DMODEL);

    attn_tc_kernel<<<dim3(SEQ / QT, BATCH * NHEAD), 256, ATTN3_SMEM_BYTES>>>(
        qkvh, lnw, lnb, attnh);

    dim3 ggrid(DMODEL / 128, MTOT / 128);   // (8, 32)
    gemm_f16<float><<<ggrid, 256, HGEMM_SMEM_BYTES>>>(attnh, woh, out, MTOT, DMODEL, DMODEL);
}